// round 1
// baseline (speedup 1.0000x reference)
#include <cuda_runtime.h>

#define S_LEN 2304
#define C_DIM 1024
#define NH    16
#define HD    64
#define BATCH 2

// Scratch: qkv [3][b][n][s][hd], z [b][s][c]
__device__ float g_qkv[(size_t)3 * BATCH * NH * S_LEN * HD];
__device__ float g_z[(size_t)BATCH * S_LEN * C_DIM];

#define BM 64
#define BN 64
#define BK 16
#define TM 4
#define TN 4

// ---------------------------------------------------------------------------
// QKV projection: Out[mo, t] = sum_k Wqkv[mo,k] * x[b,k,t] + bqkv[mo]
// x is [b, c, w*h] so x[b] is already the [K, N] B-matrix (t contiguous).
// Scatter into g_qkv[which][b][head][t][d]; BM=64 tile covers exactly one
// (which, head) pair since hd = 64.
// ---------------------------------------------------------------------------
__global__ void qkv_gemm(const float* __restrict__ x,
                         const float* __restrict__ W,
                         const float* __restrict__ bias) {
    __shared__ float As[BK][BM];
    __shared__ float Bs[BK][BN];
    int b  = blockIdx.z;
    int m0 = blockIdx.y * BM;
    int n0 = blockIdx.x * BN;
    int tid = threadIdx.x;
    int tx = tid & 15, ty = tid >> 4;

    const float* xb = x + (size_t)b * C_DIM * S_LEN;
    float acc[TM][TN] = {};

    for (int k0 = 0; k0 < C_DIM; k0 += BK) {
        int li = tid * 4;
        {   // A: 64 rows x 16 k, transposed store
            int m = li >> 4;
            int k = li & 15;
            float4 v = *reinterpret_cast<const float4*>(W + (size_t)(m0 + m) * C_DIM + k0 + k);
            As[k + 0][m] = v.x; As[k + 1][m] = v.y; As[k + 2][m] = v.z; As[k + 3][m] = v.w;
        }
        {   // B: 16 k x 64 n, direct store
            int k = li >> 6;
            int n = li & 63;
            float4 v = *reinterpret_cast<const float4*>(xb + (size_t)(k0 + k) * S_LEN + n0 + n);
            *reinterpret_cast<float4*>(&Bs[k][n]) = v;
        }
        __syncthreads();
#pragma unroll
        for (int k = 0; k < BK; k++) {
            float a[TM], bb[TN];
#pragma unroll
            for (int i = 0; i < TM; i++) a[i] = As[k][ty * TM + i];
#pragma unroll
            for (int j = 0; j < TN; j++) bb[j] = Bs[k][tx * TN + j];
#pragma unroll
            for (int i = 0; i < TM; i++)
#pragma unroll
                for (int j = 0; j < TN; j++)
                    acc[i][j] += a[i] * bb[j];
        }
        __syncthreads();
    }

    int which = m0 / C_DIM;
    int head  = (m0 % C_DIM) / HD;
    float* dst = g_qkv + ((size_t)(which * BATCH + b) * NH + head) * (size_t)S_LEN * HD;
#pragma unroll
    for (int i = 0; i < TM; i++) {
        int d = ty * TM + i;
        float bv = bias[m0 + d];
#pragma unroll
        for (int j = 0; j < TN; j++) {
            int t = n0 + tx * TN + j;
            dst[(size_t)t * HD + d] = acc[i][j] + bv;
        }
    }
}

// ---------------------------------------------------------------------------
// Flash attention (fp32). Block = (q-tile of 64 rows, head, batch).
// Soft causal mask (-10000) => masked tiles contribute exactly 0 (exp
// underflow), so only k-tiles <= q-tile are processed (exact).
// ---------------------------------------------------------------------------
__global__ void attn_kernel() {
    extern __shared__ float sm[];
    float* Qt   = sm;                 // [HD][64]  (d-major)
    float* Kt   = Qt + 64 * 64;       // [HD][64]  (d-major)
    float* Vs   = Kt + 64 * 64;       // [64][HD]
    float* Ss   = Vs + 64 * 64;       // [64][65]
    float* mrow = Ss + 64 * 65;       // [64]
    float* lrow = mrow + 64;          // [64]
    float* arow = lrow + 64;          // [64]

    int qt   = blockIdx.x;
    int head = blockIdx.y;
    int b    = blockIdx.z;
    int tid  = threadIdx.x;
    int tx = tid & 15, ty = tid >> 4;

    const float* qb = g_qkv + ((size_t)(0 * BATCH + b) * NH + head) * (size_t)S_LEN * HD;
    const float* kb = g_qkv + ((size_t)(1 * BATCH + b) * NH + head) * (size_t)S_LEN * HD;
    const float* vb = g_qkv + ((size_t)(2 * BATCH + b) * NH + head) * (size_t)S_LEN * HD;

    int q0 = qt * 64;

    // Load Q tile transposed (d-major)
    for (int li = tid * 4; li < 64 * 64; li += 256 * 4) {
        int r = li >> 6, d = li & 63;
        float4 v = *reinterpret_cast<const float4*>(qb + (size_t)(q0 + r) * HD + d);
        Qt[(d + 0) * 64 + r] = v.x; Qt[(d + 1) * 64 + r] = v.y;
        Qt[(d + 2) * 64 + r] = v.z; Qt[(d + 3) * 64 + r] = v.w;
    }
    if (tid < 64) { mrow[tid] = -1e30f; lrow[tid] = 0.0f; }

    float o[TM][TN] = {};
    __syncthreads();

    for (int kt = 0; kt <= qt; kt++) {
        int c0 = kt * 64;
        // Load K (transposed) and V tiles
        for (int li = tid * 4; li < 64 * 64; li += 256 * 4) {
            int r = li >> 6, d = li & 63;
            float4 v = *reinterpret_cast<const float4*>(kb + (size_t)(c0 + r) * HD + d);
            Kt[(d + 0) * 64 + r] = v.x; Kt[(d + 1) * 64 + r] = v.y;
            Kt[(d + 2) * 64 + r] = v.z; Kt[(d + 3) * 64 + r] = v.w;
            float4 w = *reinterpret_cast<const float4*>(vb + (size_t)(c0 + r) * HD + d);
            *reinterpret_cast<float4*>(&Vs[r * 64 + d]) = w;
        }
        __syncthreads();

        // S = Q K^T * (1/8), with soft mask on diagonal tile
        {
            float acc[TM][TN] = {};
#pragma unroll
            for (int d = 0; d < HD; d++) {
                float a[TM], bb[TN];
#pragma unroll
                for (int i = 0; i < TM; i++) a[i] = Qt[d * 64 + ty * TM + i];
#pragma unroll
                for (int j = 0; j < TN; j++) bb[j] = Kt[d * 64 + tx * TN + j];
#pragma unroll
                for (int i = 0; i < TM; i++)
#pragma unroll
                    for (int j = 0; j < TN; j++)
                        acc[i][j] += a[i] * bb[j];
            }
#pragma unroll
            for (int i = 0; i < TM; i++) {
                int r = ty * TM + i;
#pragma unroll
                for (int j = 0; j < TN; j++) {
                    int c = tx * TN + j;
                    float sv = acc[i][j] * 0.125f;
                    if (kt == qt && (c0 + c) > (q0 + r)) sv -= 10000.0f;
                    Ss[r * 65 + c] = sv;
                }
            }
        }
        __syncthreads();

        // Online softmax: 4 threads per row
        {
            int r = tid >> 2;
            int g = tid & 3;
            float* row = Ss + r * 65 + g * 16;
            float mx = -1e30f;
#pragma unroll
            for (int c = 0; c < 16; c++) mx = fmaxf(mx, row[c]);
            mx = fmaxf(mx, __shfl_xor_sync(0xffffffffu, mx, 1));
            mx = fmaxf(mx, __shfl_xor_sync(0xffffffffu, mx, 2));
            float mold = mrow[r];
            float mnew = fmaxf(mold, mx);
            float lsum = 0.0f;
#pragma unroll
            for (int c = 0; c < 16; c++) {
                float p = __expf(row[c] - mnew);
                row[c] = p;
                lsum += p;
            }
            lsum += __shfl_xor_sync(0xffffffffu, lsum, 1);
            lsum += __shfl_xor_sync(0xffffffffu, lsum, 2);
            if (g == 0) {
                float alpha = __expf(mold - mnew);
                arow[r] = alpha;
                lrow[r] = lrow[r] * alpha + lsum;
                mrow[r] = mnew;
            }
        }
        __syncthreads();

        // O = O*alpha + P @ V   (O stays in registers)
        {
            float al[TM];
#pragma unroll
            for (int i = 0; i < TM; i++) al[i] = arow[ty * TM + i];
#pragma unroll
            for (int i = 0; i < TM; i++)
#pragma unroll
                for (int j = 0; j < TN; j++) o[i][j] *= al[i];
#pragma unroll
            for (int k = 0; k < 64; k++) {
                float a[TM], bb[TN];
#pragma unroll
                for (int i = 0; i < TM; i++) a[i] = Ss[(ty * TM + i) * 65 + k];
#pragma unroll
                for (int j = 0; j < TN; j++) bb[j] = Vs[k * 64 + tx * TN + j];
#pragma unroll
                for (int i = 0; i < TM; i++)
#pragma unroll
                    for (int j = 0; j < TN; j++)
                        o[i][j] += a[i] * bb[j];
            }
        }
        __syncthreads();
    }

    // Write z[b, t, head*64 + d]
    float linv[TM];
#pragma unroll
    for (int i = 0; i < TM; i++) linv[i] = 1.0f / lrow[ty * TM + i];
#pragma unroll
    for (int i = 0; i < TM; i++) {
        int t = q0 + ty * TM + i;
#pragma unroll
        for (int j = 0; j < TN; j++) {
            int cc = head * HD + tx * TN + j;
            g_z[((size_t)b * S_LEN + t) * C_DIM + cc] = o[i][j] * linv[i];
        }
    }
}

// ---------------------------------------------------------------------------
// Output projection: out[b, co, t] = sum_ci Wo[co,ci] * z[b,t,ci] + bo[co]
// B-matrix is z^T per batch (k = ci contiguous) -> transpose-on-load.
// ---------------------------------------------------------------------------
__global__ void out_gemm(const float* __restrict__ Wo,
                         const float* __restrict__ bo,
                         float* __restrict__ out) {
    __shared__ float As[BK][BM];
    __shared__ float Bs[BK][BN];
    int b  = blockIdx.z;
    int m0 = blockIdx.y * BM;  // co
    int n0 = blockIdx.x * BN;  // t
    int tid = threadIdx.x;
    int tx = tid & 15, ty = tid >> 4;

    const float* zb = g_z + (size_t)b * S_LEN * C_DIM;
    float acc[TM][TN] = {};

    for (int k0 = 0; k0 < C_DIM; k0 += BK) {
        int li = tid * 4;
        {
            int m = li >> 4;
            int k = li & 15;
            float4 v = *reinterpret_cast<const float4*>(Wo + (size_t)(m0 + m) * C_DIM + k0 + k);
            As[k + 0][m] = v.x; As[k + 1][m] = v.y; As[k + 2][m] = v.z; As[k + 3][m] = v.w;
        }
        {
            int n = li >> 4;
            int k = li & 15;
            float4 v = *reinterpret_cast<const float4*>(zb + (size_t)(n0 + n) * C_DIM + k0 + k);
            Bs[k + 0][n] = v.x; Bs[k + 1][n] = v.y; Bs[k + 2][n] = v.z; Bs[k + 3][n] = v.w;
        }
        __syncthreads();
#pragma unroll
        for (int k = 0; k < BK; k++) {
            float a[TM], bb[TN];
#pragma unroll
            for (int i = 0; i < TM; i++) a[i] = As[k][ty * TM + i];
#pragma unroll
            for (int j = 0; j < TN; j++) bb[j] = Bs[k][tx * TN + j];
#pragma unroll
            for (int i = 0; i < TM; i++)
#pragma unroll
                for (int j = 0; j < TN; j++)
                    acc[i][j] += a[i] * bb[j];
        }
        __syncthreads();
    }

#pragma unroll
    for (int i = 0; i < TM; i++) {
        int co = m0 + ty * TM + i;
        float bv = bo[co];
#pragma unroll
        for (int j = 0; j < TN; j++) {
            int t = n0 + tx * TN + j;
            out[((size_t)b * C_DIM + co) * S_LEN + t] = acc[i][j] + bv;
        }
    }
}

// ---------------------------------------------------------------------------

extern "C" void kernel_launch(void* const* d_in, const int* in_sizes, int n_in,
                              void* d_out, int out_size) {
    const float* x    = (const float*)d_in[0];
    const float* Wqkv = (const float*)d_in[1];
    const float* bqkv = (const float*)d_in[2];
    const float* Wo   = (const float*)d_in[3];
    const float* bo   = (const float*)d_in[4];
    float* out = (float*)d_out;

    dim3 gA(S_LEN / BN, (3 * C_DIM) / BM, BATCH);
    qkv_gemm<<<gA, 256>>>(x, Wqkv, bqkv);

    size_t smem = (size_t)(64 * 64 * 3 + 64 * 65 + 3 * 64) * sizeof(float);
    cudaFuncSetAttribute(attn_kernel, cudaFuncAttributeMaxDynamicSharedMemorySize, (int)smem);
    dim3 gB(S_LEN / 64, NH, BATCH);
    attn_kernel<<<gB, 256, smem>>>();

    dim3 gC(S_LEN / BN, C_DIM / BM, BATCH);
    out_gemm<<<gC, 256>>>(Wo, bo, out);
}

// round 2
// speedup vs baseline: 1.4209x; 1.4209x over previous
#include <cuda_runtime.h>

#define S_LEN 2304
#define C_DIM 1024
#define NH    16
#define HD    64
#define BATCH 2

// Scratch: qkv [3][b][n][s][hd] (q pre-scaled by 1/8), z [b][s][c]
__device__ float g_qkv[(size_t)3 * BATCH * NH * S_LEN * HD];
__device__ float g_z[(size_t)BATCH * S_LEN * C_DIM];

// ---------------- GEMM config: 128x128x8 tiles, 256 threads, 8x8 frags -----
#define BM 128
#define BN 128
#define BK 8
#define PITCH 132

// ---------------------------------------------------------------------------
// QKV projection: Out[m, t] = sum_k Wqkv[m,k] * x[b,k,t] + bqkv[m]
// Scatter into g_qkv[which][b][head][t][d]; Q part scaled by 0.125.
// ---------------------------------------------------------------------------
__global__ __launch_bounds__(256, 2)
void qkv_gemm(const float* __restrict__ x,
              const float* __restrict__ W,
              const float* __restrict__ bias) {
    __shared__ float As[BK * PITCH];
    __shared__ float Bs[BK * PITCH];
    int b  = blockIdx.z;
    int m0 = blockIdx.y * BM;
    int n0 = blockIdx.x * BN;
    int tid = threadIdx.x;
    int tx = tid & 15, ty = tid >> 4;

    const float* xb = x + (size_t)b * C_DIM * S_LEN;

    int a_m = tid >> 1, a_k = (tid & 1) * 4;     // A: 128 rows x 8 k (transpose store)
    int b_k = tid >> 5, b_n = (tid & 31) * 4;    // B: 8 k x 128 n   (direct store)

    float4 ra = *(const float4*)(W  + (size_t)(m0 + a_m) * C_DIM + a_k);
    float4 rb = *(const float4*)(xb + (size_t)b_k * S_LEN + n0 + b_n);

    float acc[8][8] = {};
    for (int k0 = 0; k0 < C_DIM; k0 += BK) {
        As[(a_k + 0) * PITCH + a_m] = ra.x;
        As[(a_k + 1) * PITCH + a_m] = ra.y;
        As[(a_k + 2) * PITCH + a_m] = ra.z;
        As[(a_k + 3) * PITCH + a_m] = ra.w;
        *(float4*)(Bs + b_k * PITCH + b_n) = rb;
        __syncthreads();
        if (k0 + BK < C_DIM) {
            ra = *(const float4*)(W  + (size_t)(m0 + a_m) * C_DIM + k0 + BK + a_k);
            rb = *(const float4*)(xb + (size_t)(k0 + BK + b_k) * S_LEN + n0 + b_n);
        }
#pragma unroll
        for (int k = 0; k < BK; k++) {
            float a[8], bb[8];
            *(float4*)(a)      = *(float4*)(As + k * PITCH + ty * 8);
            *(float4*)(a + 4)  = *(float4*)(As + k * PITCH + ty * 8 + 4);
            *(float4*)(bb)     = *(float4*)(Bs + k * PITCH + tx * 8);
            *(float4*)(bb + 4) = *(float4*)(Bs + k * PITCH + tx * 8 + 4);
#pragma unroll
            for (int i = 0; i < 8; i++)
#pragma unroll
                for (int j = 0; j < 8; j++)
                    acc[i][j] += a[i] * bb[j];
        }
        __syncthreads();
    }

    int mbase = m0 + ty * 8;                  // 8 consecutive m -> one head (8 | 64)
    int which = mbase / C_DIM;
    int head  = (mbase % C_DIM) / HD;
    int d0    = mbase % HD;
    float scale = (which == 0) ? 0.125f : 1.0f;
    float* dst = g_qkv + ((size_t)(which * BATCH + b) * NH + head) * (size_t)S_LEN * HD;
    float bv[8];
#pragma unroll
    for (int i = 0; i < 8; i++) bv[i] = bias[mbase + i];
#pragma unroll
    for (int j = 0; j < 8; j++) {
        int t = n0 + tx * 8 + j;
#pragma unroll
        for (int ii = 0; ii < 8; ii += 4) {
            float4 v;
            v.x = (acc[ii + 0][j] + bv[ii + 0]) * scale;
            v.y = (acc[ii + 1][j] + bv[ii + 1]) * scale;
            v.z = (acc[ii + 2][j] + bv[ii + 2]) * scale;
            v.w = (acc[ii + 3][j] + bv[ii + 3]) * scale;
            *(float4*)(dst + (size_t)t * HD + d0 + ii) = v;
        }
    }
}

// ---------------------------------------------------------------------------
// Flash attention fp32. Block = (paired q-tiles of 128 rows, head, batch).
// Pairing (17-bx, bx) makes every block do exactly 38 k-tiles (1 wave).
// Soft mask (-10000) => masked tiles contribute exactly 0 (exp underflow),
// so only k-tiles up to the diagonal are processed (exact).
// ---------------------------------------------------------------------------
#define QT 128
#define KT 64
#define QP 132
#define KP 68

__global__ __launch_bounds__(256, 2)
void attn_kernel() {
    extern __shared__ float sm[];
    float* Qt   = sm;              // [64][QP]  Q^T (d-major)
    float* Ps   = Qt + 64 * QP;    // [64][QP]  S^T / P^T (c-major rows)
    float* Kt   = Ps + 64 * QP;    // [64][KP]  K^T (d-major)
    float* Vs   = Kt + 64 * KP;    // [64][KP]  V   (k-major)
    float* mrow = Vs + 64 * KP;    // [128]
    float* lrow = mrow + 128;      // [128]
    float* arow = lrow + 128;      // [128]

    int head = blockIdx.y;
    int b    = blockIdx.z;
    int tid  = threadIdx.x;
    int tx = tid & 15, ty = tid >> 4;

    const float* qb = g_qkv + ((size_t)(0 * BATCH + b) * NH + head) * (size_t)S_LEN * HD;
    const float* kb = g_qkv + ((size_t)(1 * BATCH + b) * NH + head) * (size_t)S_LEN * HD;
    const float* vb = g_qkv + ((size_t)(2 * BATCH + b) * NH + head) * (size_t)S_LEN * HD;

    int nqt = S_LEN / QT;  // 18

    for (int rep = 0; rep < 2; rep++) {
        int qt = rep == 0 ? (nqt - 1 - blockIdx.x) : blockIdx.x;  // heavy first
        int q0 = qt * QT;

        // Load Q tile transposed (d-major)
        for (int i = tid; i < QT * HD / 4; i += 256) {
            int r = i >> 4, d = (i & 15) * 4;
            float4 v = *(const float4*)(qb + (size_t)(q0 + r) * HD + d);
            Qt[(d + 0) * QP + r] = v.x; Qt[(d + 1) * QP + r] = v.y;
            Qt[(d + 2) * QP + r] = v.z; Qt[(d + 3) * QP + r] = v.w;
        }
        if (tid < 128) { mrow[tid] = -1e30f; lrow[tid] = 0.0f; }
        float o[8][4] = {};
        __syncthreads();

        int nkt = 2 * qt + 2;
        for (int kt = 0; kt < nkt; kt++) {
            int c0 = kt * KT;
            // K transposed, V direct
            for (int i = tid; i < KT * HD / 4; i += 256) {
                int c = i >> 4, d = (i & 15) * 4;
                float4 v = *(const float4*)(kb + (size_t)(c0 + c) * HD + d);
                Kt[(d + 0) * KP + c] = v.x; Kt[(d + 1) * KP + c] = v.y;
                Kt[(d + 2) * KP + c] = v.z; Kt[(d + 3) * KP + c] = v.w;
            }
            for (int i = tid; i < KT * HD / 4; i += 256) {
                int rr = i >> 4, d = (i & 15) * 4;
                *(float4*)(Vs + rr * KP + d) =
                    *(const float4*)(vb + (size_t)(c0 + rr) * HD + d);
            }
            __syncthreads();

            // S = Q K^T (Q pre-scaled by 1/8)
            float acc[8][4] = {};
#pragma unroll
            for (int d = 0; d < HD; d++) {
                float a[8], bb[4];
                *(float4*)(a)     = *(float4*)(Qt + d * QP + ty * 8);
                *(float4*)(a + 4) = *(float4*)(Qt + d * QP + ty * 8 + 4);
                *(float4*)(bb)    = *(float4*)(Kt + d * KP + tx * 4);
#pragma unroll
                for (int i = 0; i < 8; i++)
#pragma unroll
                    for (int j = 0; j < 4; j++)
                        acc[i][j] += a[i] * bb[j];
            }
            // soft mask on diagonal tiles + transposed store
            bool diag = (c0 + KT - 1 > q0);
#pragma unroll
            for (int j = 0; j < 4; j++) {
                int c = tx * 4 + j;
                if (diag) {
#pragma unroll
                    for (int i = 0; i < 8; i++) {
                        int r = ty * 8 + i;
                        if (c0 + c > q0 + r) acc[i][j] -= 10000.0f;
                    }
                }
                float4 v0 = {acc[0][j], acc[1][j], acc[2][j], acc[3][j]};
                float4 v1 = {acc[4][j], acc[5][j], acc[6][j], acc[7][j]};
                *(float4*)(Ps + c * QP + ty * 8)     = v0;
                *(float4*)(Ps + c * QP + ty * 8 + 4) = v1;
            }
            __syncthreads();

            // Online softmax: 2 threads per row, 32 cols each
            {
                int r = tid >> 1, g = tid & 1;
                float vals[32];
                float mx = -1e30f;
#pragma unroll
                for (int c = 0; c < 32; c++) {
                    vals[c] = Ps[(g * 32 + c) * QP + r];
                    mx = fmaxf(mx, vals[c]);
                }
                mx = fmaxf(mx, __shfl_xor_sync(0xffffffffu, mx, 1));
                float mold = mrow[r];
                float mnew = fmaxf(mold, mx);
                float lsum = 0.0f;
#pragma unroll
                for (int c = 0; c < 32; c++) {
                    float p = __expf(vals[c] - mnew);
                    Ps[(g * 32 + c) * QP + r] = p;
                    lsum += p;
                }
                lsum += __shfl_xor_sync(0xffffffffu, lsum, 1);
                if (g == 0) {
                    arow[r] = __expf(mold - mnew);
                    lrow[r] = lrow[r] * arow[r] + lsum;
                    mrow[r] = mnew;
                }
            }
            __syncthreads();

            // O = O*alpha + P @ V
            {
                float al[8];
#pragma unroll
                for (int i = 0; i < 8; i++) al[i] = arow[ty * 8 + i];
#pragma unroll
                for (int i = 0; i < 8; i++)
#pragma unroll
                    for (int j = 0; j < 4; j++) o[i][j] *= al[i];
#pragma unroll
                for (int k = 0; k < KT; k++) {
                    float a[8], bb[4];
                    *(float4*)(a)     = *(float4*)(Ps + k * QP + ty * 8);
                    *(float4*)(a + 4) = *(float4*)(Ps + k * QP + ty * 8 + 4);
                    *(float4*)(bb)    = *(float4*)(Vs + k * KP + tx * 4);
#pragma unroll
                    for (int i = 0; i < 8; i++)
#pragma unroll
                        for (int j = 0; j < 4; j++)
                            o[i][j] += a[i] * bb[j];
                }
            }
            __syncthreads();
        }

        // z[b, t, head*64 + d]
        float linv[8];
#pragma unroll
        for (int i = 0; i < 8; i++) linv[i] = 1.0f / lrow[ty * 8 + i];
#pragma unroll
        for (int i = 0; i < 8; i++) {
            int t = q0 + ty * 8 + i;
            float4 v = {o[i][0] * linv[i], o[i][1] * linv[i],
                        o[i][2] * linv[i], o[i][3] * linv[i]};
            *(float4*)(g_z + ((size_t)b * S_LEN + t) * C_DIM + head * HD + tx * 4) = v;
        }
        __syncthreads();
    }
}

// ---------------------------------------------------------------------------
// Output projection: out[b, co, t] = sum_ci Wo[co,ci] * z[b,t,ci] + bo[co]
// ---------------------------------------------------------------------------
__global__ __launch_bounds__(256, 2)
void out_gemm(const float* __restrict__ Wo,
              const float* __restrict__ bo,
              float* __restrict__ out) {
    __shared__ float As[BK * PITCH];
    __shared__ float Bs[BK * PITCH];
    int b  = blockIdx.z;
    int m0 = blockIdx.y * BM;   // co
    int n0 = blockIdx.x * BN;   // t
    int tid = threadIdx.x;
    int tx = tid & 15, ty = tid >> 4;

    const float* zb = g_z + (size_t)b * S_LEN * C_DIM;

    int a_m = tid >> 1, a_k = (tid & 1) * 4;
    int b_n = tid >> 1, b_k = (tid & 1) * 4;

    float4 ra = *(const float4*)(Wo + (size_t)(m0 + a_m) * C_DIM + a_k);
    float4 rb = *(const float4*)(zb + (size_t)(n0 + b_n) * C_DIM + b_k);

    float acc[8][8] = {};
    for (int k0 = 0; k0 < C_DIM; k0 += BK) {
        As[(a_k + 0) * PITCH + a_m] = ra.x;
        As[(a_k + 1) * PITCH + a_m] = ra.y;
        As[(a_k + 2) * PITCH + a_m] = ra.z;
        As[(a_k + 3) * PITCH + a_m] = ra.w;
        Bs[(b_k + 0) * PITCH + b_n] = rb.x;
        Bs[(b_k + 1) * PITCH + b_n] = rb.y;
        Bs[(b_k + 2) * PITCH + b_n] = rb.z;
        Bs[(b_k + 3) * PITCH + b_n] = rb.w;
        __syncthreads();
        if (k0 + BK < C_DIM) {
            ra = *(const float4*)(Wo + (size_t)(m0 + a_m) * C_DIM + k0 + BK + a_k);
            rb = *(const float4*)(zb + (size_t)(n0 + b_n) * C_DIM + k0 + BK + b_k);
        }
#pragma unroll
        for (int k = 0; k < BK; k++) {
            float a[8], bb[8];
            *(float4*)(a)      = *(float4*)(As + k * PITCH + ty * 8);
            *(float4*)(a + 4)  = *(float4*)(As + k * PITCH + ty * 8 + 4);
            *(float4*)(bb)     = *(float4*)(Bs + k * PITCH + tx * 8);
            *(float4*)(bb + 4) = *(float4*)(Bs + k * PITCH + tx * 8 + 4);
#pragma unroll
            for (int i = 0; i < 8; i++)
#pragma unroll
                for (int j = 0; j < 8; j++)
                    acc[i][j] += a[i] * bb[j];
        }
        __syncthreads();
    }

#pragma unroll
    for (int i = 0; i < 8; i++) {
        int co = m0 + ty * 8 + i;
        float bv = bo[co];
        float* orow = out + ((size_t)b * C_DIM + co) * S_LEN + n0 + tx * 8;
#pragma unroll
        for (int jj = 0; jj < 8; jj += 4) {
            float4 v;
            v.x = acc[i][jj + 0] + bv;
            v.y = acc[i][jj + 1] + bv;
            v.z = acc[i][jj + 2] + bv;
            v.w = acc[i][jj + 3] + bv;
            *(float4*)(orow + jj) = v;
        }
    }
}

// ---------------------------------------------------------------------------

extern "C" void kernel_launch(void* const* d_in, const int* in_sizes, int n_in,
                              void* d_out, int out_size) {
    const float* x    = (const float*)d_in[0];
    const float* Wqkv = (const float*)d_in[1];
    const float* bqkv = (const float*)d_in[2];
    const float* Wo   = (const float*)d_in[3];
    const float* bo   = (const float*)d_in[4];
    float* out = (float*)d_out;

    dim3 gA(S_LEN / BN, (3 * C_DIM) / BM, BATCH);
    qkv_gemm<<<gA, 256>>>(x, Wqkv, bqkv);

    size_t smem = (size_t)(64 * QP * 2 + 64 * KP * 2 + 3 * 128) * sizeof(float);
    cudaFuncSetAttribute(attn_kernel, cudaFuncAttributeMaxDynamicSharedMemorySize, (int)smem);
    dim3 gB((S_LEN / QT) / 2, NH, BATCH);
    attn_kernel<<<gB, 256, smem>>>();

    dim3 gC(S_LEN / BN, C_DIM / BM, BATCH);
    out_gemm<<<gC, 256>>>(Wo, bo, out);
}

// round 4
// speedup vs baseline: 1.9688x; 1.3856x over previous
#include <cuda_runtime.h>
#include <cuda_bf16.h>
#include <cstdint>

#define S_LEN 2304
#define C_DIM 1024
#define NH    16
#define HD    64
#define BATCH 2

// ---------------- scratch ---------------------------------------------------
__device__ float g_qkv[(size_t)3 * BATCH * NH * S_LEN * HD];        // q pre-scaled 1/8
__device__ __nv_bfloat16 g_Wq_hi[(size_t)3 * C_DIM * C_DIM];
__device__ __nv_bfloat16 g_Wq_lo[(size_t)3 * C_DIM * C_DIM];
__device__ __nv_bfloat16 g_Wo_hi[(size_t)C_DIM * C_DIM];
__device__ __nv_bfloat16 g_Wo_lo[(size_t)C_DIM * C_DIM];
__device__ __nv_bfloat16 g_xT_hi[(size_t)BATCH * S_LEN * C_DIM];
__device__ __nv_bfloat16 g_xT_lo[(size_t)BATCH * S_LEN * C_DIM];
__device__ __nv_bfloat16 g_z_hi[(size_t)BATCH * S_LEN * C_DIM];
__device__ __nv_bfloat16 g_z_lo[(size_t)BATCH * S_LEN * C_DIM];

// ---------------- warp-mma helpers ------------------------------------------
__device__ __forceinline__ uint32_t smem_u32(const void* p) {
    uint32_t a;
    asm("{ .reg .u64 t; cvta.to.shared.u64 t, %1; cvt.u32.u64 %0, t; }" : "=r"(a) : "l"(p));
    return a;
}
__device__ __forceinline__ void ldsm4(uint32_t* r, uint32_t addr) {
    asm volatile("ldmatrix.sync.aligned.m8n8.x4.shared.b16 {%0,%1,%2,%3}, [%4];"
                 : "=r"(r[0]), "=r"(r[1]), "=r"(r[2]), "=r"(r[3]) : "r"(addr));
}
__device__ __forceinline__ void mma_bf16(float* c, const uint32_t* a,
                                         uint32_t b0, uint32_t b1) {
    asm volatile(
        "mma.sync.aligned.m16n8k16.row.col.f32.bf16.bf16.f32 "
        "{%0,%1,%2,%3}, {%4,%5,%6,%7}, {%8,%9}, {%0,%1,%2,%3};"
        : "+f"(c[0]), "+f"(c[1]), "+f"(c[2]), "+f"(c[3])
        : "r"(a[0]), "r"(a[1]), "r"(a[2]), "r"(a[3]), "r"(b0), "r"(b1));
}

// ---------------- prep kernels ----------------------------------------------
__global__ void split_kernel(const float* __restrict__ src,
                             __nv_bfloat16* __restrict__ hi,
                             __nv_bfloat16* __restrict__ lo, int n4) {
    int i = blockIdx.x * 256 + threadIdx.x;
    if (i >= n4) return;
    float4 v = reinterpret_cast<const float4*>(src)[i];
    __nv_bfloat16 h0 = __float2bfloat16(v.x), h1 = __float2bfloat16(v.y);
    __nv_bfloat16 h2 = __float2bfloat16(v.z), h3 = __float2bfloat16(v.w);
    __nv_bfloat162 hh0{h0, h1}, hh1{h2, h3};
    __nv_bfloat162 ll0{__float2bfloat16(v.x - __bfloat162float(h0)),
                       __float2bfloat16(v.y - __bfloat162float(h1))};
    __nv_bfloat162 ll1{__float2bfloat16(v.z - __bfloat162float(h2)),
                       __float2bfloat16(v.w - __bfloat162float(h3))};
    *reinterpret_cast<__nv_bfloat162*>(hi + i * 4)     = hh0;
    *reinterpret_cast<__nv_bfloat162*>(hi + i * 4 + 2) = hh1;
    *reinterpret_cast<__nv_bfloat162*>(lo + i * 4)     = ll0;
    *reinterpret_cast<__nv_bfloat162*>(lo + i * 4 + 2) = ll1;
}

__global__ void xpose_split(const float* __restrict__ x) {
    __shared__ float tile[32][33];
    int b = blockIdx.z, t0 = blockIdx.x * 32, c0 = blockIdx.y * 32;
    int tx = threadIdx.x, ty = threadIdx.y;
    for (int i = ty; i < 32; i += 8)
        tile[i][tx] = x[((size_t)b * C_DIM + c0 + i) * S_LEN + t0 + tx];
    __syncthreads();
    for (int i = ty; i < 32; i += 8) {
        float v = tile[tx][i];
        size_t oi = ((size_t)b * S_LEN + t0 + i) * C_DIM + c0 + tx;
        __nv_bfloat16 h = __float2bfloat16(v);
        g_xT_hi[oi] = h;
        g_xT_lo[oi] = __float2bfloat16(v - __bfloat162float(h));
    }
}

// ---------------- mma.sync GEMM core ------------------------------------------
// CTA tile 128(m) x 128(n), K chunk 32 bf16, hi/lo split (3 passes).
// smem: 2 stages x 4 tiles (Ah, Al, Bh, Bl), each [128][40] bf16 (pitch 40).
#define GPITCH 40
#define TBYTES (128 * GPITCH * 2)     // 10240
#define STBYTES (4 * TBYTES)          // 40960

struct Frag {
    float acc[2][8][4];
};

// fill one stage: each thread loads 2x16B per tile
__device__ __forceinline__ void fill_stage(
    char* stage, int tid, int k0,
    const __nv_bfloat16* Ah, const __nv_bfloat16* Al,
    const __nv_bfloat16* Bh, const __nv_bfloat16* Bl) {
    int row = tid >> 1, half = tid & 1;
    size_t go = (size_t)row * C_DIM + k0 + half * 16;
    uint32_t so = row * (GPITCH * 2) + half * 32;
    const __nv_bfloat16* srcs[4] = {Ah, Al, Bh, Bl};
#pragma unroll
    for (int t4 = 0; t4 < 4; t4++) {
        const uint4* g = reinterpret_cast<const uint4*>(srcs[t4] + go);
        uint4 v0 = g[0], v1 = g[1];
        char* s = stage + t4 * TBYTES + so;
        *reinterpret_cast<uint4*>(s)      = v0;
        *reinterpret_cast<uint4*>(s + 16) = v1;
    }
}

__device__ __forceinline__ void compute_stage(
    uint32_t st, int lane, int wm, int wn, Frag& f) {
    uint32_t Ah_s = st, Al_s = st + TBYTES, Bh_s = st + 2 * TBYTES, Bl_s = st + 3 * TBYTES;
    // B ldmatrix address pieces
    int bgrp = lane >> 3, br = lane & 7;
    int brow = wn * 64 + (bgrp >> 1) * 8 + br;
    int bcolh = (bgrp & 1) * 8;
    // A ldmatrix address pieces
    int ar = lane & 15, acolh = (lane >> 4) * 8;
#pragma unroll
    for (int ks = 0; ks < 2; ks++) {
        uint32_t ah[2][4], al[2][4];
#pragma unroll
        for (int mi = 0; mi < 2; mi++) {
            uint32_t off = ((wm * 32 + mi * 16 + ar) * GPITCH + ks * 16 + acolh) * 2;
            ldsm4(ah[mi], Ah_s + off);
            ldsm4(al[mi], Al_s + off);
        }
        uint32_t bb[4][4];
#pragma unroll
        for (int nj = 0; nj < 4; nj++) {
            uint32_t off = ((brow + nj * 16) * GPITCH + ks * 16 + bcolh) * 2;
            ldsm4(bb[nj], Bh_s + off);
        }
#pragma unroll
        for (int mi = 0; mi < 2; mi++)
#pragma unroll
            for (int nj = 0; nj < 4; nj++) {
                mma_bf16(f.acc[mi][nj * 2],     ah[mi], bb[nj][0], bb[nj][1]);
                mma_bf16(f.acc[mi][nj * 2 + 1], ah[mi], bb[nj][2], bb[nj][3]);
                mma_bf16(f.acc[mi][nj * 2],     al[mi], bb[nj][0], bb[nj][1]);
                mma_bf16(f.acc[mi][nj * 2 + 1], al[mi], bb[nj][2], bb[nj][3]);
            }
#pragma unroll
        for (int nj = 0; nj < 4; nj++) {
            uint32_t off = ((brow + nj * 16) * GPITCH + ks * 16 + bcolh) * 2;
            ldsm4(bb[nj], Bl_s + off);
        }
#pragma unroll
        for (int mi = 0; mi < 2; mi++)
#pragma unroll
            for (int nj = 0; nj < 4; nj++) {
                mma_bf16(f.acc[mi][nj * 2],     ah[mi], bb[nj][0], bb[nj][1]);
                mma_bf16(f.acc[mi][nj * 2 + 1], ah[mi], bb[nj][2], bb[nj][3]);
            }
    }
}

__device__ __forceinline__ void gemm_body(
    char* sm, uint32_t smb, int tid, Frag& f,
    const __nv_bfloat16* Ah, const __nv_bfloat16* Al,
    const __nv_bfloat16* Bh, const __nv_bfloat16* Bl) {
    int lane = tid & 31, wid = tid >> 5;
    int wm = wid & 3, wn = wid >> 2;
    fill_stage(sm, tid, 0, Ah, Al, Bh, Bl);
    __syncthreads();
    for (int ch = 0; ch < C_DIM / 32; ch++) {
        if (ch + 1 < C_DIM / 32)
            fill_stage(sm + ((ch + 1) & 1) * STBYTES, tid, (ch + 1) * 32, Ah, Al, Bh, Bl);
        compute_stage(smb + (ch & 1) * STBYTES, lane, wm, wn, f);
        __syncthreads();
    }
}

// ---------------- QKV projection (mma.sync) -----------------------------------
__global__ __launch_bounds__(256)
void qkv_tc(const float* __restrict__ bias) {
    extern __shared__ char sm[];
    uint32_t smb = smem_u32(sm);
    int tid = threadIdx.x;
    int b = blockIdx.z, m0 = blockIdx.y * 128, n0 = blockIdx.x * 128;

    Frag f;
#pragma unroll
    for (int mi = 0; mi < 2; mi++)
#pragma unroll
        for (int ni = 0; ni < 8; ni++)
#pragma unroll
            for (int r = 0; r < 4; r++) f.acc[mi][ni][r] = 0.0f;

    gemm_body(sm, smb, tid, f,
              g_Wq_hi + (size_t)m0 * C_DIM, g_Wq_lo + (size_t)m0 * C_DIM,
              g_xT_hi + ((size_t)b * S_LEN + n0) * C_DIM,
              g_xT_lo + ((size_t)b * S_LEN + n0) * C_DIM);

    int lane = tid & 31, wid = tid >> 5;
    int wm = wid & 3, wn = wid >> 2;
#pragma unroll
    for (int mi = 0; mi < 2; mi++) {
#pragma unroll
        for (int rg = 0; rg < 2; rg++) {
            int m = m0 + wm * 32 + mi * 16 + (lane >> 2) + rg * 8;
            int which = m >> 10, head = (m & 1023) >> 6, d = m & 63;
            float scale = (which == 0) ? 0.125f : 1.0f;
            float bv = bias[m];
            float* dst = g_qkv + ((size_t)(which * BATCH + b) * NH + head) * (size_t)S_LEN * HD + d;
#pragma unroll
            for (int ni = 0; ni < 8; ni++) {
                int t = n0 + wn * 64 + ni * 8 + ((lane & 3) << 1);
                dst[(size_t)t * HD]       = (f.acc[mi][ni][rg * 2 + 0] + bv) * scale;
                dst[(size_t)(t + 1) * HD] = (f.acc[mi][ni][rg * 2 + 1] + bv) * scale;
            }
        }
    }
}

// ---------------- Output projection (mma.sync) --------------------------------
__global__ __launch_bounds__(256)
void out_tc(const float* __restrict__ bo, float* __restrict__ out) {
    extern __shared__ char sm[];
    uint32_t smb = smem_u32(sm);
    int tid = threadIdx.x;
    int b = blockIdx.z, m0 = blockIdx.y * 128, n0 = blockIdx.x * 128;

    Frag f;
#pragma unroll
    for (int mi = 0; mi < 2; mi++)
#pragma unroll
        for (int ni = 0; ni < 8; ni++)
#pragma unroll
            for (int r = 0; r < 4; r++) f.acc[mi][ni][r] = 0.0f;

    gemm_body(sm, smb, tid, f,
              g_Wo_hi + (size_t)m0 * C_DIM, g_Wo_lo + (size_t)m0 * C_DIM,
              g_z_hi + ((size_t)b * S_LEN + n0) * C_DIM,
              g_z_lo + ((size_t)b * S_LEN + n0) * C_DIM);

    int lane = tid & 31, wid = tid >> 5;
    int wm = wid & 3, wn = wid >> 2;
#pragma unroll
    for (int mi = 0; mi < 2; mi++) {
#pragma unroll
        for (int rg = 0; rg < 2; rg++) {
            int m = m0 + wm * 32 + mi * 16 + (lane >> 2) + rg * 8;
            float bv = bo[m];
            float* dst = out + ((size_t)b * C_DIM + m) * S_LEN;
#pragma unroll
            for (int ni = 0; ni < 8; ni++) {
                int t = n0 + wn * 64 + ni * 8 + ((lane & 3) << 1);
                float2 v = {f.acc[mi][ni][rg * 2 + 0] + bv,
                            f.acc[mi][ni][rg * 2 + 1] + bv};
                *reinterpret_cast<float2*>(dst + t) = v;
            }
        }
    }
}

// ---------------- Flash attention (fp32 SIMT, proven) --------------------------
#define QT 128
#define KT 64
#define QP 132
#define KP 68

__global__ __launch_bounds__(256, 2)
void attn_kernel() {
    extern __shared__ float smf[];
    float* Qt   = smf;
    float* Ps   = Qt + 64 * QP;
    float* Kt   = Ps + 64 * QP;
    float* Vs   = Kt + 64 * KP;
    float* mrow = Vs + 64 * KP;
    float* lrow = mrow + 128;
    float* arow = lrow + 128;

    int head = blockIdx.y;
    int b    = blockIdx.z;
    int tid  = threadIdx.x;
    int tx = tid & 15, ty = tid >> 4;

    const float* qb = g_qkv + ((size_t)(0 * BATCH + b) * NH + head) * (size_t)S_LEN * HD;
    const float* kb = g_qkv + ((size_t)(1 * BATCH + b) * NH + head) * (size_t)S_LEN * HD;
    const float* vb = g_qkv + ((size_t)(2 * BATCH + b) * NH + head) * (size_t)S_LEN * HD;

    int nqt = S_LEN / QT;

    for (int rep = 0; rep < 2; rep++) {
        int qt = rep == 0 ? (nqt - 1 - blockIdx.x) : blockIdx.x;
        int q0 = qt * QT;

        for (int i = tid; i < QT * HD / 4; i += 256) {
            int r = i >> 4, d = (i & 15) * 4;
            float4 v = *(const float4*)(qb + (size_t)(q0 + r) * HD + d);
            Qt[(d + 0) * QP + r] = v.x; Qt[(d + 1) * QP + r] = v.y;
            Qt[(d + 2) * QP + r] = v.z; Qt[(d + 3) * QP + r] = v.w;
        }
        if (tid < 128) { mrow[tid] = -1e30f; lrow[tid] = 0.0f; }
        float o[8][4] = {};
        __syncthreads();

        int nkt = 2 * qt + 2;
        for (int kt = 0; kt < nkt; kt++) {
            int c0 = kt * KT;
            for (int i = tid; i < KT * HD / 4; i += 256) {
                int c = i >> 4, d = (i & 15) * 4;
                float4 v = *(const float4*)(kb + (size_t)(c0 + c) * HD + d);
                Kt[(d + 0) * KP + c] = v.x; Kt[(d + 1) * KP + c] = v.y;
                Kt[(d + 2) * KP + c] = v.z; Kt[(d + 3) * KP + c] = v.w;
            }
            for (int i = tid; i < KT * HD / 4; i += 256) {
                int rr = i >> 4, d = (i & 15) * 4;
                *(float4*)(Vs + rr * KP + d) =
                    *(const float4*)(vb + (size_t)(c0 + rr) * HD + d);
            }
            __syncthreads();

            float acc[8][4] = {};
#pragma unroll
            for (int d = 0; d < HD; d++) {
                float a[8], bb[4];
                *(float4*)(a)     = *(float4*)(Qt + d * QP + ty * 8);
                *(float4*)(a + 4) = *(float4*)(Qt + d * QP + ty * 8 + 4);
                *(float4*)(bb)    = *(float4*)(Kt + d * KP + tx * 4);
#pragma unroll
                for (int i = 0; i < 8; i++)
#pragma unroll
                    for (int j = 0; j < 4; j++)
                        acc[i][j] += a[i] * bb[j];
            }
            bool diag = (c0 + KT - 1 > q0);
#pragma unroll
            for (int j = 0; j < 4; j++) {
                int c = tx * 4 + j;
                if (diag) {
#pragma unroll
                    for (int i = 0; i < 8; i++) {
                        int r = ty * 8 + i;
                        if (c0 + c > q0 + r) acc[i][j] -= 10000.0f;
                    }
                }
                float4 v0 = {acc[0][j], acc[1][j], acc[2][j], acc[3][j]};
                float4 v1 = {acc[4][j], acc[5][j], acc[6][j], acc[7][j]};
                *(float4*)(Ps + c * QP + ty * 8)     = v0;
                *(float4*)(Ps + c * QP + ty * 8 + 4) = v1;
            }
            __syncthreads();

            {
                int r = tid >> 1, g = tid & 1;
                float vals[32];
                float mx = -1e30f;
#pragma unroll
                for (int c = 0; c < 32; c++) {
                    vals[c] = Ps[(g * 32 + c) * QP + r];
                    mx = fmaxf(mx, vals[c]);
                }
                mx = fmaxf(mx, __shfl_xor_sync(0xffffffffu, mx, 1));
                float mold = mrow[r];
                float mnew = fmaxf(mold, mx);
                float lsum = 0.0f;
#pragma unroll
                for (int c = 0; c < 32; c++) {
                    float p = __expf(vals[c] - mnew);
                    Ps[(g * 32 + c) * QP + r] = p;
                    lsum += p;
                }
                lsum += __shfl_xor_sync(0xffffffffu, lsum, 1);
                if (g == 0) {
                    arow[r] = __expf(mold - mnew);
                    lrow[r] = lrow[r] * arow[r] + lsum;
                    mrow[r] = mnew;
                }
            }
            __syncthreads();

            {
                float al[8];
#pragma unroll
                for (int i = 0; i < 8; i++) al[i] = arow[ty * 8 + i];
#pragma unroll
                for (int i = 0; i < 8; i++)
#pragma unroll
                    for (int j = 0; j < 4; j++) o[i][j] *= al[i];
#pragma unroll
                for (int k = 0; k < KT; k++) {
                    float a[8], bb[4];
                    *(float4*)(a)     = *(float4*)(Ps + k * QP + ty * 8);
                    *(float4*)(a + 4) = *(float4*)(Ps + k * QP + ty * 8 + 4);
                    *(float4*)(bb)    = *(float4*)(Vs + k * KP + tx * 4);
#pragma unroll
                    for (int i = 0; i < 8; i++)
#pragma unroll
                        for (int j = 0; j < 4; j++)
                            o[i][j] += a[i] * bb[j];
                }
            }
            __syncthreads();
        }

        // write z as bf16 hi/lo: z[b, t, head*64 + d]
        float linv[8];
#pragma unroll
        for (int i = 0; i < 8; i++) linv[i] = 1.0f / lrow[ty * 8 + i];
#pragma unroll
        for (int i = 0; i < 8; i++) {
            int t = q0 + ty * 8 + i;
            size_t zi = ((size_t)b * S_LEN + t) * C_DIM + head * HD + tx * 4;
            float f0 = o[i][0] * linv[i], f1 = o[i][1] * linv[i];
            float f2 = o[i][2] * linv[i], f3 = o[i][3] * linv[i];
            __nv_bfloat16 h0 = __float2bfloat16(f0), h1 = __float2bfloat16(f1);
            __nv_bfloat16 h2 = __float2bfloat16(f2), h3 = __float2bfloat16(f3);
            __nv_bfloat162 hh0{h0, h1}, hh1{h2, h3};
            __nv_bfloat162 ll0{__float2bfloat16(f0 - __bfloat162float(h0)),
                               __float2bfloat16(f1 - __bfloat162float(h1))};
            __nv_bfloat162 ll1{__float2bfloat16(f2 - __bfloat162float(h2)),
                               __float2bfloat16(f3 - __bfloat162float(h3))};
            *reinterpret_cast<__nv_bfloat162*>(g_z_hi + zi)     = hh0;
            *reinterpret_cast<__nv_bfloat162*>(g_z_hi + zi + 2) = hh1;
            *reinterpret_cast<__nv_bfloat162*>(g_z_lo + zi)     = ll0;
            *reinterpret_cast<__nv_bfloat162*>(g_z_lo + zi + 2) = ll1;
        }
        __syncthreads();
    }
}

// ---------------------------------------------------------------------------

extern "C" void kernel_launch(void* const* d_in, const int* in_sizes, int n_in,
                              void* d_out, int out_size) {
    const float* x    = (const float*)d_in[0];
    const float* Wqkv = (const float*)d_in[1];
    const float* bqkv = (const float*)d_in[2];
    const float* Wo   = (const float*)d_in[3];
    const float* bo   = (const float*)d_in[4];
    float* out = (float*)d_out;

    __nv_bfloat16 *wq_hi, *wq_lo, *wo_hi, *wo_lo;
    cudaGetSymbolAddress((void**)&wq_hi, g_Wq_hi);
    cudaGetSymbolAddress((void**)&wq_lo, g_Wq_lo);
    cudaGetSymbolAddress((void**)&wo_hi, g_Wo_hi);
    cudaGetSymbolAddress((void**)&wo_lo, g_Wo_lo);

    int nq4 = 3 * C_DIM * C_DIM / 4;
    split_kernel<<<(nq4 + 255) / 256, 256>>>(Wqkv, wq_hi, wq_lo, nq4);
    int no4 = C_DIM * C_DIM / 4;
    split_kernel<<<(no4 + 255) / 256, 256>>>(Wo, wo_hi, wo_lo, no4);

    dim3 gT(S_LEN / 32, C_DIM / 32, BATCH);
    xpose_split<<<gT, dim3(32, 8)>>>(x);

    size_t gsmem = 2 * STBYTES;  // 81920
    cudaFuncSetAttribute(qkv_tc, cudaFuncAttributeMaxDynamicSharedMemorySize, (int)gsmem);
    cudaFuncSetAttribute(out_tc, cudaFuncAttributeMaxDynamicSharedMemorySize, (int)gsmem);

    dim3 gA(S_LEN / 128, 3 * C_DIM / 128, BATCH);
    qkv_tc<<<gA, 256, gsmem>>>(bqkv);

    size_t asmem = (size_t)(64 * QP * 2 + 64 * KP * 2 + 3 * 128) * sizeof(float);
    cudaFuncSetAttribute(attn_kernel, cudaFuncAttributeMaxDynamicSharedMemorySize, (int)asmem);
    dim3 gB((S_LEN / QT) / 2, NH, BATCH);
    attn_kernel<<<gB, 256, asmem>>>();

    dim3 gC(S_LEN / 128, C_DIM / 128, BATCH);
    out_tc<<<gC, 256, gsmem>>>(bo, out);
}

// round 5
// speedup vs baseline: 2.7621x; 1.4029x over previous
#include <cuda_runtime.h>
#include <cuda_bf16.h>
#include <cstdint>

#define S_LEN 2304
#define C_DIM 1024
#define NH    16
#define HD    64
#define BATCH 2

// ---------------- scratch ---------------------------------------------------
__device__ __nv_bfloat16 g_Wq_hi[(size_t)3 * C_DIM * C_DIM];
__device__ __nv_bfloat16 g_Wq_lo[(size_t)3 * C_DIM * C_DIM];
__device__ __nv_bfloat16 g_Wo_hi[(size_t)C_DIM * C_DIM];
__device__ __nv_bfloat16 g_Wo_lo[(size_t)C_DIM * C_DIM];
__device__ __nv_bfloat16 g_xT_hi[(size_t)BATCH * S_LEN * C_DIM];
__device__ __nv_bfloat16 g_xT_lo[(size_t)BATCH * S_LEN * C_DIM];
__device__ __nv_bfloat16 g_z_hi[(size_t)BATCH * S_LEN * C_DIM];
__device__ __nv_bfloat16 g_z_lo[(size_t)BATCH * S_LEN * C_DIM];
// q (pre-scaled 1/8), k, v as bf16 hi/lo, layout [b][head][s][hd]
__device__ __nv_bfloat16 g_q_hi[(size_t)BATCH * NH * S_LEN * HD];
__device__ __nv_bfloat16 g_q_lo[(size_t)BATCH * NH * S_LEN * HD];
__device__ __nv_bfloat16 g_k_hi[(size_t)BATCH * NH * S_LEN * HD];
__device__ __nv_bfloat16 g_k_lo[(size_t)BATCH * NH * S_LEN * HD];
__device__ __nv_bfloat16 g_v_hi[(size_t)BATCH * NH * S_LEN * HD];
__device__ __nv_bfloat16 g_v_lo[(size_t)BATCH * NH * S_LEN * HD];

// ---------------- warp-mma helpers ------------------------------------------
__device__ __forceinline__ uint32_t smem_u32(const void* p) {
    uint32_t a;
    asm("{ .reg .u64 t; cvta.to.shared.u64 t, %1; cvt.u32.u64 %0, t; }" : "=r"(a) : "l"(p));
    return a;
}
__device__ __forceinline__ void ldsm4(uint32_t* r, uint32_t addr) {
    asm volatile("ldmatrix.sync.aligned.m8n8.x4.shared.b16 {%0,%1,%2,%3}, [%4];"
                 : "=r"(r[0]), "=r"(r[1]), "=r"(r[2]), "=r"(r[3]) : "r"(addr));
}
__device__ __forceinline__ void ldsm4t(uint32_t* r, uint32_t addr) {
    asm volatile("ldmatrix.sync.aligned.m8n8.x4.trans.shared.b16 {%0,%1,%2,%3}, [%4];"
                 : "=r"(r[0]), "=r"(r[1]), "=r"(r[2]), "=r"(r[3]) : "r"(addr));
}
__device__ __forceinline__ void mma_bf16(float* c, const uint32_t* a,
                                         uint32_t b0, uint32_t b1) {
    asm volatile(
        "mma.sync.aligned.m16n8k16.row.col.f32.bf16.bf16.f32 "
        "{%0,%1,%2,%3}, {%4,%5,%6,%7}, {%8,%9}, {%0,%1,%2,%3};"
        : "+f"(c[0]), "+f"(c[1]), "+f"(c[2]), "+f"(c[3])
        : "r"(a[0]), "r"(a[1]), "r"(a[2]), "r"(a[3]), "r"(b0), "r"(b1));
}

// ---------------- prep kernels ----------------------------------------------
__global__ void split_kernel(const float* __restrict__ src,
                             __nv_bfloat16* __restrict__ hi,
                             __nv_bfloat16* __restrict__ lo, int n4) {
    int i = blockIdx.x * 256 + threadIdx.x;
    if (i >= n4) return;
    float4 v = reinterpret_cast<const float4*>(src)[i];
    __nv_bfloat16 h0 = __float2bfloat16(v.x), h1 = __float2bfloat16(v.y);
    __nv_bfloat16 h2 = __float2bfloat16(v.z), h3 = __float2bfloat16(v.w);
    __nv_bfloat162 hh0{h0, h1}, hh1{h2, h3};
    __nv_bfloat162 ll0{__float2bfloat16(v.x - __bfloat162float(h0)),
                       __float2bfloat16(v.y - __bfloat162float(h1))};
    __nv_bfloat162 ll1{__float2bfloat16(v.z - __bfloat162float(h2)),
                       __float2bfloat16(v.w - __bfloat162float(h3))};
    *reinterpret_cast<__nv_bfloat162*>(hi + i * 4)     = hh0;
    *reinterpret_cast<__nv_bfloat162*>(hi + i * 4 + 2) = hh1;
    *reinterpret_cast<__nv_bfloat162*>(lo + i * 4)     = ll0;
    *reinterpret_cast<__nv_bfloat162*>(lo + i * 4 + 2) = ll1;
}

__global__ void xpose_split(const float* __restrict__ x) {
    __shared__ float tile[32][33];
    int b = blockIdx.z, t0 = blockIdx.x * 32, c0 = blockIdx.y * 32;
    int tx = threadIdx.x, ty = threadIdx.y;
    for (int i = ty; i < 32; i += 8)
        tile[i][tx] = x[((size_t)b * C_DIM + c0 + i) * S_LEN + t0 + tx];
    __syncthreads();
    for (int i = ty; i < 32; i += 8) {
        float v = tile[tx][i];
        size_t oi = ((size_t)b * S_LEN + t0 + i) * C_DIM + c0 + tx;
        __nv_bfloat16 h = __float2bfloat16(v);
        g_xT_hi[oi] = h;
        g_xT_lo[oi] = __float2bfloat16(v - __bfloat162float(h));
    }
}

// ---------------- mma.sync GEMM core ------------------------------------------
#define GPITCH 40
#define TBYTES (128 * GPITCH * 2)
#define STBYTES (4 * TBYTES)

struct Frag { float acc[2][8][4]; };

__device__ __forceinline__ void fill_stage(
    char* stage, int tid, int k0,
    const __nv_bfloat16* Ah, const __nv_bfloat16* Al,
    const __nv_bfloat16* Bh, const __nv_bfloat16* Bl) {
    int row = tid >> 1, half = tid & 1;
    size_t go = (size_t)row * C_DIM + k0 + half * 16;
    uint32_t so = row * (GPITCH * 2) + half * 32;
    const __nv_bfloat16* srcs[4] = {Ah, Al, Bh, Bl};
#pragma unroll
    for (int t4 = 0; t4 < 4; t4++) {
        const uint4* g = reinterpret_cast<const uint4*>(srcs[t4] + go);
        uint4 v0 = g[0], v1 = g[1];
        char* s = stage + t4 * TBYTES + so;
        *reinterpret_cast<uint4*>(s)      = v0;
        *reinterpret_cast<uint4*>(s + 16) = v1;
    }
}

__device__ __forceinline__ void compute_stage(
    uint32_t st, int lane, int wm, int wn, Frag& f) {
    uint32_t Ah_s = st, Al_s = st + TBYTES, Bh_s = st + 2 * TBYTES, Bl_s = st + 3 * TBYTES;
    int bgrp = lane >> 3, br = lane & 7;
    int brow = wn * 64 + (bgrp >> 1) * 8 + br;
    int bcolh = (bgrp & 1) * 8;
    int ar = lane & 15, acolh = (lane >> 4) * 8;
#pragma unroll
    for (int ks = 0; ks < 2; ks++) {
        uint32_t ah[2][4], al[2][4];
#pragma unroll
        for (int mi = 0; mi < 2; mi++) {
            uint32_t off = ((wm * 32 + mi * 16 + ar) * GPITCH + ks * 16 + acolh) * 2;
            ldsm4(ah[mi], Ah_s + off);
            ldsm4(al[mi], Al_s + off);
        }
        uint32_t bb[4][4];
#pragma unroll
        for (int nj = 0; nj < 4; nj++) {
            uint32_t off = ((brow + nj * 16) * GPITCH + ks * 16 + bcolh) * 2;
            ldsm4(bb[nj], Bh_s + off);
        }
#pragma unroll
        for (int mi = 0; mi < 2; mi++)
#pragma unroll
            for (int nj = 0; nj < 4; nj++) {
                mma_bf16(f.acc[mi][nj * 2],     ah[mi], bb[nj][0], bb[nj][1]);
                mma_bf16(f.acc[mi][nj * 2 + 1], ah[mi], bb[nj][2], bb[nj][3]);
                mma_bf16(f.acc[mi][nj * 2],     al[mi], bb[nj][0], bb[nj][1]);
                mma_bf16(f.acc[mi][nj * 2 + 1], al[mi], bb[nj][2], bb[nj][3]);
            }
#pragma unroll
        for (int nj = 0; nj < 4; nj++) {
            uint32_t off = ((brow + nj * 16) * GPITCH + ks * 16 + bcolh) * 2;
            ldsm4(bb[nj], Bl_s + off);
        }
#pragma unroll
        for (int mi = 0; mi < 2; mi++)
#pragma unroll
            for (int nj = 0; nj < 4; nj++) {
                mma_bf16(f.acc[mi][nj * 2],     ah[mi], bb[nj][0], bb[nj][1]);
                mma_bf16(f.acc[mi][nj * 2 + 1], ah[mi], bb[nj][2], bb[nj][3]);
            }
    }
}

__device__ __forceinline__ void gemm_body(
    char* sm, uint32_t smb, int tid, Frag& f,
    const __nv_bfloat16* Ah, const __nv_bfloat16* Al,
    const __nv_bfloat16* Bh, const __nv_bfloat16* Bl) {
    int lane = tid & 31, wid = tid >> 5;
    int wm = wid & 3, wn = wid >> 2;
    fill_stage(sm, tid, 0, Ah, Al, Bh, Bl);
    __syncthreads();
    for (int ch = 0; ch < C_DIM / 32; ch++) {
        if (ch + 1 < C_DIM / 32)
            fill_stage(sm + ((ch + 1) & 1) * STBYTES, tid, (ch + 1) * 32, Ah, Al, Bh, Bl);
        compute_stage(smb + (ch & 1) * STBYTES, lane, wm, wn, f);
        __syncthreads();
    }
}

// ---------------- QKV projection (mma.sync) -----------------------------------
__global__ __launch_bounds__(256)
void qkv_tc(const float* __restrict__ bias) {
    extern __shared__ char sm[];
    uint32_t smb = smem_u32(sm);
    int tid = threadIdx.x;
    int b = blockIdx.z, m0 = blockIdx.y * 128, n0 = blockIdx.x * 128;

    Frag f;
#pragma unroll
    for (int mi = 0; mi < 2; mi++)
#pragma unroll
        for (int ni = 0; ni < 8; ni++)
#pragma unroll
            for (int r = 0; r < 4; r++) f.acc[mi][ni][r] = 0.0f;

    gemm_body(sm, smb, tid, f,
              g_Wq_hi + (size_t)m0 * C_DIM, g_Wq_lo + (size_t)m0 * C_DIM,
              g_xT_hi + ((size_t)b * S_LEN + n0) * C_DIM,
              g_xT_lo + ((size_t)b * S_LEN + n0) * C_DIM);

    int lane = tid & 31, wid = tid >> 5;
    int wm = wid & 3, wn = wid >> 2;
    int which = m0 >> 10;
    __nv_bfloat16* hib = (which == 0) ? g_q_hi : (which == 1) ? g_k_hi : g_v_hi;
    __nv_bfloat16* lob = (which == 0) ? g_q_lo : (which == 1) ? g_k_lo : g_v_lo;
    float scale = (which == 0) ? 0.125f : 1.0f;
#pragma unroll
    for (int mi = 0; mi < 2; mi++) {
#pragma unroll
        for (int rg = 0; rg < 2; rg++) {
            int m = m0 + wm * 32 + mi * 16 + (lane >> 2) + rg * 8;
            int head = (m >> 6) & 15, d = m & 63;
            float bv = bias[m];
            __nv_bfloat16* dh = hib + ((size_t)(b * NH + head)) * S_LEN * HD + d;
            __nv_bfloat16* dl = lob + ((size_t)(b * NH + head)) * S_LEN * HD + d;
#pragma unroll
            for (int ni = 0; ni < 8; ni++) {
                int t = n0 + wn * 64 + ni * 8 + ((lane & 3) << 1);
                float v0 = (f.acc[mi][ni][rg * 2 + 0] + bv) * scale;
                float v1 = (f.acc[mi][ni][rg * 2 + 1] + bv) * scale;
                __nv_bfloat16 h0 = __float2bfloat16(v0), h1 = __float2bfloat16(v1);
                dh[(size_t)t * HD]       = h0;
                dh[(size_t)(t + 1) * HD] = h1;
                dl[(size_t)t * HD]       = __float2bfloat16(v0 - __bfloat162float(h0));
                dl[(size_t)(t + 1) * HD] = __float2bfloat16(v1 - __bfloat162float(h1));
            }
        }
    }
}

// ---------------- Output projection (mma.sync) --------------------------------
__global__ __launch_bounds__(256)
void out_tc(const float* __restrict__ bo, float* __restrict__ out) {
    extern __shared__ char sm[];
    uint32_t smb = smem_u32(sm);
    int tid = threadIdx.x;
    int b = blockIdx.z, m0 = blockIdx.y * 128, n0 = blockIdx.x * 128;

    Frag f;
#pragma unroll
    for (int mi = 0; mi < 2; mi++)
#pragma unroll
        for (int ni = 0; ni < 8; ni++)
#pragma unroll
            for (int r = 0; r < 4; r++) f.acc[mi][ni][r] = 0.0f;

    gemm_body(sm, smb, tid, f,
              g_Wo_hi + (size_t)m0 * C_DIM, g_Wo_lo + (size_t)m0 * C_DIM,
              g_z_hi + ((size_t)b * S_LEN + n0) * C_DIM,
              g_z_lo + ((size_t)b * S_LEN + n0) * C_DIM);

    int lane = tid & 31, wid = tid >> 5;
    int wm = wid & 3, wn = wid >> 2;
#pragma unroll
    for (int mi = 0; mi < 2; mi++) {
#pragma unroll
        for (int rg = 0; rg < 2; rg++) {
            int m = m0 + wm * 32 + mi * 16 + (lane >> 2) + rg * 8;
            float bv = bo[m];
            float* dst = out + ((size_t)b * C_DIM + m) * S_LEN;
#pragma unroll
            for (int ni = 0; ni < 8; ni++) {
                int t = n0 + wn * 64 + ni * 8 + ((lane & 3) << 1);
                float2 v = {f.acc[mi][ni][rg * 2 + 0] + bv,
                            f.acc[mi][ni][rg * 2 + 1] + bv};
                *reinterpret_cast<float2*>(dst + t) = v;
            }
        }
    }
}

// ---------------- Flash attention (mma.sync tensor cores) ----------------------
#define QPITCH 72
#define SPITCH 68

__global__ __launch_bounds__(256, 1)
void attn_tc() {
    extern __shared__ char sm[];
    __nv_bfloat16* Qh = (__nv_bfloat16*)sm;           // [128][72]
    __nv_bfloat16* Ql = Qh + 128 * QPITCH;
    __nv_bfloat16* Kh = Ql + 128 * QPITCH;            // [64][72]
    __nv_bfloat16* Kl = Kh + 64 * QPITCH;
    __nv_bfloat16* Vh = Kl + 64 * QPITCH;
    __nv_bfloat16* Vl = Vh + 64 * QPITCH;
    __nv_bfloat16* Ph = Vl + 64 * QPITCH;             // [128][72]
    __nv_bfloat16* Pl = Ph + 128 * QPITCH;
    float* S    = (float*)(Pl + 128 * QPITCH);        // [128][68]
    float* mrow = S + 128 * SPITCH;
    float* lrow = mrow + 128;
    float* arow = lrow + 128;

    uint32_t Qh_s = smem_u32(Qh), Ql_s = smem_u32(Ql);
    uint32_t Kh_s = smem_u32(Kh), Kl_s = smem_u32(Kl);
    uint32_t Vh_s = smem_u32(Vh), Vl_s = smem_u32(Vl);
    uint32_t Ph_s = smem_u32(Ph), Pl_s = smem_u32(Pl);

    int head = blockIdx.y, b = blockIdx.z;
    int tid = threadIdx.x, lane = tid & 31, wid = tid >> 5;
    int wm = wid & 3, wn = wid >> 2;

    size_t base = ((size_t)(b * NH + head)) * S_LEN * HD;
    const __nv_bfloat16* qhp = g_q_hi + base;
    const __nv_bfloat16* qlp = g_q_lo + base;
    const __nv_bfloat16* khp = g_k_hi + base;
    const __nv_bfloat16* klp = g_k_lo + base;
    const __nv_bfloat16* vhp = g_v_hi + base;
    const __nv_bfloat16* vlp = g_v_lo + base;

    int ar = lane & 15, ach = (lane >> 4) * 8;
    int bg = lane >> 3, br = lane & 7;
    int krow_off = ((bg >> 1) * 8 + br) * QPITCH + (bg & 1) * 8;   // K frag addr piece
    int vrow = ((lane >> 3) & 1) * 8 + (lane & 7);                 // V trans pieces
    int vcol = (lane >> 4) * 8;

    for (int rep = 0; rep < 2; rep++) {
        int qt = rep == 0 ? (17 - blockIdx.x) : blockIdx.x;
        int q0 = qt * 128;

        for (int i = tid; i < 1024; i += 256) {
            int r = i >> 3, c8 = (i & 7) * 8;
            uint32_t so = r * QPITCH + c8;
            size_t go = (size_t)(q0 + r) * HD + c8;
            *(uint4*)(Qh + so) = *(const uint4*)(qhp + go);
            *(uint4*)(Ql + so) = *(const uint4*)(qlp + go);
        }
        if (tid < 128) { mrow[tid] = -1e30f; lrow[tid] = 0.0f; }
        float o[2][4][4] = {};
        __syncthreads();

        int nkt = 2 * qt + 2;
        for (int kt = 0; kt < nkt; kt++) {
            int c0 = kt * 64;
            for (int i = tid; i < 512; i += 256) {
                int r = i >> 3, c8 = (i & 7) * 8;
                uint32_t so = r * QPITCH + c8;
                size_t go = (size_t)(c0 + r) * HD + c8;
                *(uint4*)(Kh + so) = *(const uint4*)(khp + go);
                *(uint4*)(Kl + so) = *(const uint4*)(klp + go);
                *(uint4*)(Vh + so) = *(const uint4*)(vhp + go);
                *(uint4*)(Vl + so) = *(const uint4*)(vlp + go);
            }
            __syncthreads();

            // ---- S = Q K^T (3-pass hi/lo) ----
            float s[2][4][4] = {};
#pragma unroll
            for (int ks = 0; ks < 4; ks++) {
                uint32_t ah[2][4], al[2][4];
#pragma unroll
                for (int mi = 0; mi < 2; mi++) {
                    uint32_t off = ((wm * 32 + mi * 16 + ar) * QPITCH + ks * 16 + ach) * 2;
                    ldsm4(ah[mi], Qh_s + off);
                    ldsm4(al[mi], Ql_s + off);
                }
#pragma unroll
                for (int nj2 = 0; nj2 < 2; nj2++) {
                    uint32_t off = ((wn * 32 + nj2 * 16) * QPITCH + ks * 16) * 2 + krow_off * 2;
                    uint32_t kk[4];
                    ldsm4(kk, Kh_s + off);
#pragma unroll
                    for (int mi = 0; mi < 2; mi++) {
                        mma_bf16(s[mi][nj2 * 2],     ah[mi], kk[0], kk[1]);
                        mma_bf16(s[mi][nj2 * 2 + 1], ah[mi], kk[2], kk[3]);
                        mma_bf16(s[mi][nj2 * 2],     al[mi], kk[0], kk[1]);
                        mma_bf16(s[mi][nj2 * 2 + 1], al[mi], kk[2], kk[3]);
                    }
                    ldsm4(kk, Kl_s + off);
#pragma unroll
                    for (int mi = 0; mi < 2; mi++) {
                        mma_bf16(s[mi][nj2 * 2],     ah[mi], kk[0], kk[1]);
                        mma_bf16(s[mi][nj2 * 2 + 1], ah[mi], kk[2], kk[3]);
                    }
                }
            }
            // mask + store S (fp32)
            bool dt = (c0 + 63 > q0);
#pragma unroll
            for (int mi = 0; mi < 2; mi++)
#pragma unroll
                for (int nf = 0; nf < 4; nf++) {
                    int col = wn * 32 + nf * 8 + ((lane & 3) << 1);
#pragma unroll
                    for (int rg = 0; rg < 2; rg++) {
                        int r = wm * 32 + mi * 16 + (lane >> 2) + rg * 8;
                        float v0 = s[mi][nf][rg * 2], v1 = s[mi][nf][rg * 2 + 1];
                        if (dt) {
                            if (c0 + col     > q0 + r) v0 -= 10000.0f;
                            if (c0 + col + 1 > q0 + r) v1 -= 10000.0f;
                        }
                        *(float2*)(S + r * SPITCH + col) = make_float2(v0, v1);
                    }
                }
            __syncthreads();

            // ---- SIMT online softmax (2 threads / row) ----
            {
                int r = tid >> 1, g = tid & 1;
                const float* srow = S + r * SPITCH + g * 32;
                float vals[32];
                float mx = -1e30f;
#pragma unroll
                for (int c4 = 0; c4 < 8; c4++) {
                    float4 v = *(const float4*)(srow + c4 * 4);
                    vals[c4 * 4 + 0] = v.x; vals[c4 * 4 + 1] = v.y;
                    vals[c4 * 4 + 2] = v.z; vals[c4 * 4 + 3] = v.w;
                    mx = fmaxf(mx, fmaxf(fmaxf(v.x, v.y), fmaxf(v.z, v.w)));
                }
                mx = fmaxf(mx, __shfl_xor_sync(0xffffffffu, mx, 1));
                float mold = mrow[r];
                float mnew = fmaxf(mold, mx);
                float lsum = 0.0f;
                __nv_bfloat16* ph = Ph + r * QPITCH + g * 32;
                __nv_bfloat16* pl = Pl + r * QPITCH + g * 32;
#pragma unroll
                for (int c2 = 0; c2 < 16; c2++) {
                    float p0 = __expf(vals[c2 * 2]     - mnew);
                    float p1 = __expf(vals[c2 * 2 + 1] - mnew);
                    lsum += p0 + p1;
                    __nv_bfloat16 h0 = __float2bfloat16(p0), h1 = __float2bfloat16(p1);
                    *(__nv_bfloat162*)(ph + c2 * 2) = __nv_bfloat162{h0, h1};
                    *(__nv_bfloat162*)(pl + c2 * 2) =
                        __nv_bfloat162{__float2bfloat16(p0 - __bfloat162float(h0)),
                                       __float2bfloat16(p1 - __bfloat162float(h1))};
                }
                lsum += __shfl_xor_sync(0xffffffffu, lsum, 1);
                if (g == 0) {
                    arow[r] = __expf(mold - mnew);
                    lrow[r] = lrow[r] * arow[r] + lsum;
                    mrow[r] = mnew;
                }
            }
            __syncthreads();

            // ---- O = O*alpha + P V (3-pass hi/lo) ----
            float alr[2][2];
#pragma unroll
            for (int mi = 0; mi < 2; mi++)
#pragma unroll
                for (int rg = 0; rg < 2; rg++)
                    alr[mi][rg] = arow[wm * 32 + mi * 16 + (lane >> 2) + rg * 8];
#pragma unroll
            for (int mi = 0; mi < 2; mi++)
#pragma unroll
                for (int nf = 0; nf < 4; nf++)
#pragma unroll
                    for (int rg = 0; rg < 2; rg++) {
                        o[mi][nf][rg * 2]     *= alr[mi][rg];
                        o[mi][nf][rg * 2 + 1] *= alr[mi][rg];
                    }
#pragma unroll
            for (int ks = 0; ks < 4; ks++) {
                uint32_t ph[2][4], pl[2][4];
#pragma unroll
                for (int mi = 0; mi < 2; mi++) {
                    uint32_t off = ((wm * 32 + mi * 16 + ar) * QPITCH + ks * 16 + ach) * 2;
                    ldsm4(ph[mi], Ph_s + off);
                    ldsm4(pl[mi], Pl_s + off);
                }
#pragma unroll
                for (int nj2 = 0; nj2 < 2; nj2++) {
                    uint32_t off = ((ks * 16 + vrow) * QPITCH + wn * 32 + nj2 * 16 + vcol) * 2;
                    uint32_t vv[4];
                    ldsm4t(vv, Vh_s + off);
#pragma unroll
                    for (int mi = 0; mi < 2; mi++) {
                        mma_bf16(o[mi][nj2 * 2],     ph[mi], vv[0], vv[1]);
                        mma_bf16(o[mi][nj2 * 2 + 1], ph[mi], vv[2], vv[3]);
                        mma_bf16(o[mi][nj2 * 2],     pl[mi], vv[0], vv[1]);
                        mma_bf16(o[mi][nj2 * 2 + 1], pl[mi], vv[2], vv[3]);
                    }
                    ldsm4t(vv, Vl_s + off);
#pragma unroll
                    for (int mi = 0; mi < 2; mi++) {
                        mma_bf16(o[mi][nj2 * 2],     ph[mi], vv[0], vv[1]);
                        mma_bf16(o[mi][nj2 * 2 + 1], ph[mi], vv[2], vv[3]);
                    }
                }
            }
            __syncthreads();
        }

        // ---- epilogue: z = O / l, bf16 hi/lo ----
#pragma unroll
        for (int mi = 0; mi < 2; mi++)
#pragma unroll
            for (int rg = 0; rg < 2; rg++) {
                int r = wm * 32 + mi * 16 + (lane >> 2) + rg * 8;
                float linv = 1.0f / lrow[r];
                int t = q0 + r;
#pragma unroll
                for (int nf = 0; nf < 4; nf++) {
                    int d = wn * 32 + nf * 8 + ((lane & 3) << 1);
                    size_t zi = ((size_t)b * S_LEN + t) * C_DIM + head * HD + d;
                    float f0 = o[mi][nf][rg * 2] * linv;
                    float f1 = o[mi][nf][rg * 2 + 1] * linv;
                    __nv_bfloat16 h0 = __float2bfloat16(f0), h1 = __float2bfloat16(f1);
                    *(__nv_bfloat162*)(g_z_hi + zi) = __nv_bfloat162{h0, h1};
                    *(__nv_bfloat162*)(g_z_lo + zi) =
                        __nv_bfloat162{__float2bfloat16(f0 - __bfloat162float(h0)),
                                       __float2bfloat16(f1 - __bfloat162float(h1))};
                }
            }
        __syncthreads();
    }
}

// ---------------------------------------------------------------------------

extern "C" void kernel_launch(void* const* d_in, const int* in_sizes, int n_in,
                              void* d_out, int out_size) {
    const float* x    = (const float*)d_in[0];
    const float* Wqkv = (const float*)d_in[1];
    const float* bqkv = (const float*)d_in[2];
    const float* Wo   = (const float*)d_in[3];
    const float* bo   = (const float*)d_in[4];
    float* out = (float*)d_out;

    __nv_bfloat16 *wq_hi, *wq_lo, *wo_hi, *wo_lo;
    cudaGetSymbolAddress((void**)&wq_hi, g_Wq_hi);
    cudaGetSymbolAddress((void**)&wq_lo, g_Wq_lo);
    cudaGetSymbolAddress((void**)&wo_hi, g_Wo_hi);
    cudaGetSymbolAddress((void**)&wo_lo, g_Wo_lo);

    int nq4 = 3 * C_DIM * C_DIM / 4;
    split_kernel<<<(nq4 + 255) / 256, 256>>>(Wqkv, wq_hi, wq_lo, nq4);
    int no4 = C_DIM * C_DIM / 4;
    split_kernel<<<(no4 + 255) / 256, 256>>>(Wo, wo_hi, wo_lo, no4);

    dim3 gT(S_LEN / 32, C_DIM / 32, BATCH);
    xpose_split<<<gT, dim3(32, 8)>>>(x);

    size_t gsmem = 2 * STBYTES;
    cudaFuncSetAttribute(qkv_tc, cudaFuncAttributeMaxDynamicSharedMemorySize, (int)gsmem);
    cudaFuncSetAttribute(out_tc, cudaFuncAttributeMaxDynamicSharedMemorySize, (int)gsmem);

    dim3 gA(S_LEN / 128, 3 * C_DIM / 128, BATCH);
    qkv_tc<<<gA, 256, gsmem>>>(bqkv);

    size_t asmem = (size_t)(128 * QPITCH * 2 + 64 * QPITCH * 4 + 128 * QPITCH * 2) * 2
                 + (size_t)(128 * SPITCH + 3 * 128) * 4;
    cudaFuncSetAttribute(attn_tc, cudaFuncAttributeMaxDynamicSharedMemorySize, (int)asmem);
    dim3 gB(9, NH, BATCH);
    attn_tc<<<gB, 256, asmem>>>();

    dim3 gC(S_LEN / 128, C_DIM / 128, BATCH);
    out_tc<<<gC, 256, gsmem>>>(bo, out);
}

// round 6
// speedup vs baseline: 3.4928x; 1.2645x over previous
#include <cuda_runtime.h>
#include <cuda_bf16.h>
#include <cstdint>

#define S_LEN 2304
#define C_DIM 1024
#define NH    16
#define HD    64
#define BATCH 2

// ---------------- scratch ---------------------------------------------------
__device__ __nv_bfloat16 g_Wq_hi[(size_t)3 * C_DIM * C_DIM];
__device__ __nv_bfloat16 g_Wq_lo[(size_t)3 * C_DIM * C_DIM];
__device__ __nv_bfloat16 g_Wo_hi[(size_t)C_DIM * C_DIM];
__device__ __nv_bfloat16 g_Wo_lo[(size_t)C_DIM * C_DIM];
__device__ __nv_bfloat16 g_xT_hi[(size_t)BATCH * S_LEN * C_DIM];
__device__ __nv_bfloat16 g_xT_lo[(size_t)BATCH * S_LEN * C_DIM];
__device__ __nv_bfloat16 g_z_hi[(size_t)BATCH * S_LEN * C_DIM];
__device__ __nv_bfloat16 g_z_lo[(size_t)BATCH * S_LEN * C_DIM];
// q (pre-scaled 1/8), k, v as bf16 hi/lo, layout [b][head][s][hd]
__device__ __nv_bfloat16 g_q_hi[(size_t)BATCH * NH * S_LEN * HD];
__device__ __nv_bfloat16 g_q_lo[(size_t)BATCH * NH * S_LEN * HD];
__device__ __nv_bfloat16 g_k_hi[(size_t)BATCH * NH * S_LEN * HD];
__device__ __nv_bfloat16 g_k_lo[(size_t)BATCH * NH * S_LEN * HD];
__device__ __nv_bfloat16 g_v_hi[(size_t)BATCH * NH * S_LEN * HD];
__device__ __nv_bfloat16 g_v_lo[(size_t)BATCH * NH * S_LEN * HD];

// ---------------- helpers ----------------------------------------------------
__device__ __forceinline__ uint32_t smem_u32(const void* p) {
    uint32_t a;
    asm("{ .reg .u64 t; cvta.to.shared.u64 t, %1; cvt.u32.u64 %0, t; }" : "=r"(a) : "l"(p));
    return a;
}
__device__ __forceinline__ void ldsm4(uint32_t* r, uint32_t addr) {
    asm volatile("ldmatrix.sync.aligned.m8n8.x4.shared.b16 {%0,%1,%2,%3}, [%4];"
                 : "=r"(r[0]), "=r"(r[1]), "=r"(r[2]), "=r"(r[3]) : "r"(addr));
}
__device__ __forceinline__ void ldsm4t(uint32_t* r, uint32_t addr) {
    asm volatile("ldmatrix.sync.aligned.m8n8.x4.trans.shared.b16 {%0,%1,%2,%3}, [%4];"
                 : "=r"(r[0]), "=r"(r[1]), "=r"(r[2]), "=r"(r[3]) : "r"(addr));
}
__device__ __forceinline__ void mma_bf16(float* c, const uint32_t* a,
                                         uint32_t b0, uint32_t b1) {
    asm volatile(
        "mma.sync.aligned.m16n8k16.row.col.f32.bf16.bf16.f32 "
        "{%0,%1,%2,%3}, {%4,%5,%6,%7}, {%8,%9}, {%0,%1,%2,%3};"
        : "+f"(c[0]), "+f"(c[1]), "+f"(c[2]), "+f"(c[3])
        : "r"(a[0]), "r"(a[1]), "r"(a[2]), "r"(a[3]), "r"(b0), "r"(b1));
}
#define CP16(dst, src) asm volatile("cp.async.cg.shared.global [%0], [%1], 16;" :: "r"(dst), "l"(src))
#define CP_COMMIT()    asm volatile("cp.async.commit_group;" ::: "memory")
#define CP_WAIT0()     asm volatile("cp.async.wait_group 0;" ::: "memory")
#define CP_WAIT1()     asm volatile("cp.async.wait_group 1;" ::: "memory")

__device__ __forceinline__ uint32_t pack_hi(float a, float b, uint32_t& lo) {
    __nv_bfloat162 h = __float22bfloat162_rn(make_float2(a, b));
    float2 hf = __bfloat1622float2(h);
    __nv_bfloat162 l = __float22bfloat162_rn(make_float2(a - hf.x, b - hf.y));
    lo = *reinterpret_cast<uint32_t*>(&l);
    return *reinterpret_cast<uint32_t*>(&h);
}

// ---------------- prep kernels ----------------------------------------------
__global__ void split_kernel(const float* __restrict__ src,
                             __nv_bfloat16* __restrict__ hi,
                             __nv_bfloat16* __restrict__ lo, int n4) {
    int i = blockIdx.x * 256 + threadIdx.x;
    if (i >= n4) return;
    float4 v = reinterpret_cast<const float4*>(src)[i];
    __nv_bfloat16 h0 = __float2bfloat16(v.x), h1 = __float2bfloat16(v.y);
    __nv_bfloat16 h2 = __float2bfloat16(v.z), h3 = __float2bfloat16(v.w);
    __nv_bfloat162 hh0{h0, h1}, hh1{h2, h3};
    __nv_bfloat162 ll0{__float2bfloat16(v.x - __bfloat162float(h0)),
                       __float2bfloat16(v.y - __bfloat162float(h1))};
    __nv_bfloat162 ll1{__float2bfloat16(v.z - __bfloat162float(h2)),
                       __float2bfloat16(v.w - __bfloat162float(h3))};
    *reinterpret_cast<__nv_bfloat162*>(hi + i * 4)     = hh0;
    *reinterpret_cast<__nv_bfloat162*>(hi + i * 4 + 2) = hh1;
    *reinterpret_cast<__nv_bfloat162*>(lo + i * 4)     = ll0;
    *reinterpret_cast<__nv_bfloat162*>(lo + i * 4 + 2) = ll1;
}

__global__ void xpose_split(const float* __restrict__ x) {
    __shared__ float tile[32][33];
    int b = blockIdx.z, t0 = blockIdx.x * 32, c0 = blockIdx.y * 32;
    int tx = threadIdx.x, ty = threadIdx.y;
    for (int i = ty; i < 32; i += 8)
        tile[i][tx] = x[((size_t)b * C_DIM + c0 + i) * S_LEN + t0 + tx];
    __syncthreads();
    for (int i = ty; i < 32; i += 8) {
        float v = tile[tx][i];
        size_t oi = ((size_t)b * S_LEN + t0 + i) * C_DIM + c0 + tx;
        __nv_bfloat16 h = __float2bfloat16(v);
        g_xT_hi[oi] = h;
        g_xT_lo[oi] = __float2bfloat16(v - __bfloat162float(h));
    }
}

// ---------------- mma.sync GEMM core (cp.async fills) --------------------------
#define GPITCH 40
#define TBYTES (128 * GPITCH * 2)
#define STBYTES (4 * TBYTES)

struct Frag { float acc[2][8][4]; };

__device__ __forceinline__ void fill_async(
    uint32_t stage_s, int tid, int k0,
    const __nv_bfloat16* Ah, const __nv_bfloat16* Al,
    const __nv_bfloat16* Bh, const __nv_bfloat16* Bl) {
    int row = tid >> 1, half = tid & 1;
    size_t go = (size_t)row * C_DIM + k0 + half * 16;
    uint32_t so = row * (GPITCH * 2) + half * 32;
    const __nv_bfloat16* srcs[4] = {Ah, Al, Bh, Bl};
#pragma unroll
    for (int t4 = 0; t4 < 4; t4++) {
        const char* s = (const char*)(srcs[t4] + go);
        uint32_t d = stage_s + t4 * TBYTES + so;
        CP16(d, s);
        CP16(d + 16, s + 16);
    }
    CP_COMMIT();
}

__device__ __forceinline__ void compute_stage(
    uint32_t st, int lane, int wm, int wn, Frag& f) {
    uint32_t Ah_s = st, Al_s = st + TBYTES, Bh_s = st + 2 * TBYTES, Bl_s = st + 3 * TBYTES;
    int bgrp = lane >> 3, br = lane & 7;
    int brow = wn * 64 + (bgrp >> 1) * 8 + br;
    int bcolh = (bgrp & 1) * 8;
    int ar = lane & 15, acolh = (lane >> 4) * 8;
#pragma unroll
    for (int ks = 0; ks < 2; ks++) {
        uint32_t ah[2][4], al[2][4];
#pragma unroll
        for (int mi = 0; mi < 2; mi++) {
            uint32_t off = ((wm * 32 + mi * 16 + ar) * GPITCH + ks * 16 + acolh) * 2;
            ldsm4(ah[mi], Ah_s + off);
            ldsm4(al[mi], Al_s + off);
        }
        uint32_t bb[4][4];
#pragma unroll
        for (int nj = 0; nj < 4; nj++) {
            uint32_t off = ((brow + nj * 16) * GPITCH + ks * 16 + bcolh) * 2;
            ldsm4(bb[nj], Bh_s + off);
        }
#pragma unroll
        for (int mi = 0; mi < 2; mi++)
#pragma unroll
            for (int nj = 0; nj < 4; nj++) {
                mma_bf16(f.acc[mi][nj * 2],     ah[mi], bb[nj][0], bb[nj][1]);
                mma_bf16(f.acc[mi][nj * 2 + 1], ah[mi], bb[nj][2], bb[nj][3]);
                mma_bf16(f.acc[mi][nj * 2],     al[mi], bb[nj][0], bb[nj][1]);
                mma_bf16(f.acc[mi][nj * 2 + 1], al[mi], bb[nj][2], bb[nj][3]);
            }
#pragma unroll
        for (int nj = 0; nj < 4; nj++) {
            uint32_t off = ((brow + nj * 16) * GPITCH + ks * 16 + bcolh) * 2;
            ldsm4(bb[nj], Bl_s + off);
        }
#pragma unroll
        for (int mi = 0; mi < 2; mi++)
#pragma unroll
            for (int nj = 0; nj < 4; nj++) {
                mma_bf16(f.acc[mi][nj * 2],     ah[mi], bb[nj][0], bb[nj][1]);
                mma_bf16(f.acc[mi][nj * 2 + 1], ah[mi], bb[nj][2], bb[nj][3]);
            }
    }
}

__device__ __forceinline__ void gemm_body(
    uint32_t smb, int tid, Frag& f,
    const __nv_bfloat16* Ah, const __nv_bfloat16* Al,
    const __nv_bfloat16* Bh, const __nv_bfloat16* Bl) {
    int lane = tid & 31, wid = tid >> 5;
    int wm = wid & 3, wn = wid >> 2;
    const int NC = C_DIM / 32;
    fill_async(smb, tid, 0, Ah, Al, Bh, Bl);
    for (int ch = 0; ch < NC; ch++) {
        if (ch + 1 < NC) {
            fill_async(smb + ((ch + 1) & 1) * STBYTES, tid, (ch + 1) * 32, Ah, Al, Bh, Bl);
            CP_WAIT1();
        } else {
            CP_WAIT0();
        }
        __syncthreads();
        compute_stage(smb + (ch & 1) * STBYTES, lane, wm, wn, f);
        __syncthreads();
    }
}

// ---------------- QKV projection (mma.sync) -----------------------------------
__global__ __launch_bounds__(256, 2)
void qkv_tc(const float* __restrict__ bias) {
    extern __shared__ char sm[];
    uint32_t smb = smem_u32(sm);
    int tid = threadIdx.x;
    int b = blockIdx.z, m0 = blockIdx.y * 128, n0 = blockIdx.x * 128;

    Frag f;
#pragma unroll
    for (int mi = 0; mi < 2; mi++)
#pragma unroll
        for (int ni = 0; ni < 8; ni++)
#pragma unroll
            for (int r = 0; r < 4; r++) f.acc[mi][ni][r] = 0.0f;

    gemm_body(smb, tid, f,
              g_Wq_hi + (size_t)m0 * C_DIM, g_Wq_lo + (size_t)m0 * C_DIM,
              g_xT_hi + ((size_t)b * S_LEN + n0) * C_DIM,
              g_xT_lo + ((size_t)b * S_LEN + n0) * C_DIM);

    int lane = tid & 31, wid = tid >> 5;
    int wm = wid & 3, wn = wid >> 2;
    int which = m0 >> 10;
    __nv_bfloat16* hib = (which == 0) ? g_q_hi : (which == 1) ? g_k_hi : g_v_hi;
    __nv_bfloat16* lob = (which == 0) ? g_q_lo : (which == 1) ? g_k_lo : g_v_lo;
    float scale = (which == 0) ? 0.125f : 1.0f;
#pragma unroll
    for (int mi = 0; mi < 2; mi++) {
#pragma unroll
        for (int rg = 0; rg < 2; rg++) {
            int m = m0 + wm * 32 + mi * 16 + (lane >> 2) + rg * 8;
            int head = (m >> 6) & 15, d = m & 63;
            float bv = bias[m];
            __nv_bfloat16* dh = hib + ((size_t)(b * NH + head)) * S_LEN * HD + d;
            __nv_bfloat16* dl = lob + ((size_t)(b * NH + head)) * S_LEN * HD + d;
#pragma unroll
            for (int ni = 0; ni < 8; ni++) {
                int t = n0 + wn * 64 + ni * 8 + ((lane & 3) << 1);
                float v0 = (f.acc[mi][ni][rg * 2 + 0] + bv) * scale;
                float v1 = (f.acc[mi][ni][rg * 2 + 1] + bv) * scale;
                __nv_bfloat16 h0 = __float2bfloat16(v0), h1 = __float2bfloat16(v1);
                dh[(size_t)t * HD]       = h0;
                dh[(size_t)(t + 1) * HD] = h1;
                dl[(size_t)t * HD]       = __float2bfloat16(v0 - __bfloat162float(h0));
                dl[(size_t)(t + 1) * HD] = __float2bfloat16(v1 - __bfloat162float(h1));
            }
        }
    }
}

// ---------------- Output projection (mma.sync) --------------------------------
__global__ __launch_bounds__(256, 2)
void out_tc(const float* __restrict__ bo, float* __restrict__ out) {
    extern __shared__ char sm[];
    uint32_t smb = smem_u32(sm);
    int tid = threadIdx.x;
    int b = blockIdx.z, m0 = blockIdx.y * 128, n0 = blockIdx.x * 128;

    Frag f;
#pragma unroll
    for (int mi = 0; mi < 2; mi++)
#pragma unroll
        for (int ni = 0; ni < 8; ni++)
#pragma unroll
            for (int r = 0; r < 4; r++) f.acc[mi][ni][r] = 0.0f;

    gemm_body(smb, tid, f,
              g_Wo_hi + (size_t)m0 * C_DIM, g_Wo_lo + (size_t)m0 * C_DIM,
              g_z_hi + ((size_t)b * S_LEN + n0) * C_DIM,
              g_z_lo + ((size_t)b * S_LEN + n0) * C_DIM);

    int lane = tid & 31, wid = tid >> 5;
    int wm = wid & 3, wn = wid >> 2;
#pragma unroll
    for (int mi = 0; mi < 2; mi++) {
#pragma unroll
        for (int rg = 0; rg < 2; rg++) {
            int m = m0 + wm * 32 + mi * 16 + (lane >> 2) + rg * 8;
            float bv = bo[m];
            float* dst = out + ((size_t)b * C_DIM + m) * S_LEN;
#pragma unroll
            for (int ni = 0; ni < 8; ni++) {
                int t = n0 + wn * 64 + ni * 8 + ((lane & 3) << 1);
                float2 v = {f.acc[mi][ni][rg * 2 + 0] + bv,
                            f.acc[mi][ni][rg * 2 + 1] + bv};
                *reinterpret_cast<float2*>(dst + t) = v;
            }
        }
    }
}

// ---------------- Flash attention: FA2-style register layout -------------------
// 8 warps x 16 q-rows. Q persistent in smem (36KB); K/V double-buffered (2x36KB).
#define AP 72                       // bf16 pitch (144 B rows)
#define QBYTES   36864              // 128*144*2 (hi+lo)
#define KVTILE   9216               // 64*144
#define KVBUF    36864              // 4 tiles

__device__ __forceinline__ void fill_kv(
    uint32_t dst, int tid, int s0,
    const __nv_bfloat16* kh, const __nv_bfloat16* kl,
    const __nv_bfloat16* vh, const __nv_bfloat16* vl) {
#pragma unroll
    for (int i = tid; i < 512; i += 256) {
        int r = i >> 3, c = (i & 7) * 16;
        uint32_t so = r * 144 + c;
        size_t go = (size_t)(s0 + r) * HD;
        CP16(dst + so,              (const char*)(kh + go) + c);
        CP16(dst + KVTILE + so,     (const char*)(kl + go) + c);
        CP16(dst + 2 * KVTILE + so, (const char*)(vh + go) + c);
        CP16(dst + 3 * KVTILE + so, (const char*)(vl + go) + c);
    }
    CP_COMMIT();
}

__global__ __launch_bounds__(256, 2)
void attn_tc() {
    extern __shared__ char sm[];
    uint32_t smb = smem_u32(sm);
    uint32_t Q_s  = smb;
    uint32_t KV_s = smb + QBYTES;

    int head = blockIdx.y, b = blockIdx.z;
    int tid = threadIdx.x, lane = tid & 31, wid = tid >> 5;
    int r0w = wid * 16;
    int g = lane >> 2, tc = lane & 3;

    size_t base = ((size_t)(b * NH + head)) * S_LEN * HD;
    const __nv_bfloat16* qhp = g_q_hi + base;
    const __nv_bfloat16* qlp = g_q_lo + base;
    const __nv_bfloat16* khp = g_k_hi + base;
    const __nv_bfloat16* klp = g_k_lo + base;
    const __nv_bfloat16* vhp = g_v_hi + base;
    const __nv_bfloat16* vlp = g_v_lo + base;

    int ar = lane & 15, ach = (lane >> 4) * 8;
    int bg = lane >> 3, br = lane & 7;
    int krow_off = ((bg >> 1) * 8 + br) * AP + (bg & 1) * 8;
    int vrow = ((lane >> 3) & 1) * 8 + (lane & 7);
    int vcol = (lane >> 4) * 8;

    for (int rep = 0; rep < 2; rep++) {
        int qt = rep == 0 ? (17 - (int)blockIdx.x) : (int)blockIdx.x;
        int q0 = qt * 128;

        // load Q (hi/lo)
#pragma unroll
        for (int i = tid; i < 1024; i += 256) {
            int r = i >> 3, c = (i & 7) * 16;
            uint32_t so = r * 144 + c;
            size_t go = (size_t)(q0 + r) * HD;
            CP16(Q_s + so,              (const char*)(qhp + go) + c);
            CP16(Q_s + QBYTES / 2 + so, (const char*)(qlp + go) + c);
        }
        CP_COMMIT();
        CP_WAIT0();
        __syncthreads();

        float o[8][4] = {};
        float mA = -1e30f, mB = -1e30f, lA = 0.0f, lB = 0.0f;

        int nkt = 2 * qt + 2;
        fill_kv(KV_s, tid, 0, khp, klp, vhp, vlp);
        for (int kt = 0; kt < nkt; kt++) {
            int c0 = kt * 64;
            if (kt + 1 < nkt) {
                fill_kv(KV_s + ((kt + 1) & 1) * KVBUF, tid, (kt + 1) * 64, khp, klp, vhp, vlp);
                CP_WAIT1();
            } else {
                CP_WAIT0();
            }
            __syncthreads();
            uint32_t Kh_s = KV_s + (kt & 1) * KVBUF;
            uint32_t Kl_s = Kh_s + KVTILE;
            uint32_t Vh_s = Kh_s + 2 * KVTILE;
            uint32_t Vl_s = Kh_s + 3 * KVTILE;

            // ---- S = Q K^T (3-pass hi/lo) ----
            float s[8][4] = {};
#pragma unroll
            for (int kc = 0; kc < 4; kc++) {
                uint32_t qoff = ((r0w + ar) * AP + kc * 16 + ach) * 2;
                uint32_t qh[4], ql[4];
                ldsm4(qh, Q_s + qoff);
                ldsm4(ql, Q_s + QBYTES / 2 + qoff);
#pragma unroll
                for (int np = 0; np < 4; np++) {
                    uint32_t koff = (np * 16 * AP + kc * 16 + krow_off) * 2;
                    uint32_t kk[4];
                    ldsm4(kk, Kh_s + koff);
                    mma_bf16(s[np * 2],     qh, kk[0], kk[1]);
                    mma_bf16(s[np * 2 + 1], qh, kk[2], kk[3]);
                    mma_bf16(s[np * 2],     ql, kk[0], kk[1]);
                    mma_bf16(s[np * 2 + 1], ql, kk[2], kk[3]);
                    ldsm4(kk, Kl_s + koff);
                    mma_bf16(s[np * 2],     qh, kk[0], kk[1]);
                    mma_bf16(s[np * 2 + 1], qh, kk[2], kk[3]);
                }
            }

            // ---- mask (register domain) ----
            if (c0 + 63 > q0 + r0w) {
                int rowA = q0 + r0w + g, rowB = rowA + 8;
#pragma unroll
                for (int nf = 0; nf < 8; nf++) {
                    int col = c0 + nf * 8 + tc * 2;
                    if (col     > rowA) s[nf][0] -= 10000.0f;
                    if (col + 1 > rowA) s[nf][1] -= 10000.0f;
                    if (col     > rowB) s[nf][2] -= 10000.0f;
                    if (col + 1 > rowB) s[nf][3] -= 10000.0f;
                }
            }

            // ---- register softmax (quad shuffles) ----
            float pmA = -1e30f, pmB = -1e30f;
#pragma unroll
            for (int nf = 0; nf < 8; nf++) {
                pmA = fmaxf(pmA, fmaxf(s[nf][0], s[nf][1]));
                pmB = fmaxf(pmB, fmaxf(s[nf][2], s[nf][3]));
            }
            pmA = fmaxf(pmA, __shfl_xor_sync(0xffffffffu, pmA, 1));
            pmA = fmaxf(pmA, __shfl_xor_sync(0xffffffffu, pmA, 2));
            pmB = fmaxf(pmB, __shfl_xor_sync(0xffffffffu, pmB, 1));
            pmB = fmaxf(pmB, __shfl_xor_sync(0xffffffffu, pmB, 2));
            float mnA = fmaxf(mA, pmA), mnB = fmaxf(mB, pmB);
            float alA = __expf(mA - mnA), alB = __expf(mB - mnB);
            float lsA = 0.0f, lsB = 0.0f;
#pragma unroll
            for (int nf = 0; nf < 8; nf++) {
                s[nf][0] = __expf(s[nf][0] - mnA);
                s[nf][1] = __expf(s[nf][1] - mnA);
                s[nf][2] = __expf(s[nf][2] - mnB);
                s[nf][3] = __expf(s[nf][3] - mnB);
                lsA += s[nf][0] + s[nf][1];
                lsB += s[nf][2] + s[nf][3];
            }
            lsA += __shfl_xor_sync(0xffffffffu, lsA, 1);
            lsA += __shfl_xor_sync(0xffffffffu, lsA, 2);
            lsB += __shfl_xor_sync(0xffffffffu, lsB, 1);
            lsB += __shfl_xor_sync(0xffffffffu, lsB, 2);
            lA = lA * alA + lsA;
            lB = lB * alB + lsB;
            mA = mnA; mB = mnB;
#pragma unroll
            for (int nf = 0; nf < 8; nf++) {
                o[nf][0] *= alA; o[nf][1] *= alA;
                o[nf][2] *= alB; o[nf][3] *= alB;
            }

            // ---- O += P V (P rebuilt from accum frags, 3-pass hi/lo) ----
#pragma unroll
            for (int kc = 0; kc < 4; kc++) {
                uint32_t ph[4], pl[4];
                ph[0] = pack_hi(s[2 * kc][0],     s[2 * kc][1],     pl[0]);
                ph[1] = pack_hi(s[2 * kc][2],     s[2 * kc][3],     pl[1]);
                ph[2] = pack_hi(s[2 * kc + 1][0], s[2 * kc + 1][1], pl[2]);
                ph[3] = pack_hi(s[2 * kc + 1][2], s[2 * kc + 1][3], pl[3]);
#pragma unroll
                for (int np = 0; np < 4; np++) {
                    uint32_t voff = ((kc * 16 + vrow) * AP + np * 16 + vcol) * 2;
                    uint32_t vv[4];
                    ldsm4t(vv, Vh_s + voff);
                    mma_bf16(o[np * 2],     ph, vv[0], vv[1]);
                    mma_bf16(o[np * 2 + 1], ph, vv[2], vv[3]);
                    mma_bf16(o[np * 2],     pl, vv[0], vv[1]);
                    mma_bf16(o[np * 2 + 1], pl, vv[2], vv[3]);
                    ldsm4t(vv, Vl_s + voff);
                    mma_bf16(o[np * 2],     ph, vv[0], vv[1]);
                    mma_bf16(o[np * 2 + 1], ph, vv[2], vv[3]);
                }
            }
            __syncthreads();
        }

        // ---- epilogue: z = O / l, bf16 hi/lo ----
        float liA = 1.0f / lA, liB = 1.0f / lB;
        int tA = q0 + r0w + g, tB = tA + 8;
#pragma unroll
        for (int nf = 0; nf < 8; nf++) {
            int d = nf * 8 + tc * 2;
            size_t ziA = ((size_t)b * S_LEN + tA) * C_DIM + head * HD + d;
            size_t ziB = ((size_t)b * S_LEN + tB) * C_DIM + head * HD + d;
            float f0 = o[nf][0] * liA, f1 = o[nf][1] * liA;
            float f2 = o[nf][2] * liB, f3 = o[nf][3] * liB;
            uint32_t loA, loB;
            uint32_t hiA = pack_hi(f0, f1, loA);
            uint32_t hiB = pack_hi(f2, f3, loB);
            *reinterpret_cast<uint32_t*>(g_z_hi + ziA) = hiA;
            *reinterpret_cast<uint32_t*>(g_z_lo + ziA) = loA;
            *reinterpret_cast<uint32_t*>(g_z_hi + ziB) = hiB;
            *reinterpret_cast<uint32_t*>(g_z_lo + ziB) = loB;
        }
        __syncthreads();
    }
}

// ---------------------------------------------------------------------------

extern "C" void kernel_launch(void* const* d_in, const int* in_sizes, int n_in,
                              void* d_out, int out_size) {
    const float* x    = (const float*)d_in[0];
    const float* Wqkv = (const float*)d_in[1];
    const float* bqkv = (const float*)d_in[2];
    const float* Wo   = (const float*)d_in[3];
    const float* bo   = (const float*)d_in[4];
    float* out = (float*)d_out;

    __nv_bfloat16 *wq_hi, *wq_lo, *wo_hi, *wo_lo;
    cudaGetSymbolAddress((void**)&wq_hi, g_Wq_hi);
    cudaGetSymbolAddress((void**)&wq_lo, g_Wq_lo);
    cudaGetSymbolAddress((void**)&wo_hi, g_Wo_hi);
    cudaGetSymbolAddress((void**)&wo_lo, g_Wo_lo);

    int nq4 = 3 * C_DIM * C_DIM / 4;
    split_kernel<<<(nq4 + 255) / 256, 256>>>(Wqkv, wq_hi, wq_lo, nq4);
    int no4 = C_DIM * C_DIM / 4;
    split_kernel<<<(no4 + 255) / 256, 256>>>(Wo, wo_hi, wo_lo, no4);

    dim3 gT(S_LEN / 32, C_DIM / 32, BATCH);
    xpose_split<<<gT, dim3(32, 8)>>>(x);

    size_t gsmem = 2 * STBYTES;
    cudaFuncSetAttribute(qkv_tc, cudaFuncAttributeMaxDynamicSharedMemorySize, (int)gsmem);
    cudaFuncSetAttribute(out_tc, cudaFuncAttributeMaxDynamicSharedMemorySize, (int)gsmem);

    dim3 gA(S_LEN / 128, 3 * C_DIM / 128, BATCH);
    qkv_tc<<<gA, 256, gsmem>>>(bqkv);

    size_t asmem = QBYTES + 2 * KVBUF;   // 110592
    cudaFuncSetAttribute(attn_tc, cudaFuncAttributeMaxDynamicSharedMemorySize, (int)asmem);
    dim3 gB(9, NH, BATCH);
    attn_tc<<<gB, 256, asmem>>>();

    dim3 gC(S_LEN / 128, C_DIM / 128, BATCH);
    out_tc<<<gC, 256, gsmem>>>(bo, out);
}

// round 7
// speedup vs baseline: 3.4937x; 1.0003x over previous
#include <cuda_runtime.h>
#include <cuda_bf16.h>
#include <cstdint>

#define S_LEN 2304
#define C_DIM 1024
#define NH    16
#define HD    64
#define BATCH 2

// ---------------- scratch ---------------------------------------------------
__device__ __nv_bfloat16 g_Wq_hi[(size_t)3 * C_DIM * C_DIM];
__device__ __nv_bfloat16 g_Wq_lo[(size_t)3 * C_DIM * C_DIM];
__device__ __nv_bfloat16 g_Wo_hi[(size_t)C_DIM * C_DIM];
__device__ __nv_bfloat16 g_Wo_lo[(size_t)C_DIM * C_DIM];
__device__ __nv_bfloat16 g_xT_hi[(size_t)BATCH * S_LEN * C_DIM];
__device__ __nv_bfloat16 g_xT_lo[(size_t)BATCH * S_LEN * C_DIM];
__device__ __nv_bfloat16 g_z_hi[(size_t)BATCH * S_LEN * C_DIM];
__device__ __nv_bfloat16 g_z_lo[(size_t)BATCH * S_LEN * C_DIM];
// q (pre-scaled 1/8), k, v as bf16 hi/lo, layout [b][head][s][hd]
__device__ __nv_bfloat16 g_q_hi[(size_t)BATCH * NH * S_LEN * HD];
__device__ __nv_bfloat16 g_q_lo[(size_t)BATCH * NH * S_LEN * HD];
__device__ __nv_bfloat16 g_k_hi[(size_t)BATCH * NH * S_LEN * HD];
__device__ __nv_bfloat16 g_k_lo[(size_t)BATCH * NH * S_LEN * HD];
__device__ __nv_bfloat16 g_v_hi[(size_t)BATCH * NH * S_LEN * HD];
__device__ __nv_bfloat16 g_v_lo[(size_t)BATCH * NH * S_LEN * HD];

// ---------------- helpers ----------------------------------------------------
__device__ __forceinline__ uint32_t smem_u32(const void* p) {
    uint32_t a;
    asm("{ .reg .u64 t; cvta.to.shared.u64 t, %1; cvt.u32.u64 %0, t; }" : "=r"(a) : "l"(p));
    return a;
}
__device__ __forceinline__ void ldsm4(uint32_t* r, uint32_t addr) {
    asm volatile("ldmatrix.sync.aligned.m8n8.x4.shared.b16 {%0,%1,%2,%3}, [%4];"
                 : "=r"(r[0]), "=r"(r[1]), "=r"(r[2]), "=r"(r[3]) : "r"(addr));
}
__device__ __forceinline__ void ldsm4t(uint32_t* r, uint32_t addr) {
    asm volatile("ldmatrix.sync.aligned.m8n8.x4.trans.shared.b16 {%0,%1,%2,%3}, [%4];"
                 : "=r"(r[0]), "=r"(r[1]), "=r"(r[2]), "=r"(r[3]) : "r"(addr));
}
__device__ __forceinline__ void mma_bf16(float* c, const uint32_t* a,
                                         uint32_t b0, uint32_t b1) {
    asm volatile(
        "mma.sync.aligned.m16n8k16.row.col.f32.bf16.bf16.f32 "
        "{%0,%1,%2,%3}, {%4,%5,%6,%7}, {%8,%9}, {%0,%1,%2,%3};"
        : "+f"(c[0]), "+f"(c[1]), "+f"(c[2]), "+f"(c[3])
        : "r"(a[0]), "r"(a[1]), "r"(a[2]), "r"(a[3]), "r"(b0), "r"(b1));
}
#define CP16(dst, src) asm volatile("cp.async.cg.shared.global [%0], [%1], 16;" :: "r"(dst), "l"(src))
#define CP_COMMIT()    asm volatile("cp.async.commit_group;" ::: "memory")
#define CP_WAIT0()     asm volatile("cp.async.wait_group 0;" ::: "memory")
#define CP_WAIT1()     asm volatile("cp.async.wait_group 1;" ::: "memory")

__device__ __forceinline__ uint32_t pack_hi(float a, float b, uint32_t& lo) {
    __nv_bfloat162 h = __float22bfloat162_rn(make_float2(a, b));
    float2 hf = __bfloat1622float2(h);
    __nv_bfloat162 l = __float22bfloat162_rn(make_float2(a - hf.x, b - hf.y));
    lo = *reinterpret_cast<uint32_t*>(&l);
    return *reinterpret_cast<uint32_t*>(&h);
}

// ---------------- prep kernels ----------------------------------------------
__global__ void split_kernel(const float* __restrict__ src,
                             __nv_bfloat16* __restrict__ hi,
                             __nv_bfloat16* __restrict__ lo, int n4) {
    int i = blockIdx.x * 256 + threadIdx.x;
    if (i >= n4) return;
    float4 v = reinterpret_cast<const float4*>(src)[i];
    __nv_bfloat16 h0 = __float2bfloat16(v.x), h1 = __float2bfloat16(v.y);
    __nv_bfloat16 h2 = __float2bfloat16(v.z), h3 = __float2bfloat16(v.w);
    __nv_bfloat162 hh0{h0, h1}, hh1{h2, h3};
    __nv_bfloat162 ll0{__float2bfloat16(v.x - __bfloat162float(h0)),
                       __float2bfloat16(v.y - __bfloat162float(h1))};
    __nv_bfloat162 ll1{__float2bfloat16(v.z - __bfloat162float(h2)),
                       __float2bfloat16(v.w - __bfloat162float(h3))};
    *reinterpret_cast<__nv_bfloat162*>(hi + i * 4)     = hh0;
    *reinterpret_cast<__nv_bfloat162*>(hi + i * 4 + 2) = hh1;
    *reinterpret_cast<__nv_bfloat162*>(lo + i * 4)     = ll0;
    *reinterpret_cast<__nv_bfloat162*>(lo + i * 4 + 2) = ll1;
}

__global__ void xpose_split(const float* __restrict__ x) {
    __shared__ float tile[32][33];
    int b = blockIdx.z, t0 = blockIdx.x * 32, c0 = blockIdx.y * 32;
    int tx = threadIdx.x, ty = threadIdx.y;
    for (int i = ty; i < 32; i += 8)
        tile[i][tx] = x[((size_t)b * C_DIM + c0 + i) * S_LEN + t0 + tx];
    __syncthreads();
    for (int i = ty; i < 32; i += 8) {
        float v = tile[tx][i];
        size_t oi = ((size_t)b * S_LEN + t0 + i) * C_DIM + c0 + tx;
        __nv_bfloat16 h = __float2bfloat16(v);
        g_xT_hi[oi] = h;
        g_xT_lo[oi] = __float2bfloat16(v - __bfloat162float(h));
    }
}

// ---------------- mma.sync GEMM core (cp.async fills) --------------------------
#define GPITCH 40
#define TBYTES (128 * GPITCH * 2)
#define STBYTES (4 * TBYTES)

struct Frag { float acc[2][8][4]; };

__device__ __forceinline__ void fill_async(
    uint32_t stage_s, int tid, int k0,
    const __nv_bfloat16* Ah, const __nv_bfloat16* Al,
    const __nv_bfloat16* Bh, const __nv_bfloat16* Bl) {
    int row = tid >> 1, half = tid & 1;
    size_t go = (size_t)row * C_DIM + k0 + half * 16;
    uint32_t so = row * (GPITCH * 2) + half * 32;
    const __nv_bfloat16* srcs[4] = {Ah, Al, Bh, Bl};
#pragma unroll
    for (int t4 = 0; t4 < 4; t4++) {
        const char* s = (const char*)(srcs[t4] + go);
        uint32_t d = stage_s + t4 * TBYTES + so;
        CP16(d, s);
        CP16(d + 16, s + 16);
    }
    CP_COMMIT();
}

__device__ __forceinline__ void compute_stage(
    uint32_t st, int lane, int wm, int wn, Frag& f) {
    uint32_t Ah_s = st, Al_s = st + TBYTES, Bh_s = st + 2 * TBYTES, Bl_s = st + 3 * TBYTES;
    int bgrp = lane >> 3, br = lane & 7;
    int brow = wn * 64 + (bgrp >> 1) * 8 + br;
    int bcolh = (bgrp & 1) * 8;
    int ar = lane & 15, acolh = (lane >> 4) * 8;
#pragma unroll
    for (int ks = 0; ks < 2; ks++) {
        uint32_t ah[2][4], al[2][4], bb[4][4];
#pragma unroll
        for (int mi = 0; mi < 2; mi++) {
            uint32_t off = ((wm * 32 + mi * 16 + ar) * GPITCH + ks * 16 + acolh) * 2;
            ldsm4(ah[mi], Ah_s + off);
            ldsm4(al[mi], Al_s + off);
        }
#pragma unroll
        for (int nj = 0; nj < 4; nj++) {
            uint32_t off = ((brow + nj * 16) * GPITCH + ks * 16 + bcolh) * 2;
            ldsm4(bb[nj], Bh_s + off);
        }
        // pass 1: Ah * Bh  (32 independent MMAs)
#pragma unroll
        for (int mi = 0; mi < 2; mi++)
#pragma unroll
            for (int nj = 0; nj < 4; nj++) {
                mma_bf16(f.acc[mi][nj * 2],     ah[mi], bb[nj][0], bb[nj][1]);
                mma_bf16(f.acc[mi][nj * 2 + 1], ah[mi], bb[nj][2], bb[nj][3]);
            }
        // pass 2: Al * Bh  (RAW distance 32)
#pragma unroll
        for (int mi = 0; mi < 2; mi++)
#pragma unroll
            for (int nj = 0; nj < 4; nj++) {
                mma_bf16(f.acc[mi][nj * 2],     al[mi], bb[nj][0], bb[nj][1]);
                mma_bf16(f.acc[mi][nj * 2 + 1], al[mi], bb[nj][2], bb[nj][3]);
            }
        // pass 3: Ah * Bl
#pragma unroll
        for (int nj = 0; nj < 4; nj++) {
            uint32_t off = ((brow + nj * 16) * GPITCH + ks * 16 + bcolh) * 2;
            ldsm4(bb[nj], Bl_s + off);
        }
#pragma unroll
        for (int mi = 0; mi < 2; mi++)
#pragma unroll
            for (int nj = 0; nj < 4; nj++) {
                mma_bf16(f.acc[mi][nj * 2],     ah[mi], bb[nj][0], bb[nj][1]);
                mma_bf16(f.acc[mi][nj * 2 + 1], ah[mi], bb[nj][2], bb[nj][3]);
            }
    }
}

__device__ __forceinline__ void gemm_body(
    uint32_t smb, int tid, Frag& f,
    const __nv_bfloat16* Ah, const __nv_bfloat16* Al,
    const __nv_bfloat16* Bh, const __nv_bfloat16* Bl) {
    int lane = tid & 31, wid = tid >> 5;
    int wm = wid & 3, wn = wid >> 2;
    const int NC = C_DIM / 32;
    fill_async(smb, tid, 0, Ah, Al, Bh, Bl);
    for (int ch = 0; ch < NC; ch++) {
        if (ch + 1 < NC) {
            fill_async(smb + ((ch + 1) & 1) * STBYTES, tid, (ch + 1) * 32, Ah, Al, Bh, Bl);
            CP_WAIT1();
        } else {
            CP_WAIT0();
        }
        __syncthreads();
        compute_stage(smb + (ch & 1) * STBYTES, lane, wm, wn, f);
        __syncthreads();
    }
}

// ---------------- QKV projection (mma.sync) -----------------------------------
__global__ __launch_bounds__(256, 2)
void qkv_tc(const float* __restrict__ bias) {
    extern __shared__ char sm[];
    uint32_t smb = smem_u32(sm);
    int tid = threadIdx.x;
    int b = blockIdx.z, m0 = blockIdx.y * 128, n0 = blockIdx.x * 128;

    Frag f;
#pragma unroll
    for (int mi = 0; mi < 2; mi++)
#pragma unroll
        for (int ni = 0; ni < 8; ni++)
#pragma unroll
            for (int r = 0; r < 4; r++) f.acc[mi][ni][r] = 0.0f;

    gemm_body(smb, tid, f,
              g_Wq_hi + (size_t)m0 * C_DIM, g_Wq_lo + (size_t)m0 * C_DIM,
              g_xT_hi + ((size_t)b * S_LEN + n0) * C_DIM,
              g_xT_lo + ((size_t)b * S_LEN + n0) * C_DIM);

    int lane = tid & 31, wid = tid >> 5;
    int wm = wid & 3, wn = wid >> 2;
    int which = m0 >> 10;
    __nv_bfloat16* hib = (which == 0) ? g_q_hi : (which == 1) ? g_k_hi : g_v_hi;
    __nv_bfloat16* lob = (which == 0) ? g_q_lo : (which == 1) ? g_k_lo : g_v_lo;
    float scale = (which == 0) ? 0.125f : 1.0f;
#pragma unroll
    for (int mi = 0; mi < 2; mi++) {
#pragma unroll
        for (int rg = 0; rg < 2; rg++) {
            int m = m0 + wm * 32 + mi * 16 + (lane >> 2) + rg * 8;
            int head = (m >> 6) & 15, d = m & 63;
            float bv = bias[m];
            __nv_bfloat16* dh = hib + ((size_t)(b * NH + head)) * S_LEN * HD + d;
            __nv_bfloat16* dl = lob + ((size_t)(b * NH + head)) * S_LEN * HD + d;
#pragma unroll
            for (int ni = 0; ni < 8; ni++) {
                int t = n0 + wn * 64 + ni * 8 + ((lane & 3) << 1);
                float v0 = (f.acc[mi][ni][rg * 2 + 0] + bv) * scale;
                float v1 = (f.acc[mi][ni][rg * 2 + 1] + bv) * scale;
                __nv_bfloat16 h0 = __float2bfloat16(v0), h1 = __float2bfloat16(v1);
                dh[(size_t)t * HD]       = h0;
                dh[(size_t)(t + 1) * HD] = h1;
                dl[(size_t)t * HD]       = __float2bfloat16(v0 - __bfloat162float(h0));
                dl[(size_t)(t + 1) * HD] = __float2bfloat16(v1 - __bfloat162float(h1));
            }
        }
    }
}

// ---------------- Output projection (mma.sync) --------------------------------
__global__ __launch_bounds__(256, 2)
void out_tc(const float* __restrict__ bo, float* __restrict__ out) {
    extern __shared__ char sm[];
    uint32_t smb = smem_u32(sm);
    int tid = threadIdx.x;
    int b = blockIdx.z, m0 = blockIdx.y * 128, n0 = blockIdx.x * 128;

    Frag f;
#pragma unroll
    for (int mi = 0; mi < 2; mi++)
#pragma unroll
        for (int ni = 0; ni < 8; ni++)
#pragma unroll
            for (int r = 0; r < 4; r++) f.acc[mi][ni][r] = 0.0f;

    gemm_body(smb, tid, f,
              g_Wo_hi + (size_t)m0 * C_DIM, g_Wo_lo + (size_t)m0 * C_DIM,
              g_z_hi + ((size_t)b * S_LEN + n0) * C_DIM,
              g_z_lo + ((size_t)b * S_LEN + n0) * C_DIM);

    int lane = tid & 31, wid = tid >> 5;
    int wm = wid & 3, wn = wid >> 2;
#pragma unroll
    for (int mi = 0; mi < 2; mi++) {
#pragma unroll
        for (int rg = 0; rg < 2; rg++) {
            int m = m0 + wm * 32 + mi * 16 + (lane >> 2) + rg * 8;
            float bv = bo[m];
            float* dst = out + ((size_t)b * C_DIM + m) * S_LEN;
#pragma unroll
            for (int ni = 0; ni < 8; ni++) {
                int t = n0 + wn * 64 + ni * 8 + ((lane & 3) << 1);
                float2 v = {f.acc[mi][ni][rg * 2 + 0] + bv,
                            f.acc[mi][ni][rg * 2 + 1] + bv};
                *reinterpret_cast<float2*>(dst + t) = v;
            }
        }
    }
}

// ---------------- Flash attention: FA2-style register layout -------------------
#define AP 72
#define QBYTES   36864
#define KVTILE   9216
#define KVBUF    36864

__device__ __forceinline__ void fill_kv(
    uint32_t dst, int tid, int s0,
    const __nv_bfloat16* kh, const __nv_bfloat16* kl,
    const __nv_bfloat16* vh, const __nv_bfloat16* vl) {
#pragma unroll
    for (int i = tid; i < 512; i += 256) {
        int r = i >> 3, c = (i & 7) * 16;
        uint32_t so = r * 144 + c;
        size_t go = (size_t)(s0 + r) * HD;
        CP16(dst + so,              (const char*)(kh + go) + c);
        CP16(dst + KVTILE + so,     (const char*)(kl + go) + c);
        CP16(dst + 2 * KVTILE + so, (const char*)(vh + go) + c);
        CP16(dst + 3 * KVTILE + so, (const char*)(vl + go) + c);
    }
    CP_COMMIT();
}

__global__ __launch_bounds__(256, 2)
void attn_tc() {
    extern __shared__ char sm[];
    uint32_t smb = smem_u32(sm);
    uint32_t Q_s  = smb;
    uint32_t KV_s = smb + QBYTES;

    int head = blockIdx.y, b = blockIdx.z;
    int tid = threadIdx.x, lane = tid & 31, wid = tid >> 5;
    int r0w = wid * 16;
    int g = lane >> 2, tc = lane & 3;

    size_t base = ((size_t)(b * NH + head)) * S_LEN * HD;
    const __nv_bfloat16* qhp = g_q_hi + base;
    const __nv_bfloat16* qlp = g_q_lo + base;
    const __nv_bfloat16* khp = g_k_hi + base;
    const __nv_bfloat16* klp = g_k_lo + base;
    const __nv_bfloat16* vhp = g_v_hi + base;
    const __nv_bfloat16* vlp = g_v_lo + base;

    int ar = lane & 15, ach = (lane >> 4) * 8;
    int bg = lane >> 3, br = lane & 7;
    int krow_off = ((bg >> 1) * 8 + br) * AP + (bg & 1) * 8;
    int vrow = ((lane >> 3) & 1) * 8 + (lane & 7);
    int vcol = (lane >> 4) * 8;

    for (int rep = 0; rep < 2; rep++) {
        int qt = rep == 0 ? (17 - (int)blockIdx.x) : (int)blockIdx.x;
        int q0 = qt * 128;

#pragma unroll
        for (int i = tid; i < 1024; i += 256) {
            int r = i >> 3, c = (i & 7) * 16;
            uint32_t so = r * 144 + c;
            size_t go = (size_t)(q0 + r) * HD;
            CP16(Q_s + so,              (const char*)(qhp + go) + c);
            CP16(Q_s + QBYTES / 2 + so, (const char*)(qlp + go) + c);
        }
        CP_COMMIT();
        CP_WAIT0();
        __syncthreads();

        float o[8][4] = {};
        float mA = -1e30f, mB = -1e30f, lA = 0.0f, lB = 0.0f;

        int nkt = 2 * qt + 2;
        fill_kv(KV_s, tid, 0, khp, klp, vhp, vlp);
        for (int kt = 0; kt < nkt; kt++) {
            int c0 = kt * 64;
            if (kt + 1 < nkt) {
                fill_kv(KV_s + ((kt + 1) & 1) * KVBUF, tid, (kt + 1) * 64, khp, klp, vhp, vlp);
                CP_WAIT1();
            } else {
                CP_WAIT0();
            }
            __syncthreads();
            uint32_t Kh_s = KV_s + (kt & 1) * KVBUF;
            uint32_t Kl_s = Kh_s + KVTILE;
            uint32_t Vh_s = Kh_s + 2 * KVTILE;
            uint32_t Vl_s = Kh_s + 3 * KVTILE;

            // ---- S = Q K^T (3-pass hi/lo, ILP-ordered) ----
            float s[8][4] = {};
#pragma unroll
            for (int kc = 0; kc < 4; kc++) {
                uint32_t qoff = ((r0w + ar) * AP + kc * 16 + ach) * 2;
                uint32_t qh[4], ql[4], kk[4][4];
                ldsm4(qh, Q_s + qoff);
                ldsm4(ql, Q_s + QBYTES / 2 + qoff);
#pragma unroll
                for (int np = 0; np < 4; np++)
                    ldsm4(kk[np], Kh_s + (np * 16 * AP + kc * 16 + krow_off) * 2);
#pragma unroll
                for (int np = 0; np < 4; np++) {
                    mma_bf16(s[np * 2],     qh, kk[np][0], kk[np][1]);
                    mma_bf16(s[np * 2 + 1], qh, kk[np][2], kk[np][3]);
                }
#pragma unroll
                for (int np = 0; np < 4; np++) {
                    mma_bf16(s[np * 2],     ql, kk[np][0], kk[np][1]);
                    mma_bf16(s[np * 2 + 1], ql, kk[np][2], kk[np][3]);
                }
#pragma unroll
                for (int np = 0; np < 4; np++)
                    ldsm4(kk[np], Kl_s + (np * 16 * AP + kc * 16 + krow_off) * 2);
#pragma unroll
                for (int np = 0; np < 4; np++) {
                    mma_bf16(s[np * 2],     qh, kk[np][0], kk[np][1]);
                    mma_bf16(s[np * 2 + 1], qh, kk[np][2], kk[np][3]);
                }
            }

            // ---- mask (register domain) ----
            if (c0 + 63 > q0 + r0w) {
                int rowA = q0 + r0w + g, rowB = rowA + 8;
#pragma unroll
                for (int nf = 0; nf < 8; nf++) {
                    int col = c0 + nf * 8 + tc * 2;
                    if (col     > rowA) s[nf][0] -= 10000.0f;
                    if (col + 1 > rowA) s[nf][1] -= 10000.0f;
                    if (col     > rowB) s[nf][2] -= 10000.0f;
                    if (col + 1 > rowB) s[nf][3] -= 10000.0f;
                }
            }

            // ---- register softmax ----
            float pmA = -1e30f, pmB = -1e30f;
#pragma unroll
            for (int nf = 0; nf < 8; nf++) {
                pmA = fmaxf(pmA, fmaxf(s[nf][0], s[nf][1]));
                pmB = fmaxf(pmB, fmaxf(s[nf][2], s[nf][3]));
            }
            pmA = fmaxf(pmA, __shfl_xor_sync(0xffffffffu, pmA, 1));
            pmA = fmaxf(pmA, __shfl_xor_sync(0xffffffffu, pmA, 2));
            pmB = fmaxf(pmB, __shfl_xor_sync(0xffffffffu, pmB, 1));
            pmB = fmaxf(pmB, __shfl_xor_sync(0xffffffffu, pmB, 2));
            float mnA = fmaxf(mA, pmA), mnB = fmaxf(mB, pmB);
            float alA = __expf(mA - mnA), alB = __expf(mB - mnB);
            float lsA = 0.0f, lsB = 0.0f;
#pragma unroll
            for (int nf = 0; nf < 8; nf++) {
                s[nf][0] = __expf(s[nf][0] - mnA);
                s[nf][1] = __expf(s[nf][1] - mnA);
                s[nf][2] = __expf(s[nf][2] - mnB);
                s[nf][3] = __expf(s[nf][3] - mnB);
                lsA += s[nf][0] + s[nf][1];
                lsB += s[nf][2] + s[nf][3];
            }
            lsA += __shfl_xor_sync(0xffffffffu, lsA, 1);
            lsA += __shfl_xor_sync(0xffffffffu, lsA, 2);
            lsB += __shfl_xor_sync(0xffffffffu, lsB, 1);
            lsB += __shfl_xor_sync(0xffffffffu, lsB, 2);
            lA = lA * alA + lsA;
            lB = lB * alB + lsB;
            mA = mnA; mB = mnB;
#pragma unroll
            for (int nf = 0; nf < 8; nf++) {
                o[nf][0] *= alA; o[nf][1] *= alA;
                o[nf][2] *= alB; o[nf][3] *= alB;
            }

            // ---- O += P V (3-pass hi/lo, ILP-ordered) ----
#pragma unroll
            for (int kc = 0; kc < 4; kc++) {
                uint32_t ph[4], pl[4], vv[4][4];
                ph[0] = pack_hi(s[2 * kc][0],     s[2 * kc][1],     pl[0]);
                ph[1] = pack_hi(s[2 * kc][2],     s[2 * kc][3],     pl[1]);
                ph[2] = pack_hi(s[2 * kc + 1][0], s[2 * kc + 1][1], pl[2]);
                ph[3] = pack_hi(s[2 * kc + 1][2], s[2 * kc + 1][3], pl[3]);
#pragma unroll
                for (int np = 0; np < 4; np++)
                    ldsm4t(vv[np], Vh_s + ((kc * 16 + vrow) * AP + np * 16 + vcol) * 2);
#pragma unroll
                for (int np = 0; np < 4; np++) {
                    mma_bf16(o[np * 2],     ph, vv[np][0], vv[np][1]);
                    mma_bf16(o[np * 2 + 1], ph, vv[np][2], vv[np][3]);
                }
#pragma unroll
                for (int np = 0; np < 4; np++) {
                    mma_bf16(o[np * 2],     pl, vv[np][0], vv[np][1]);
                    mma_bf16(o[np * 2 + 1], pl, vv[np][2], vv[np][3]);
                }
#pragma unroll
                for (int np = 0; np < 4; np++)
                    ldsm4t(vv[np], Vl_s + ((kc * 16 + vrow) * AP + np * 16 + vcol) * 2);
#pragma unroll
                for (int np = 0; np < 4; np++) {
                    mma_bf16(o[np * 2],     ph, vv[np][0], vv[np][1]);
                    mma_bf16(o[np * 2 + 1], ph, vv[np][2], vv[np][3]);
                }
            }
            __syncthreads();
        }

        // ---- epilogue ----
        float liA = 1.0f / lA, liB = 1.0f / lB;
        int tA = q0 + r0w + g, tB = tA + 8;
#pragma unroll
        for (int nf = 0; nf < 8; nf++) {
            int d = nf * 8 + tc * 2;
            size_t ziA = ((size_t)b * S_LEN + tA) * C_DIM + head * HD + d;
            size_t ziB = ((size_t)b * S_LEN + tB) * C_DIM + head * HD + d;
            float f0 = o[nf][0] * liA, f1 = o[nf][1] * liA;
            float f2 = o[nf][2] * liB, f3 = o[nf][3] * liB;
            uint32_t loA, loB;
            uint32_t hiA = pack_hi(f0, f1, loA);
            uint32_t hiB = pack_hi(f2, f3, loB);
            *reinterpret_cast<uint32_t*>(g_z_hi + ziA) = hiA;
            *reinterpret_cast<uint32_t*>(g_z_lo + ziA) = loA;
            *reinterpret_cast<uint32_t*>(g_z_hi + ziB) = hiB;
            *reinterpret_cast<uint32_t*>(g_z_lo + ziB) = loB;
        }
        __syncthreads();
    }
}

// ---------------------------------------------------------------------------

extern "C" void kernel_launch(void* const* d_in, const int* in_sizes, int n_in,
                              void* d_out, int out_size) {
    const float* x    = (const float*)d_in[0];
    const float* Wqkv = (const float*)d_in[1];
    const float* bqkv = (const float*)d_in[2];
    const float* Wo   = (const float*)d_in[3];
    const float* bo   = (const float*)d_in[4];
    float* out = (float*)d_out;

    __nv_bfloat16 *wq_hi, *wq_lo, *wo_hi, *wo_lo;
    cudaGetSymbolAddress((void**)&wq_hi, g_Wq_hi);
    cudaGetSymbolAddress((void**)&wq_lo, g_Wq_lo);
    cudaGetSymbolAddress((void**)&wo_hi, g_Wo_hi);
    cudaGetSymbolAddress((void**)&wo_lo, g_Wo_lo);

    int nq4 = 3 * C_DIM * C_DIM / 4;
    split_kernel<<<(nq4 + 255) / 256, 256>>>(Wqkv, wq_hi, wq_lo, nq4);
    int no4 = C_DIM * C_DIM / 4;
    split_kernel<<<(no4 + 255) / 256, 256>>>(Wo, wo_hi, wo_lo, no4);

    dim3 gT(S_LEN / 32, C_DIM / 32, BATCH);
    xpose_split<<<gT, dim3(32, 8)>>>(x);

    size_t gsmem = 2 * STBYTES;
    cudaFuncSetAttribute(qkv_tc, cudaFuncAttributeMaxDynamicSharedMemorySize, (int)gsmem);
    cudaFuncSetAttribute(out_tc, cudaFuncAttributeMaxDynamicSharedMemorySize, (int)gsmem);

    dim3 gA(S_LEN / 128, 3 * C_DIM / 128, BATCH);
    qkv_tc<<<gA, 256, gsmem>>>(bqkv);

    size_t asmem = QBYTES + 2 * KVBUF;
    cudaFuncSetAttribute(attn_tc, cudaFuncAttributeMaxDynamicSharedMemorySize, (int)asmem);
    dim3 gB(9, NH, BATCH);
    attn_tc<<<gB, 256, asmem>>>();

    dim3 gC(S_LEN / 128, C_DIM / 128, BATCH);
    out_tc<<<gC, 256, gsmem>>>(bo, out);
}

// round 8
// speedup vs baseline: 4.9580x; 1.4191x over previous
#include <cuda_runtime.h>
#include <cuda_fp16.h>
#include <cstdint>

#define S_LEN 2304
#define C_DIM 1024
#define NH    16
#define HD    64
#define BATCH 2

// ---------------- scratch ---------------------------------------------------
// A-side operands: hi/lo fp16 split. B-side operands: single fp16 (round nearest).
__device__ __half g_Wq_hi[(size_t)3 * C_DIM * C_DIM];
__device__ __half g_Wq_lo[(size_t)3 * C_DIM * C_DIM];
__device__ __half g_Wo_hi[(size_t)C_DIM * C_DIM];
__device__ __half g_Wo_lo[(size_t)C_DIM * C_DIM];
__device__ __half g_x[(size_t)BATCH * S_LEN * C_DIM];     // x^T, single fp16
__device__ __half g_z[(size_t)BATCH * S_LEN * C_DIM];     // z, single fp16
__device__ __half g_q_hi[(size_t)BATCH * NH * S_LEN * HD]; // q pre-scaled 1/8
__device__ __half g_q_lo[(size_t)BATCH * NH * S_LEN * HD];
__device__ __half g_k[(size_t)BATCH * NH * S_LEN * HD];    // single fp16
__device__ __half g_v[(size_t)BATCH * NH * S_LEN * HD];    // single fp16

// ---------------- helpers ----------------------------------------------------
__device__ __forceinline__ uint32_t smem_u32(const void* p) {
    uint32_t a;
    asm("{ .reg .u64 t; cvta.to.shared.u64 t, %1; cvt.u32.u64 %0, t; }" : "=r"(a) : "l"(p));
    return a;
}
__device__ __forceinline__ void ldsm4(uint32_t* r, uint32_t addr) {
    asm volatile("ldmatrix.sync.aligned.m8n8.x4.shared.b16 {%0,%1,%2,%3}, [%4];"
                 : "=r"(r[0]), "=r"(r[1]), "=r"(r[2]), "=r"(r[3]) : "r"(addr));
}
__device__ __forceinline__ void ldsm4t(uint32_t* r, uint32_t addr) {
    asm volatile("ldmatrix.sync.aligned.m8n8.x4.trans.shared.b16 {%0,%1,%2,%3}, [%4];"
                 : "=r"(r[0]), "=r"(r[1]), "=r"(r[2]), "=r"(r[3]) : "r"(addr));
}
__device__ __forceinline__ void mma_f16(float* c, const uint32_t* a,
                                        uint32_t b0, uint32_t b1) {
    asm volatile(
        "mma.sync.aligned.m16n8k16.row.col.f32.f16.f16.f32 "
        "{%0,%1,%2,%3}, {%4,%5,%6,%7}, {%8,%9}, {%0,%1,%2,%3};"
        : "+f"(c[0]), "+f"(c[1]), "+f"(c[2]), "+f"(c[3])
        : "r"(a[0]), "r"(a[1]), "r"(a[2]), "r"(a[3]), "r"(b0), "r"(b1));
}
#define CP16(dst, src) asm volatile("cp.async.cg.shared.global [%0], [%1], 16;" :: "r"(dst), "l"(src))
#define CP_COMMIT()    asm volatile("cp.async.commit_group;" ::: "memory")
#define CP_WAIT0()     asm volatile("cp.async.wait_group 0;" ::: "memory")
#define CP_WAIT1()     asm volatile("cp.async.wait_group 1;" ::: "memory")

__device__ __forceinline__ uint32_t pack2h(float a, float b) {
    __half2 h = __floats2half2_rn(a, b);
    return *reinterpret_cast<uint32_t*>(&h);
}
__device__ __forceinline__ uint32_t pack_hilo(float a, float b, uint32_t& lo) {
    __half2 h = __floats2half2_rn(a, b);
    float2 hf = __half22float2(h);
    __half2 l = __floats2half2_rn(a - hf.x, b - hf.y);
    lo = *reinterpret_cast<uint32_t*>(&l);
    return *reinterpret_cast<uint32_t*>(&h);
}

// ---------------- prep kernels ----------------------------------------------
__global__ void split_kernel(const float* __restrict__ src,
                             __half* __restrict__ hi,
                             __half* __restrict__ lo, int n4) {
    int i = blockIdx.x * 256 + threadIdx.x;
    if (i >= n4) return;
    float4 v = reinterpret_cast<const float4*>(src)[i];
    uint32_t l0, l1;
    uint32_t h0 = pack_hilo(v.x, v.y, l0);
    uint32_t h1 = pack_hilo(v.z, v.w, l1);
    *reinterpret_cast<uint32_t*>(hi + i * 4)     = h0;
    *reinterpret_cast<uint32_t*>(hi + i * 4 + 2) = h1;
    *reinterpret_cast<uint32_t*>(lo + i * 4)     = l0;
    *reinterpret_cast<uint32_t*>(lo + i * 4 + 2) = l1;
}

__global__ void xpose_half(const float* __restrict__ x) {
    __shared__ float tile[32][33];
    int b = blockIdx.z, t0 = blockIdx.x * 32, c0 = blockIdx.y * 32;
    int tx = threadIdx.x, ty = threadIdx.y;
    for (int i = ty; i < 32; i += 8)
        tile[i][tx] = x[((size_t)b * C_DIM + c0 + i) * S_LEN + t0 + tx];
    __syncthreads();
    for (int i = ty; i < 32; i += 8) {
        size_t oi = ((size_t)b * S_LEN + t0 + i) * C_DIM + c0 + tx;
        g_x[oi] = __float2half_rn(tile[tx][i]);
    }
}

// ---------------- mma.sync GEMM core (fp16 2-pass) -----------------------------
#define GPITCH 40
#define TBYTES (128 * GPITCH * 2)      // 10240
#define STBYTES (3 * TBYTES)           // 30720: Ah, Al, B

struct Frag { float acc[2][8][4]; };

__device__ __forceinline__ void fill_async(
    uint32_t stage_s, int tid, int k0,
    const __half* Ah, const __half* Al, const __half* B) {
    int row = tid >> 1, half = tid & 1;
    size_t go = (size_t)row * C_DIM + k0 + half * 16;
    uint32_t so = row * (GPITCH * 2) + half * 32;
    const __half* srcs[3] = {Ah, Al, B};
#pragma unroll
    for (int t3 = 0; t3 < 3; t3++) {
        const char* s = (const char*)(srcs[t3] + go);
        uint32_t d = stage_s + t3 * TBYTES + so;
        CP16(d, s);
        CP16(d + 16, s + 16);
    }
    CP_COMMIT();
}

__device__ __forceinline__ void compute_stage(
    uint32_t st, int lane, int wm, int wn, Frag& f) {
    uint32_t Ah_s = st, Al_s = st + TBYTES, B_s = st + 2 * TBYTES;
    int bgrp = lane >> 3, br = lane & 7;
    int brow = wn * 64 + (bgrp >> 1) * 8 + br;
    int bcolh = (bgrp & 1) * 8;
    int ar = lane & 15, acolh = (lane >> 4) * 8;
#pragma unroll
    for (int ks = 0; ks < 2; ks++) {
        uint32_t ah[2][4], al[2][4], bb[4][4];
#pragma unroll
        for (int mi = 0; mi < 2; mi++) {
            uint32_t off = ((wm * 32 + mi * 16 + ar) * GPITCH + ks * 16 + acolh) * 2;
            ldsm4(ah[mi], Ah_s + off);
            ldsm4(al[mi], Al_s + off);
        }
#pragma unroll
        for (int nj = 0; nj < 4; nj++) {
            uint32_t off = ((brow + nj * 16) * GPITCH + ks * 16 + bcolh) * 2;
            ldsm4(bb[nj], B_s + off);
        }
#pragma unroll
        for (int mi = 0; mi < 2; mi++)
#pragma unroll
            for (int nj = 0; nj < 4; nj++) {
                mma_f16(f.acc[mi][nj * 2],     ah[mi], bb[nj][0], bb[nj][1]);
                mma_f16(f.acc[mi][nj * 2 + 1], ah[mi], bb[nj][2], bb[nj][3]);
            }
#pragma unroll
        for (int mi = 0; mi < 2; mi++)
#pragma unroll
            for (int nj = 0; nj < 4; nj++) {
                mma_f16(f.acc[mi][nj * 2],     al[mi], bb[nj][0], bb[nj][1]);
                mma_f16(f.acc[mi][nj * 2 + 1], al[mi], bb[nj][2], bb[nj][3]);
            }
    }
}

__device__ __forceinline__ void gemm_body(
    uint32_t smb, int tid, Frag& f,
    const __half* Ah, const __half* Al, const __half* B) {
    int lane = tid & 31, wid = tid >> 5;
    int wm = wid & 3, wn = wid >> 2;
    const int NC = C_DIM / 32;
    fill_async(smb, tid, 0, Ah, Al, B);
    for (int ch = 0; ch < NC; ch++) {
        if (ch + 1 < NC) {
            fill_async(smb + ((ch + 1) & 1) * STBYTES, tid, (ch + 1) * 32, Ah, Al, B);
            CP_WAIT1();
        } else {
            CP_WAIT0();
        }
        __syncthreads();
        compute_stage(smb + (ch & 1) * STBYTES, lane, wm, wn, f);
        __syncthreads();
    }
}

// ---------------- QKV projection -----------------------------------------------
__global__ __launch_bounds__(256, 2)
void qkv_tc(const float* __restrict__ bias) {
    extern __shared__ char sm[];
    uint32_t smb = smem_u32(sm);
    int tid = threadIdx.x;
    int b = blockIdx.z, m0 = blockIdx.y * 128, n0 = blockIdx.x * 128;

    Frag f;
#pragma unroll
    for (int mi = 0; mi < 2; mi++)
#pragma unroll
        for (int ni = 0; ni < 8; ni++)
#pragma unroll
            for (int r = 0; r < 4; r++) f.acc[mi][ni][r] = 0.0f;

    gemm_body(smb, tid, f,
              g_Wq_hi + (size_t)m0 * C_DIM, g_Wq_lo + (size_t)m0 * C_DIM,
              g_x + ((size_t)b * S_LEN + n0) * C_DIM);

    int lane = tid & 31, wid = tid >> 5;
    int wm = wid & 3, wn = wid >> 2;
    int which = m0 >> 10;
#pragma unroll
    for (int mi = 0; mi < 2; mi++) {
#pragma unroll
        for (int rg = 0; rg < 2; rg++) {
            int m = m0 + wm * 32 + mi * 16 + (lane >> 2) + rg * 8;
            int head = (m >> 6) & 15, d = m & 63;
            float bv = bias[m];
            size_t hb = ((size_t)(b * NH + head)) * S_LEN * HD + d;
            if (which == 0) {
#pragma unroll
                for (int ni = 0; ni < 8; ni++) {
                    int t = n0 + wn * 64 + ni * 8 + ((lane & 3) << 1);
                    float v0 = (f.acc[mi][ni][rg * 2 + 0] + bv) * 0.125f;
                    float v1 = (f.acc[mi][ni][rg * 2 + 1] + bv) * 0.125f;
                    __half h0 = __float2half_rn(v0), h1 = __float2half_rn(v1);
                    g_q_hi[hb + (size_t)t * HD]       = h0;
                    g_q_hi[hb + (size_t)(t + 1) * HD] = h1;
                    g_q_lo[hb + (size_t)t * HD]       = __float2half_rn(v0 - __half2float(h0));
                    g_q_lo[hb + (size_t)(t + 1) * HD] = __float2half_rn(v1 - __half2float(h1));
                }
            } else {
                __half* dst = (which == 1) ? g_k : g_v;
#pragma unroll
                for (int ni = 0; ni < 8; ni++) {
                    int t = n0 + wn * 64 + ni * 8 + ((lane & 3) << 1);
                    dst[hb + (size_t)t * HD]       = __float2half_rn(f.acc[mi][ni][rg * 2 + 0] + bv);
                    dst[hb + (size_t)(t + 1) * HD] = __float2half_rn(f.acc[mi][ni][rg * 2 + 1] + bv);
                }
            }
        }
    }
}

// ---------------- Output projection ---------------------------------------------
__global__ __launch_bounds__(256, 2)
void out_tc(const float* __restrict__ bo, float* __restrict__ out) {
    extern __shared__ char sm[];
    uint32_t smb = smem_u32(sm);
    int tid = threadIdx.x;
    int b = blockIdx.z, m0 = blockIdx.y * 128, n0 = blockIdx.x * 128;

    Frag f;
#pragma unroll
    for (int mi = 0; mi < 2; mi++)
#pragma unroll
        for (int ni = 0; ni < 8; ni++)
#pragma unroll
            for (int r = 0; r < 4; r++) f.acc[mi][ni][r] = 0.0f;

    gemm_body(smb, tid, f,
              g_Wo_hi + (size_t)m0 * C_DIM, g_Wo_lo + (size_t)m0 * C_DIM,
              g_z + ((size_t)b * S_LEN + n0) * C_DIM);

    int lane = tid & 31, wid = tid >> 5;
    int wm = wid & 3, wn = wid >> 2;
#pragma unroll
    for (int mi = 0; mi < 2; mi++) {
#pragma unroll
        for (int rg = 0; rg < 2; rg++) {
            int m = m0 + wm * 32 + mi * 16 + (lane >> 2) + rg * 8;
            float bv = bo[m];
            float* dst = out + ((size_t)b * C_DIM + m) * S_LEN;
#pragma unroll
            for (int ni = 0; ni < 8; ni++) {
                int t = n0 + wn * 64 + ni * 8 + ((lane & 3) << 1);
                float2 v = {f.acc[mi][ni][rg * 2 + 0] + bv,
                            f.acc[mi][ni][rg * 2 + 1] + bv};
                *reinterpret_cast<float2*>(dst + t) = v;
            }
        }
    }
}

// ---------------- Flash attention (fp16 2-pass) ---------------------------------
#define AP 72
#define QBYTES   36864              // Q hi + lo
#define KVTILE   9216               // one 64x64 fp16 tile @ pitch 144B
#define KVBUF    18432              // K + V

__device__ __forceinline__ void fill_kv(
    uint32_t dst, int tid, int s0,
    const __half* k, const __half* v) {
#pragma unroll
    for (int i = tid; i < 512; i += 256) {
        int r = i >> 3, c = (i & 7) * 16;
        uint32_t so = r * 144 + c;
        size_t go = (size_t)(s0 + r) * HD;
        CP16(dst + so,          (const char*)(k + go) + c);
        CP16(dst + KVTILE + so, (const char*)(v + go) + c);
    }
    CP_COMMIT();
}

__global__ __launch_bounds__(256, 2)
void attn_tc() {
    extern __shared__ char sm[];
    uint32_t smb = smem_u32(sm);
    uint32_t Q_s  = smb;
    uint32_t KV_s = smb + QBYTES;

    int head = blockIdx.y, b = blockIdx.z;
    int tid = threadIdx.x, lane = tid & 31, wid = tid >> 5;
    int r0w = wid * 16;
    int g = lane >> 2, tc = lane & 3;

    size_t base = ((size_t)(b * NH + head)) * S_LEN * HD;
    const __half* qhp = g_q_hi + base;
    const __half* qlp = g_q_lo + base;
    const __half* kp  = g_k + base;
    const __half* vp  = g_v + base;

    int ar = lane & 15, ach = (lane >> 4) * 8;
    int bg = lane >> 3, br = lane & 7;
    int krow_off = ((bg >> 1) * 8 + br) * AP + (bg & 1) * 8;
    int vrow = ((lane >> 3) & 1) * 8 + (lane & 7);
    int vcol = (lane >> 4) * 8;

    for (int rep = 0; rep < 2; rep++) {
        int qt = rep == 0 ? (17 - (int)blockIdx.x) : (int)blockIdx.x;
        int q0 = qt * 128;

#pragma unroll
        for (int i = tid; i < 1024; i += 256) {
            int r = i >> 3, c = (i & 7) * 16;
            uint32_t so = r * 144 + c;
            size_t go = (size_t)(q0 + r) * HD;
            CP16(Q_s + so,              (const char*)(qhp + go) + c);
            CP16(Q_s + QBYTES / 2 + so, (const char*)(qlp + go) + c);
        }
        CP_COMMIT();
        CP_WAIT0();
        __syncthreads();

        float o[8][4] = {};
        float mA = -1e30f, mB = -1e30f, lA = 0.0f, lB = 0.0f;

        int nkt = 2 * qt + 2;
        fill_kv(KV_s, tid, 0, kp, vp);
        for (int kt = 0; kt < nkt; kt++) {
            int c0 = kt * 64;
            if (kt + 1 < nkt) {
                fill_kv(KV_s + ((kt + 1) & 1) * KVBUF, tid, (kt + 1) * 64, kp, vp);
                CP_WAIT1();
            } else {
                CP_WAIT0();
            }
            __syncthreads();
            uint32_t K_s = KV_s + (kt & 1) * KVBUF;
            uint32_t V_s = K_s + KVTILE;

            // ---- S = Q K^T (2-pass: Qh, Ql) ----
            float s[8][4] = {};
#pragma unroll
            for (int kc = 0; kc < 4; kc++) {
                uint32_t qoff = ((r0w + ar) * AP + kc * 16 + ach) * 2;
                uint32_t qh[4], ql[4], kk[4][4];
                ldsm4(qh, Q_s + qoff);
                ldsm4(ql, Q_s + QBYTES / 2 + qoff);
#pragma unroll
                for (int np = 0; np < 4; np++)
                    ldsm4(kk[np], K_s + (np * 16 * AP + kc * 16 + krow_off) * 2);
#pragma unroll
                for (int np = 0; np < 4; np++) {
                    mma_f16(s[np * 2],     qh, kk[np][0], kk[np][1]);
                    mma_f16(s[np * 2 + 1], qh, kk[np][2], kk[np][3]);
                }
#pragma unroll
                for (int np = 0; np < 4; np++) {
                    mma_f16(s[np * 2],     ql, kk[np][0], kk[np][1]);
                    mma_f16(s[np * 2 + 1], ql, kk[np][2], kk[np][3]);
                }
            }

            // ---- mask (register domain) ----
            if (c0 + 63 > q0 + r0w) {
                int rowA = q0 + r0w + g, rowB = rowA + 8;
#pragma unroll
                for (int nf = 0; nf < 8; nf++) {
                    int col = c0 + nf * 8 + tc * 2;
                    if (col     > rowA) s[nf][0] -= 10000.0f;
                    if (col + 1 > rowA) s[nf][1] -= 10000.0f;
                    if (col     > rowB) s[nf][2] -= 10000.0f;
                    if (col + 1 > rowB) s[nf][3] -= 10000.0f;
                }
            }

            // ---- register softmax ----
            float pmA = -1e30f, pmB = -1e30f;
#pragma unroll
            for (int nf = 0; nf < 8; nf++) {
                pmA = fmaxf(pmA, fmaxf(s[nf][0], s[nf][1]));
                pmB = fmaxf(pmB, fmaxf(s[nf][2], s[nf][3]));
            }
            pmA = fmaxf(pmA, __shfl_xor_sync(0xffffffffu, pmA, 1));
            pmA = fmaxf(pmA, __shfl_xor_sync(0xffffffffu, pmA, 2));
            pmB = fmaxf(pmB, __shfl_xor_sync(0xffffffffu, pmB, 1));
            pmB = fmaxf(pmB, __shfl_xor_sync(0xffffffffu, pmB, 2));
            float mnA = fmaxf(mA, pmA), mnB = fmaxf(mB, pmB);
            float alA = __expf(mA - mnA), alB = __expf(mB - mnB);
            float lsA = 0.0f, lsB = 0.0f;
#pragma unroll
            for (int nf = 0; nf < 8; nf++) {
                s[nf][0] = __expf(s[nf][0] - mnA);
                s[nf][1] = __expf(s[nf][1] - mnA);
                s[nf][2] = __expf(s[nf][2] - mnB);
                s[nf][3] = __expf(s[nf][3] - mnB);
                lsA += s[nf][0] + s[nf][1];
                lsB += s[nf][2] + s[nf][3];
            }
            lsA += __shfl_xor_sync(0xffffffffu, lsA, 1);
            lsA += __shfl_xor_sync(0xffffffffu, lsA, 2);
            lsB += __shfl_xor_sync(0xffffffffu, lsB, 1);
            lsB += __shfl_xor_sync(0xffffffffu, lsB, 2);
            lA = lA * alA + lsA;
            lB = lB * alB + lsB;
            mA = mnA; mB = mnB;
#pragma unroll
            for (int nf = 0; nf < 8; nf++) {
                o[nf][0] *= alA; o[nf][1] *= alA;
                o[nf][2] *= alB; o[nf][3] *= alB;
            }

            // ---- O += P V (P hi/lo 2-pass, V single) ----
#pragma unroll
            for (int kc = 0; kc < 4; kc++) {
                uint32_t ph[4], pl[4], vv[4][4];
                ph[0] = pack_hilo(s[2 * kc][0],     s[2 * kc][1],     pl[0]);
                ph[1] = pack_hilo(s[2 * kc][2],     s[2 * kc][3],     pl[1]);
                ph[2] = pack_hilo(s[2 * kc + 1][0], s[2 * kc + 1][1], pl[2]);
                ph[3] = pack_hilo(s[2 * kc + 1][2], s[2 * kc + 1][3], pl[3]);
#pragma unroll
                for (int np = 0; np < 4; np++)
                    ldsm4t(vv[np], V_s + ((kc * 16 + vrow) * AP + np * 16 + vcol) * 2);
#pragma unroll
                for (int np = 0; np < 4; np++) {
                    mma_f16(o[np * 2],     ph, vv[np][0], vv[np][1]);
                    mma_f16(o[np * 2 + 1], ph, vv[np][2], vv[np][3]);
                }
#pragma unroll
                for (int np = 0; np < 4; np++) {
                    mma_f16(o[np * 2],     pl, vv[np][0], vv[np][1]);
                    mma_f16(o[np * 2 + 1], pl, vv[np][2], vv[np][3]);
                }
            }
            __syncthreads();
        }

        // ---- epilogue: z = O / l, single fp16 ----
        float liA = 1.0f / lA, liB = 1.0f / lB;
        int tA = q0 + r0w + g, tB = tA + 8;
#pragma unroll
        for (int nf = 0; nf < 8; nf++) {
            int d = nf * 8 + tc * 2;
            size_t ziA = ((size_t)b * S_LEN + tA) * C_DIM + head * HD + d;
            size_t ziB = ((size_t)b * S_LEN + tB) * C_DIM + head * HD + d;
            *reinterpret_cast<uint32_t*>(g_z + ziA) = pack2h(o[nf][0] * liA, o[nf][1] * liA);
            *reinterpret_cast<uint32_t*>(g_z + ziB) = pack2h(o[nf][2] * liB, o[nf][3] * liB);
        }
        __syncthreads();
    }
}

// ---------------------------------------------------------------------------

extern "C" void kernel_launch(void* const* d_in, const int* in_sizes, int n_in,
                              void* d_out, int out_size) {
    const float* x    = (const float*)d_in[0];
    const float* Wqkv = (const float*)d_in[1];
    const float* bqkv = (const float*)d_in[2];
    const float* Wo   = (const float*)d_in[3];
    const float* bo   = (const float*)d_in[4];
    float* out = (float*)d_out;

    __half *wq_hi, *wq_lo, *wo_hi, *wo_lo;
    cudaGetSymbolAddress((void**)&wq_hi, g_Wq_hi);
    cudaGetSymbolAddress((void**)&wq_lo, g_Wq_lo);
    cudaGetSymbolAddress((void**)&wo_hi, g_Wo_hi);
    cudaGetSymbolAddress((void**)&wo_lo, g_Wo_lo);

    int nq4 = 3 * C_DIM * C_DIM / 4;
    split_kernel<<<(nq4 + 255) / 256, 256>>>(Wqkv, wq_hi, wq_lo, nq4);
    int no4 = C_DIM * C_DIM / 4;
    split_kernel<<<(no4 + 255) / 256, 256>>>(Wo, wo_hi, wo_lo, no4);

    dim3 gT(S_LEN / 32, C_DIM / 32, BATCH);
    xpose_half<<<gT, dim3(32, 8)>>>(x);

    size_t gsmem = 2 * STBYTES;   // 61440
    cudaFuncSetAttribute(qkv_tc, cudaFuncAttributeMaxDynamicSharedMemorySize, (int)gsmem);
    cudaFuncSetAttribute(out_tc, cudaFuncAttributeMaxDynamicSharedMemorySize, (int)gsmem);

    dim3 gA(S_LEN / 128, 3 * C_DIM / 128, BATCH);
    qkv_tc<<<gA, 256, gsmem>>>(bqkv);

    size_t asmem = QBYTES + 2 * KVBUF;   // 73728
    cudaFuncSetAttribute(attn_tc, cudaFuncAttributeMaxDynamicSharedMemorySize, (int)asmem);
    dim3 gB(9, NH, BATCH);
    attn_tc<<<gB, 256, asmem>>>();

    dim3 gC(S_LEN / 128, C_DIM / 128, BATCH);
    out_tc<<<gC, 256, gsmem>>>(bo, out);
}

// round 9
// speedup vs baseline: 7.2440x; 1.4611x over previous
#include <cuda_runtime.h>
#include <cuda_fp16.h>
#include <cstdint>

#define S_LEN 2304
#define C_DIM 1024
#define NH    16
#define HD    64
#define BATCH 2

// ---------------- scratch (all single fp16) -----------------------------------
__device__ __half g_Wq[(size_t)3 * C_DIM * C_DIM];
__device__ __half g_Wo[(size_t)C_DIM * C_DIM];
__device__ __half g_x[(size_t)BATCH * S_LEN * C_DIM];      // x^T tokens-major
__device__ __half g_z[(size_t)BATCH * S_LEN * C_DIM];
__device__ __half g_q[(size_t)BATCH * NH * S_LEN * HD];    // pre-scaled 1/8
__device__ __half g_k[(size_t)BATCH * NH * S_LEN * HD];
__device__ __half g_v[(size_t)BATCH * NH * S_LEN * HD];

// ---------------- helpers ----------------------------------------------------
__device__ __forceinline__ uint32_t smem_u32(const void* p) {
    uint32_t a;
    asm("{ .reg .u64 t; cvta.to.shared.u64 t, %1; cvt.u32.u64 %0, t; }" : "=r"(a) : "l"(p));
    return a;
}
__device__ __forceinline__ void ldsm4(uint32_t* r, uint32_t addr) {
    asm volatile("ldmatrix.sync.aligned.m8n8.x4.shared.b16 {%0,%1,%2,%3}, [%4];"
                 : "=r"(r[0]), "=r"(r[1]), "=r"(r[2]), "=r"(r[3]) : "r"(addr));
}
__device__ __forceinline__ void ldsm4t(uint32_t* r, uint32_t addr) {
    asm volatile("ldmatrix.sync.aligned.m8n8.x4.trans.shared.b16 {%0,%1,%2,%3}, [%4];"
                 : "=r"(r[0]), "=r"(r[1]), "=r"(r[2]), "=r"(r[3]) : "r"(addr));
}
__device__ __forceinline__ void mma_f16(float* c, const uint32_t* a,
                                        uint32_t b0, uint32_t b1) {
    asm volatile(
        "mma.sync.aligned.m16n8k16.row.col.f32.f16.f16.f32 "
        "{%0,%1,%2,%3}, {%4,%5,%6,%7}, {%8,%9}, {%0,%1,%2,%3};"
        : "+f"(c[0]), "+f"(c[1]), "+f"(c[2]), "+f"(c[3])
        : "r"(a[0]), "r"(a[1]), "r"(a[2]), "r"(a[3]), "r"(b0), "r"(b1));
}
#define CP16(dst, src) asm volatile("cp.async.cg.shared.global [%0], [%1], 16;" :: "r"(dst), "l"(src))
#define CP_COMMIT()    asm volatile("cp.async.commit_group;" ::: "memory")
#define CP_WAIT0()     asm volatile("cp.async.wait_group 0;" ::: "memory")
#define CP_WAIT1()     asm volatile("cp.async.wait_group 1;" ::: "memory")

__device__ __forceinline__ uint32_t pack2h(float a, float b) {
    __half2 h = __floats2half2_rn(a, b);
    return *reinterpret_cast<uint32_t*>(&h);
}

// ---------------- prep kernels ----------------------------------------------
__global__ void tohalf_kernel(const float* __restrict__ src,
                              __half* __restrict__ dst, int n4) {
    int i = blockIdx.x * 256 + threadIdx.x;
    if (i >= n4) return;
    float4 v = reinterpret_cast<const float4*>(src)[i];
    uint32_t h0 = pack2h(v.x, v.y), h1 = pack2h(v.z, v.w);
    *reinterpret_cast<uint32_t*>(dst + i * 4)     = h0;
    *reinterpret_cast<uint32_t*>(dst + i * 4 + 2) = h1;
}

__global__ void xpose_half(const float* __restrict__ x) {
    __shared__ float tile[32][33];
    int b = blockIdx.z, t0 = blockIdx.x * 32, c0 = blockIdx.y * 32;
    int tx = threadIdx.x, ty = threadIdx.y;
    for (int i = ty; i < 32; i += 8)
        tile[i][tx] = x[((size_t)b * C_DIM + c0 + i) * S_LEN + t0 + tx];
    __syncthreads();
    for (int i = ty; i < 32; i += 8) {
        size_t oi = ((size_t)b * S_LEN + t0 + i) * C_DIM + c0 + tx;
        g_x[oi] = __float2half_rn(tile[tx][i]);
    }
}

// ---------------- mma.sync GEMM core (single fp16, BK=64) ----------------------
#define GP 72                          // pitch in halfs (144 B rows)
#define TBYTES (128 * GP * 2)          // 18432
#define STBYTES (2 * TBYTES)           // A + B

struct Frag { float acc[2][8][4]; };

__device__ __forceinline__ void fill_async(
    uint32_t stage_s, int tid, int k0,
    const __half* A, const __half* B) {
    int row = tid >> 1, half = tid & 1;
    size_t go = (size_t)row * C_DIM + k0 + half * 32;   // halfs
    uint32_t so = row * 144 + half * 64;                // bytes
    const char* sa = (const char*)(A + go);
    const char* sb = (const char*)(B + go);
    uint32_t da = stage_s + so, db = stage_s + TBYTES + so;
#pragma unroll
    for (int j = 0; j < 4; j++) CP16(da + j * 16, sa + j * 16);
#pragma unroll
    for (int j = 0; j < 4; j++) CP16(db + j * 16, sb + j * 16);
    CP_COMMIT();
}

__device__ __forceinline__ void compute_stage(
    uint32_t st, int lane, int wm, int wn, Frag& f) {
    uint32_t A_s = st, B_s = st + TBYTES;
    int bgrp = lane >> 3, br = lane & 7;
    int brow = wn * 64 + (bgrp >> 1) * 8 + br;
    int bcolh = (bgrp & 1) * 8;
    int ar = lane & 15, acolh = (lane >> 4) * 8;
#pragma unroll
    for (int ks = 0; ks < 4; ks++) {
        uint32_t a[2][4], bb[4][4];
#pragma unroll
        for (int mi = 0; mi < 2; mi++)
            ldsm4(a[mi], A_s + ((wm * 32 + mi * 16 + ar) * GP + ks * 16 + acolh) * 2);
#pragma unroll
        for (int nj = 0; nj < 4; nj++)
            ldsm4(bb[nj], B_s + ((brow + nj * 16) * GP + ks * 16 + bcolh) * 2);
#pragma unroll
        for (int mi = 0; mi < 2; mi++)
#pragma unroll
            for (int nj = 0; nj < 4; nj++) {
                mma_f16(f.acc[mi][nj * 2],     a[mi], bb[nj][0], bb[nj][1]);
                mma_f16(f.acc[mi][nj * 2 + 1], a[mi], bb[nj][2], bb[nj][3]);
            }
    }
}

__device__ __forceinline__ void gemm_body(
    uint32_t smb, int tid, Frag& f, const __half* A, const __half* B) {
    int lane = tid & 31, wid = tid >> 5;
    int wm = wid & 3, wn = wid >> 2;
    const int NC = C_DIM / 64;  // 16
    fill_async(smb, tid, 0, A, B);
    for (int ch = 0; ch < NC; ch++) {
        if (ch + 1 < NC) {
            fill_async(smb + ((ch + 1) & 1) * STBYTES, tid, (ch + 1) * 64, A, B);
            CP_WAIT1();
        } else {
            CP_WAIT0();
        }
        __syncthreads();
        compute_stage(smb + (ch & 1) * STBYTES, lane, wm, wn, f);
        __syncthreads();
    }
}

// ---------------- QKV projection -----------------------------------------------
__global__ __launch_bounds__(256, 2)
void qkv_tc(const float* __restrict__ bias) {
    extern __shared__ char sm[];
    uint32_t smb = smem_u32(sm);
    int tid = threadIdx.x;
    int b = blockIdx.z, m0 = blockIdx.y * 128, n0 = blockIdx.x * 128;

    Frag f;
#pragma unroll
    for (int mi = 0; mi < 2; mi++)
#pragma unroll
        for (int ni = 0; ni < 8; ni++)
#pragma unroll
            for (int r = 0; r < 4; r++) f.acc[mi][ni][r] = 0.0f;

    gemm_body(smb, tid, f,
              g_Wq + (size_t)m0 * C_DIM,
              g_x + ((size_t)b * S_LEN + n0) * C_DIM);

    int lane = tid & 31, wid = tid >> 5;
    int wm = wid & 3, wn = wid >> 2;
    int which = m0 >> 10;
    __half* dstb = (which == 0) ? g_q : (which == 1) ? g_k : g_v;
    float scale = (which == 0) ? 0.125f : 1.0f;
#pragma unroll
    for (int mi = 0; mi < 2; mi++) {
#pragma unroll
        for (int rg = 0; rg < 2; rg++) {
            int m = m0 + wm * 32 + mi * 16 + (lane >> 2) + rg * 8;
            int head = (m >> 6) & 15, d = m & 63;
            float bv = bias[m];
            __half* dst = dstb + ((size_t)(b * NH + head)) * S_LEN * HD + d;
#pragma unroll
            for (int ni = 0; ni < 8; ni++) {
                int t = n0 + wn * 64 + ni * 8 + ((lane & 3) << 1);
                dst[(size_t)t * HD]       = __float2half_rn((f.acc[mi][ni][rg * 2 + 0] + bv) * scale);
                dst[(size_t)(t + 1) * HD] = __float2half_rn((f.acc[mi][ni][rg * 2 + 1] + bv) * scale);
            }
        }
    }
}

// ---------------- Output projection ---------------------------------------------
__global__ __launch_bounds__(256, 2)
void out_tc(const float* __restrict__ bo, float* __restrict__ out) {
    extern __shared__ char sm[];
    uint32_t smb = smem_u32(sm);
    int tid = threadIdx.x;
    int b = blockIdx.z, m0 = blockIdx.y * 128, n0 = blockIdx.x * 128;

    Frag f;
#pragma unroll
    for (int mi = 0; mi < 2; mi++)
#pragma unroll
        for (int ni = 0; ni < 8; ni++)
#pragma unroll
            for (int r = 0; r < 4; r++) f.acc[mi][ni][r] = 0.0f;

    gemm_body(smb, tid, f,
              g_Wo + (size_t)m0 * C_DIM,
              g_z + ((size_t)b * S_LEN + n0) * C_DIM);

    int lane = tid & 31, wid = tid >> 5;
    int wm = wid & 3, wn = wid >> 2;
#pragma unroll
    for (int mi = 0; mi < 2; mi++) {
#pragma unroll
        for (int rg = 0; rg < 2; rg++) {
            int m = m0 + wm * 32 + mi * 16 + (lane >> 2) + rg * 8;
            float bv = bo[m];
            float* dst = out + ((size_t)b * C_DIM + m) * S_LEN;
#pragma unroll
            for (int ni = 0; ni < 8; ni++) {
                int t = n0 + wn * 64 + ni * 8 + ((lane & 3) << 1);
                float2 v = {f.acc[mi][ni][rg * 2 + 0] + bv,
                            f.acc[mi][ni][rg * 2 + 1] + bv};
                *reinterpret_cast<float2*>(dst + t) = v;
            }
        }
    }
}

// ---------------- Flash attention (single fp16) ---------------------------------
#define AP 72
#define QBYTES   18432              // Q single, 128x144B
#define KVTILE   9216
#define KVBUF    18432              // K + V

__device__ __forceinline__ void fill_kv(
    uint32_t dst, int tid, int s0, const __half* k, const __half* v) {
#pragma unroll
    for (int i = tid; i < 512; i += 256) {
        int r = i >> 3, c = (i & 7) * 16;
        uint32_t so = r * 144 + c;
        size_t go = (size_t)(s0 + r) * HD;
        CP16(dst + so,          (const char*)(k + go) + c);
        CP16(dst + KVTILE + so, (const char*)(v + go) + c);
    }
    CP_COMMIT();
}

__global__ __launch_bounds__(256, 2)
void attn_tc() {
    extern __shared__ char sm[];
    uint32_t smb = smem_u32(sm);
    uint32_t Q_s  = smb;
    uint32_t KV_s = smb + QBYTES;

    int head = blockIdx.y, b = blockIdx.z;
    int tid = threadIdx.x, lane = tid & 31, wid = tid >> 5;
    int r0w = wid * 16;
    int g = lane >> 2, tc = lane & 3;

    size_t base = ((size_t)(b * NH + head)) * S_LEN * HD;
    const __half* qp = g_q + base;
    const __half* kp = g_k + base;
    const __half* vp = g_v + base;

    int ar = lane & 15, ach = (lane >> 4) * 8;
    int bg = lane >> 3, br = lane & 7;
    int krow_off = ((bg >> 1) * 8 + br) * AP + (bg & 1) * 8;
    int vrow = ((lane >> 3) & 1) * 8 + (lane & 7);
    int vcol = (lane >> 4) * 8;

    for (int rep = 0; rep < 2; rep++) {
        int qt = rep == 0 ? (17 - (int)blockIdx.x) : (int)blockIdx.x;
        int q0 = qt * 128;

#pragma unroll
        for (int i = tid; i < 1024; i += 256) {
            int r = i >> 3, c = (i & 7) * 16;
            CP16(Q_s + r * 144 + c, (const char*)(qp + (size_t)(q0 + r) * HD) + c);
        }
        CP_COMMIT();
        CP_WAIT0();
        __syncthreads();

        float o[8][4] = {};
        float mA = -1e30f, mB = -1e30f, lA = 0.0f, lB = 0.0f;

        int nkt = 2 * qt + 2;
        fill_kv(KV_s, tid, 0, kp, vp);
        for (int kt = 0; kt < nkt; kt++) {
            int c0 = kt * 64;
            if (kt + 1 < nkt) {
                fill_kv(KV_s + ((kt + 1) & 1) * KVBUF, tid, (kt + 1) * 64, kp, vp);
                CP_WAIT1();
            } else {
                CP_WAIT0();
            }
            __syncthreads();
            uint32_t K_s = KV_s + (kt & 1) * KVBUF;
            uint32_t V_s = K_s + KVTILE;

            // ---- S = Q K^T (single pass) ----
            float s[8][4] = {};
#pragma unroll
            for (int kc = 0; kc < 4; kc++) {
                uint32_t qh[4], kk[4][4];
                ldsm4(qh, Q_s + ((r0w + ar) * AP + kc * 16 + ach) * 2);
#pragma unroll
                for (int np = 0; np < 4; np++)
                    ldsm4(kk[np], K_s + (np * 16 * AP + kc * 16 + krow_off) * 2);
#pragma unroll
                for (int np = 0; np < 4; np++) {
                    mma_f16(s[np * 2],     qh, kk[np][0], kk[np][1]);
                    mma_f16(s[np * 2 + 1], qh, kk[np][2], kk[np][3]);
                }
            }

            // ---- mask (register domain) ----
            if (c0 + 63 > q0 + r0w) {
                int rowA = q0 + r0w + g, rowB = rowA + 8;
#pragma unroll
                for (int nf = 0; nf < 8; nf++) {
                    int col = c0 + nf * 8 + tc * 2;
                    if (col     > rowA) s[nf][0] -= 10000.0f;
                    if (col + 1 > rowA) s[nf][1] -= 10000.0f;
                    if (col     > rowB) s[nf][2] -= 10000.0f;
                    if (col + 1 > rowB) s[nf][3] -= 10000.0f;
                }
            }

            // ---- register softmax ----
            float pmA = -1e30f, pmB = -1e30f;
#pragma unroll
            for (int nf = 0; nf < 8; nf++) {
                pmA = fmaxf(pmA, fmaxf(s[nf][0], s[nf][1]));
                pmB = fmaxf(pmB, fmaxf(s[nf][2], s[nf][3]));
            }
            pmA = fmaxf(pmA, __shfl_xor_sync(0xffffffffu, pmA, 1));
            pmA = fmaxf(pmA, __shfl_xor_sync(0xffffffffu, pmA, 2));
            pmB = fmaxf(pmB, __shfl_xor_sync(0xffffffffu, pmB, 1));
            pmB = fmaxf(pmB, __shfl_xor_sync(0xffffffffu, pmB, 2));
            float mnA = fmaxf(mA, pmA), mnB = fmaxf(mB, pmB);
            float alA = __expf(mA - mnA), alB = __expf(mB - mnB);
            float lsA = 0.0f, lsB = 0.0f;
#pragma unroll
            for (int nf = 0; nf < 8; nf++) {
                s[nf][0] = __expf(s[nf][0] - mnA);
                s[nf][1] = __expf(s[nf][1] - mnA);
                s[nf][2] = __expf(s[nf][2] - mnB);
                s[nf][3] = __expf(s[nf][3] - mnB);
                lsA += s[nf][0] + s[nf][1];
                lsB += s[nf][2] + s[nf][3];
            }
            lsA += __shfl_xor_sync(0xffffffffu, lsA, 1);
            lsA += __shfl_xor_sync(0xffffffffu, lsA, 2);
            lsB += __shfl_xor_sync(0xffffffffu, lsB, 1);
            lsB += __shfl_xor_sync(0xffffffffu, lsB, 2);
            lA = lA * alA + lsA;
            lB = lB * alB + lsB;
            mA = mnA; mB = mnB;
#pragma unroll
            for (int nf = 0; nf < 8; nf++) {
                o[nf][0] *= alA; o[nf][1] *= alA;
                o[nf][2] *= alB; o[nf][3] *= alB;
            }

            // ---- O += P V (single pass) ----
#pragma unroll
            for (int kc = 0; kc < 4; kc++) {
                uint32_t ph[4], vv[4][4];
                ph[0] = pack2h(s[2 * kc][0],     s[2 * kc][1]);
                ph[1] = pack2h(s[2 * kc][2],     s[2 * kc][3]);
                ph[2] = pack2h(s[2 * kc + 1][0], s[2 * kc + 1][1]);
                ph[3] = pack2h(s[2 * kc + 1][2], s[2 * kc + 1][3]);
#pragma unroll
                for (int np = 0; np < 4; np++)
                    ldsm4t(vv[np], V_s + ((kc * 16 + vrow) * AP + np * 16 + vcol) * 2);
#pragma unroll
                for (int np = 0; np < 4; np++) {
                    mma_f16(o[np * 2],     ph, vv[np][0], vv[np][1]);
                    mma_f16(o[np * 2 + 1], ph, vv[np][2], vv[np][3]);
                }
            }
            __syncthreads();
        }

        // ---- epilogue: z = O / l, fp16 ----
        float liA = 1.0f / lA, liB = 1.0f / lB;
        int tA = q0 + r0w + g, tB = tA + 8;
#pragma unroll
        for (int nf = 0; nf < 8; nf++) {
            int d = nf * 8 + tc * 2;
            size_t ziA = ((size_t)b * S_LEN + tA) * C_DIM + head * HD + d;
            size_t ziB = ((size_t)b * S_LEN + tB) * C_DIM + head * HD + d;
            *reinterpret_cast<uint32_t*>(g_z + ziA) = pack2h(o[nf][0] * liA, o[nf][1] * liA);
            *reinterpret_cast<uint32_t*>(g_z + ziB) = pack2h(o[nf][2] * liB, o[nf][3] * liB);
        }
        __syncthreads();
    }
}

// ---------------------------------------------------------------------------

extern "C" void kernel_launch(void* const* d_in, const int* in_sizes, int n_in,
                              void* d_out, int out_size) {
    const float* x    = (const float*)d_in[0];
    const float* Wqkv = (const float*)d_in[1];
    const float* bqkv = (const float*)d_in[2];
    const float* Wo   = (const float*)d_in[3];
    const float* bo   = (const float*)d_in[4];
    float* out = (float*)d_out;

    __half *wq, *wo;
    cudaGetSymbolAddress((void**)&wq, g_Wq);
    cudaGetSymbolAddress((void**)&wo, g_Wo);

    int nq4 = 3 * C_DIM * C_DIM / 4;
    tohalf_kernel<<<(nq4 + 255) / 256, 256>>>(Wqkv, wq, nq4);
    int no4 = C_DIM * C_DIM / 4;
    tohalf_kernel<<<(no4 + 255) / 256, 256>>>(Wo, wo, no4);

    dim3 gT(S_LEN / 32, C_DIM / 32, BATCH);
    xpose_half<<<gT, dim3(32, 8)>>>(x);

    size_t gsmem = 2 * STBYTES;   // 73728
    cudaFuncSetAttribute(qkv_tc, cudaFuncAttributeMaxDynamicSharedMemorySize, (int)gsmem);
    cudaFuncSetAttribute(out_tc, cudaFuncAttributeMaxDynamicSharedMemorySize, (int)gsmem);

    dim3 gA(S_LEN / 128, 3 * C_DIM / 128, BATCH);
    qkv_tc<<<gA, 256, gsmem>>>(bqkv);

    size_t asmem = QBYTES + 2 * KVBUF;   // 55296
    cudaFuncSetAttribute(attn_tc, cudaFuncAttributeMaxDynamicSharedMemorySize, (int)asmem);
    dim3 gB(9, NH, BATCH);
    attn_tc<<<gB, 256, asmem>>>();

    dim3 gC(S_LEN / 128, C_DIM / 128, BATCH);
    out_tc<<<gC, 256, gsmem>>>(bo, out);
}

// round 10
// speedup vs baseline: 7.7333x; 1.0676x over previous
#include <cuda_runtime.h>
#include <cuda_fp16.h>
#include <cstdint>

#define S_LEN 2304
#define C_DIM 1024
#define NH    16
#define HD    64
#define BATCH 2

// ---------------- scratch (all single fp16) -----------------------------------
__device__ __half g_Wq[(size_t)3 * C_DIM * C_DIM];
__device__ __half g_Wo[(size_t)C_DIM * C_DIM];
__device__ __half g_x[(size_t)BATCH * S_LEN * C_DIM];      // x^T tokens-major
__device__ __half g_z[(size_t)BATCH * S_LEN * C_DIM];
__device__ __half g_q[(size_t)BATCH * NH * S_LEN * HD];    // pre-scaled 1/8
__device__ __half g_k[(size_t)BATCH * NH * S_LEN * HD];
__device__ __half g_v[(size_t)BATCH * NH * S_LEN * HD];

// ---------------- helpers ----------------------------------------------------
__device__ __forceinline__ uint32_t smem_u32(const void* p) {
    uint32_t a;
    asm("{ .reg .u64 t; cvta.to.shared.u64 t, %1; cvt.u32.u64 %0, t; }" : "=r"(a) : "l"(p));
    return a;
}
__device__ __forceinline__ void ldsm4(uint32_t* r, uint32_t addr) {
    asm volatile("ldmatrix.sync.aligned.m8n8.x4.shared.b16 {%0,%1,%2,%3}, [%4];"
                 : "=r"(r[0]), "=r"(r[1]), "=r"(r[2]), "=r"(r[3]) : "r"(addr));
}
__device__ __forceinline__ void ldsm4t(uint32_t* r, uint32_t addr) {
    asm volatile("ldmatrix.sync.aligned.m8n8.x4.trans.shared.b16 {%0,%1,%2,%3}, [%4];"
                 : "=r"(r[0]), "=r"(r[1]), "=r"(r[2]), "=r"(r[3]) : "r"(addr));
}
__device__ __forceinline__ void mma_f16(float* c, const uint32_t* a,
                                        uint32_t b0, uint32_t b1) {
    asm volatile(
        "mma.sync.aligned.m16n8k16.row.col.f32.f16.f16.f32 "
        "{%0,%1,%2,%3}, {%4,%5,%6,%7}, {%8,%9}, {%0,%1,%2,%3};"
        : "+f"(c[0]), "+f"(c[1]), "+f"(c[2]), "+f"(c[3])
        : "r"(a[0]), "r"(a[1]), "r"(a[2]), "r"(a[3]), "r"(b0), "r"(b1));
}
#define CP16(dst, src) asm volatile("cp.async.cg.shared.global [%0], [%1], 16;" :: "r"(dst), "l"(src))
#define CP_COMMIT()    asm volatile("cp.async.commit_group;" ::: "memory")
#define CP_WAIT0()     asm volatile("cp.async.wait_group 0;" ::: "memory")
#define CP_WAIT1()     asm volatile("cp.async.wait_group 1;" ::: "memory")

__device__ __forceinline__ uint32_t pack2h(float a, float b) {
    __half2 h = __floats2half2_rn(a, b);
    return *reinterpret_cast<uint32_t*>(&h);
}

// ---------------- prep kernels ----------------------------------------------
__global__ void tohalf_kernel(const float* __restrict__ src,
                              __half* __restrict__ dst, int n4) {
    int i = blockIdx.x * 256 + threadIdx.x;
    if (i >= n4) return;
    float4 v = reinterpret_cast<const float4*>(src)[i];
    uint32_t h0 = pack2h(v.x, v.y), h1 = pack2h(v.z, v.w);
    *reinterpret_cast<uint32_t*>(dst + i * 4)     = h0;
    *reinterpret_cast<uint32_t*>(dst + i * 4 + 2) = h1;
}

__global__ void xpose_half(const float* __restrict__ x) {
    __shared__ float tile[32][33];
    int b = blockIdx.z, t0 = blockIdx.x * 32, c0 = blockIdx.y * 32;
    int tx = threadIdx.x, ty = threadIdx.y;
    for (int i = ty; i < 32; i += 8)
        tile[i][tx] = x[((size_t)b * C_DIM + c0 + i) * S_LEN + t0 + tx];
    __syncthreads();
    for (int i = ty; i < 32; i += 8) {
        size_t oi = ((size_t)b * S_LEN + t0 + i) * C_DIM + c0 + tx;
        g_x[oi] = __float2half_rn(tile[tx][i]);
    }
}

// ---------------- mma.sync GEMM core (single fp16, BK=64, 3-stage) -------------
#define GP 72                          // pitch in halfs (144 B rows)
#define TBYTES (128 * GP * 2)          // 18432
#define STBYTES (2 * TBYTES)           // A + B per stage

struct Frag { float acc[2][8][4]; };

__device__ __forceinline__ void fill_async(
    uint32_t stage_s, int tid, int k0,
    const __half* A, const __half* B) {
    int row = tid >> 1, half = tid & 1;
    size_t go = (size_t)row * C_DIM + k0 + half * 32;   // halfs
    uint32_t so = row * 144 + half * 64;                // bytes
    const char* sa = (const char*)(A + go);
    const char* sb = (const char*)(B + go);
    uint32_t da = stage_s + so, db = stage_s + TBYTES + so;
#pragma unroll
    for (int j = 0; j < 4; j++) CP16(da + j * 16, sa + j * 16);
#pragma unroll
    for (int j = 0; j < 4; j++) CP16(db + j * 16, sb + j * 16);
    CP_COMMIT();
}

__device__ __forceinline__ void compute_stage(
    uint32_t st, int lane, int wm, int wn, Frag& f) {
    uint32_t A_s = st, B_s = st + TBYTES;
    int bgrp = lane >> 3, br = lane & 7;
    int brow = wn * 64 + (bgrp >> 1) * 8 + br;
    int bcolh = (bgrp & 1) * 8;
    int ar = lane & 15, acolh = (lane >> 4) * 8;
#pragma unroll
    for (int ks = 0; ks < 4; ks++) {
        uint32_t a[2][4], bb[4][4];
#pragma unroll
        for (int mi = 0; mi < 2; mi++)
            ldsm4(a[mi], A_s + ((wm * 32 + mi * 16 + ar) * GP + ks * 16 + acolh) * 2);
#pragma unroll
        for (int nj = 0; nj < 4; nj++)
            ldsm4(bb[nj], B_s + ((brow + nj * 16) * GP + ks * 16 + bcolh) * 2);
#pragma unroll
        for (int mi = 0; mi < 2; mi++)
#pragma unroll
            for (int nj = 0; nj < 4; nj++) {
                mma_f16(f.acc[mi][nj * 2],     a[mi], bb[nj][0], bb[nj][1]);
                mma_f16(f.acc[mi][nj * 2 + 1], a[mi], bb[nj][2], bb[nj][3]);
            }
    }
}

// 3-stage ring, ONE __syncthreads per iteration.
// Recycled stage (ch+1)%3 was computed at ch-2, protected by sync at ch-1.
__device__ __forceinline__ void gemm_body(
    uint32_t smb, int tid, Frag& f, const __half* A, const __half* B) {
    int lane = tid & 31, wid = tid >> 5;
    int wm = wid & 3, wn = wid >> 2;
    const int NC = C_DIM / 64;  // 16
    fill_async(smb, tid, 0, A, B);
    for (int ch = 0; ch < NC; ch++) {
        if (ch + 1 < NC) {
            fill_async(smb + ((ch + 1) % 3) * STBYTES, tid, (ch + 1) * 64, A, B);
            CP_WAIT1();
        } else {
            CP_WAIT0();
        }
        __syncthreads();
        compute_stage(smb + (ch % 3) * STBYTES, lane, wm, wn, f);
    }
}

// ---------------- QKV projection (A = tokens, B = channels) --------------------
__global__ __launch_bounds__(256, 2)
void qkv_tc(const float* __restrict__ bias) {
    extern __shared__ char sm[];
    uint32_t smb = smem_u32(sm);
    int tid = threadIdx.x;
    int b = blockIdx.z, n0 = blockIdx.x * 128, m0 = blockIdx.y * 128;

    Frag f;
#pragma unroll
    for (int mi = 0; mi < 2; mi++)
#pragma unroll
        for (int ni = 0; ni < 8; ni++)
#pragma unroll
            for (int r = 0; r < 4; r++) f.acc[mi][ni][r] = 0.0f;

    gemm_body(smb, tid, f,
              g_x + ((size_t)b * S_LEN + n0) * C_DIM,   // A rows = tokens
              g_Wq + (size_t)m0 * C_DIM);               // B rows = channels

    int lane = tid & 31, wid = tid >> 5;
    int wm = wid & 3, wn = wid >> 2;
    int tc = lane & 3;
    int which = m0 >> 10;
    __half* dstb = (which == 0) ? g_q : (which == 1) ? g_k : g_v;
    float scale = (which == 0) ? 0.125f : 1.0f;
    int mw = m0 + wn * 64;                 // 64-aligned -> one head per warp-col
    int head = (mw >> 6) & 15;
    __half* base = dstb + ((size_t)(b * NH + head)) * S_LEN * HD;

    float bv0[8], bv1[8];
#pragma unroll
    for (int ni = 0; ni < 8; ni++) {
        bv0[ni] = bias[mw + ni * 8 + tc * 2];
        bv1[ni] = bias[mw + ni * 8 + tc * 2 + 1];
    }
#pragma unroll
    for (int mi = 0; mi < 2; mi++) {
#pragma unroll
        for (int rg = 0; rg < 2; rg++) {
            int t = n0 + wm * 32 + mi * 16 + (lane >> 2) + rg * 8;
            __half* rowp = base + (size_t)t * HD + tc * 2;
#pragma unroll
            for (int ni = 0; ni < 8; ni++) {
                uint32_t u = pack2h((f.acc[mi][ni][rg * 2 + 0] + bv0[ni]) * scale,
                                    (f.acc[mi][ni][rg * 2 + 1] + bv1[ni]) * scale);
                *reinterpret_cast<uint32_t*>(rowp + ni * 8) = u;
            }
        }
    }
}

// ---------------- Output projection ---------------------------------------------
__global__ __launch_bounds__(256, 2)
void out_tc(const float* __restrict__ bo, float* __restrict__ out) {
    extern __shared__ char sm[];
    uint32_t smb = smem_u32(sm);
    int tid = threadIdx.x;
    int b = blockIdx.z, m0 = blockIdx.y * 128, n0 = blockIdx.x * 128;

    Frag f;
#pragma unroll
    for (int mi = 0; mi < 2; mi++)
#pragma unroll
        for (int ni = 0; ni < 8; ni++)
#pragma unroll
            for (int r = 0; r < 4; r++) f.acc[mi][ni][r] = 0.0f;

    gemm_body(smb, tid, f,
              g_Wo + (size_t)m0 * C_DIM,
              g_z + ((size_t)b * S_LEN + n0) * C_DIM);

    int lane = tid & 31, wid = tid >> 5;
    int wm = wid & 3, wn = wid >> 2;
#pragma unroll
    for (int mi = 0; mi < 2; mi++) {
#pragma unroll
        for (int rg = 0; rg < 2; rg++) {
            int m = m0 + wm * 32 + mi * 16 + (lane >> 2) + rg * 8;
            float bv = bo[m];
            float* dst = out + ((size_t)b * C_DIM + m) * S_LEN;
#pragma unroll
            for (int ni = 0; ni < 8; ni++) {
                int t = n0 + wn * 64 + ni * 8 + ((lane & 3) << 1);
                float2 v = {f.acc[mi][ni][rg * 2 + 0] + bv,
                            f.acc[mi][ni][rg * 2 + 1] + bv};
                *reinterpret_cast<float2*>(dst + t) = v;
            }
        }
    }
}

// ---------------- Flash attention (single fp16, 3-stage KV ring) ----------------
#define AP 72
#define QBYTES   18432              // Q, 128x144B
#define KVTILE   9216
#define KVBUF    18432              // K + V per stage

__device__ __forceinline__ void fill_kv(
    uint32_t dst, int tid, int s0, const __half* k, const __half* v) {
#pragma unroll
    for (int i = tid; i < 512; i += 256) {
        int r = i >> 3, c = (i & 7) * 16;
        uint32_t so = r * 144 + c;
        size_t go = (size_t)(s0 + r) * HD;
        CP16(dst + so,          (const char*)(k + go) + c);
        CP16(dst + KVTILE + so, (const char*)(v + go) + c);
    }
    CP_COMMIT();
}

__global__ __launch_bounds__(256, 2)
void attn_tc() {
    extern __shared__ char sm[];
    uint32_t smb = smem_u32(sm);
    uint32_t Q_s  = smb;
    uint32_t KV_s = smb + QBYTES;

    int head = blockIdx.y, b = blockIdx.z;
    int tid = threadIdx.x, lane = tid & 31, wid = tid >> 5;
    int r0w = wid * 16;
    int g = lane >> 2, tc = lane & 3;

    size_t base = ((size_t)(b * NH + head)) * S_LEN * HD;
    const __half* qp = g_q + base;
    const __half* kp = g_k + base;
    const __half* vp = g_v + base;

    int ar = lane & 15, ach = (lane >> 4) * 8;
    int bg = lane >> 3, br = lane & 7;
    int krow_off = ((bg >> 1) * 8 + br) * AP + (bg & 1) * 8;
    int vrow = ((lane >> 3) & 1) * 8 + (lane & 7);
    int vcol = (lane >> 4) * 8;

    for (int rep = 0; rep < 2; rep++) {
        int qt = rep == 0 ? (17 - (int)blockIdx.x) : (int)blockIdx.x;
        int q0 = qt * 128;

        // Q load (completion covered by first KV wait — groups retire in order)
#pragma unroll
        for (int i = tid; i < 1024; i += 256) {
            int r = i >> 3, c = (i & 7) * 16;
            CP16(Q_s + r * 144 + c, (const char*)(qp + (size_t)(q0 + r) * HD) + c);
        }
        CP_COMMIT();

        float o[8][4] = {};
        float mA = -1e30f, mB = -1e30f, lA = 0.0f, lB = 0.0f;

        int nkt = 2 * qt + 2;
        fill_kv(KV_s, tid, 0, kp, vp);
        for (int kt = 0; kt < nkt; kt++) {
            int c0 = kt * 64;
            if (kt + 1 < nkt) {
                fill_kv(KV_s + ((kt + 1) % 3) * KVBUF, tid, (kt + 1) * 64, kp, vp);
                CP_WAIT1();
            } else {
                CP_WAIT0();
            }
            __syncthreads();
            uint32_t K_s = KV_s + (kt % 3) * KVBUF;
            uint32_t V_s = K_s + KVTILE;

            // ---- S = Q K^T ----
            float s[8][4] = {};
#pragma unroll
            for (int kc = 0; kc < 4; kc++) {
                uint32_t qh[4], kk[4][4];
                ldsm4(qh, Q_s + ((r0w + ar) * AP + kc * 16 + ach) * 2);
#pragma unroll
                for (int np = 0; np < 4; np++)
                    ldsm4(kk[np], K_s + (np * 16 * AP + kc * 16 + krow_off) * 2);
#pragma unroll
                for (int np = 0; np < 4; np++) {
                    mma_f16(s[np * 2],     qh, kk[np][0], kk[np][1]);
                    mma_f16(s[np * 2 + 1], qh, kk[np][2], kk[np][3]);
                }
            }

            // ---- mask (register domain) ----
            if (c0 + 63 > q0 + r0w) {
                int rowA = q0 + r0w + g, rowB = rowA + 8;
#pragma unroll
                for (int nf = 0; nf < 8; nf++) {
                    int col = c0 + nf * 8 + tc * 2;
                    if (col     > rowA) s[nf][0] -= 10000.0f;
                    if (col + 1 > rowA) s[nf][1] -= 10000.0f;
                    if (col     > rowB) s[nf][2] -= 10000.0f;
                    if (col + 1 > rowB) s[nf][3] -= 10000.0f;
                }
            }

            // ---- register softmax ----
            float pmA = -1e30f, pmB = -1e30f;
#pragma unroll
            for (int nf = 0; nf < 8; nf++) {
                pmA = fmaxf(pmA, fmaxf(s[nf][0], s[nf][1]));
                pmB = fmaxf(pmB, fmaxf(s[nf][2], s[nf][3]));
            }
            pmA = fmaxf(pmA, __shfl_xor_sync(0xffffffffu, pmA, 1));
            pmA = fmaxf(pmA, __shfl_xor_sync(0xffffffffu, pmA, 2));
            pmB = fmaxf(pmB, __shfl_xor_sync(0xffffffffu, pmB, 1));
            pmB = fmaxf(pmB, __shfl_xor_sync(0xffffffffu, pmB, 2));
            float mnA = fmaxf(mA, pmA), mnB = fmaxf(mB, pmB);
            float alA = __expf(mA - mnA), alB = __expf(mB - mnB);
            float lsA = 0.0f, lsB = 0.0f;
#pragma unroll
            for (int nf = 0; nf < 8; nf++) {
                s[nf][0] = __expf(s[nf][0] - mnA);
                s[nf][1] = __expf(s[nf][1] - mnA);
                s[nf][2] = __expf(s[nf][2] - mnB);
                s[nf][3] = __expf(s[nf][3] - mnB);
                lsA += s[nf][0] + s[nf][1];
                lsB += s[nf][2] + s[nf][3];
            }
            lsA += __shfl_xor_sync(0xffffffffu, lsA, 1);
            lsA += __shfl_xor_sync(0xffffffffu, lsA, 2);
            lsB += __shfl_xor_sync(0xffffffffu, lsB, 1);
            lsB += __shfl_xor_sync(0xffffffffu, lsB, 2);
            lA = lA * alA + lsA;
            lB = lB * alB + lsB;
            mA = mnA; mB = mnB;
#pragma unroll
            for (int nf = 0; nf < 8; nf++) {
                o[nf][0] *= alA; o[nf][1] *= alA;
                o[nf][2] *= alB; o[nf][3] *= alB;
            }

            // ---- O += P V ----
#pragma unroll
            for (int kc = 0; kc < 4; kc++) {
                uint32_t ph[4], vv[4][4];
                ph[0] = pack2h(s[2 * kc][0],     s[2 * kc][1]);
                ph[1] = pack2h(s[2 * kc][2],     s[2 * kc][3]);
                ph[2] = pack2h(s[2 * kc + 1][0], s[2 * kc + 1][1]);
                ph[3] = pack2h(s[2 * kc + 1][2], s[2 * kc + 1][3]);
#pragma unroll
                for (int np = 0; np < 4; np++)
                    ldsm4t(vv[np], V_s + ((kc * 16 + vrow) * AP + np * 16 + vcol) * 2);
#pragma unroll
                for (int np = 0; np < 4; np++) {
                    mma_f16(o[np * 2],     ph, vv[np][0], vv[np][1]);
                    mma_f16(o[np * 2 + 1], ph, vv[np][2], vv[np][3]);
                }
            }
            // no trailing sync — 3-stage ring makes refill safe
        }

        // ---- epilogue: z = O / l, fp16 ----
        float liA = 1.0f / lA, liB = 1.0f / lB;
        int tA = q0 + r0w + g, tB = tA + 8;
#pragma unroll
        for (int nf = 0; nf < 8; nf++) {
            int d = nf * 8 + tc * 2;
            size_t ziA = ((size_t)b * S_LEN + tA) * C_DIM + head * HD + d;
            size_t ziB = ((size_t)b * S_LEN + tB) * C_DIM + head * HD + d;
            *reinterpret_cast<uint32_t*>(g_z + ziA) = pack2h(o[nf][0] * liA, o[nf][1] * liA);
            *reinterpret_cast<uint32_t*>(g_z + ziB) = pack2h(o[nf][2] * liB, o[nf][3] * liB);
        }
        __syncthreads();   // protect Q/KV refill for rep 1
    }
}

// ---------------------------------------------------------------------------

extern "C" void kernel_launch(void* const* d_in, const int* in_sizes, int n_in,
                              void* d_out, int out_size) {
    const float* x    = (const float*)d_in[0];
    const float* Wqkv = (const float*)d_in[1];
    const float* bqkv = (const float*)d_in[2];
    const float* Wo   = (const float*)d_in[3];
    const float* bo   = (const float*)d_in[4];
    float* out = (float*)d_out;

    __half *wq, *wo;
    cudaGetSymbolAddress((void**)&wq, g_Wq);
    cudaGetSymbolAddress((void**)&wo, g_Wo);

    int nq4 = 3 * C_DIM * C_DIM / 4;
    tohalf_kernel<<<(nq4 + 255) / 256, 256>>>(Wqkv, wq, nq4);
    int no4 = C_DIM * C_DIM / 4;
    tohalf_kernel<<<(no4 + 255) / 256, 256>>>(Wo, wo, no4);

    dim3 gT(S_LEN / 32, C_DIM / 32, BATCH);
    xpose_half<<<gT, dim3(32, 8)>>>(x);

    size_t gsmem = 3 * STBYTES;   // 110592
    cudaFuncSetAttribute(qkv_tc, cudaFuncAttributeMaxDynamicSharedMemorySize, (int)gsmem);
    cudaFuncSetAttribute(out_tc, cudaFuncAttributeMaxDynamicSharedMemorySize, (int)gsmem);

    dim3 gA(S_LEN / 128, 3 * C_DIM / 128, BATCH);
    qkv_tc<<<gA, 256, gsmem>>>(bqkv);

    size_t asmem = QBYTES + 3 * KVBUF;   // 73728
    cudaFuncSetAttribute(attn_tc, cudaFuncAttributeMaxDynamicSharedMemorySize, (int)asmem);
    dim3 gB(9, NH, BATCH);
    attn_tc<<<gB, 256, asmem>>>();

    dim3 gC(S_LEN / 128, C_DIM / 128, BATCH);
    out_tc<<<gC, 256, gsmem>>>(bo, out);
}

// round 11
// speedup vs baseline: 9.4521x; 1.2223x over previous
#include <cuda_runtime.h>
#include <cuda_fp16.h>
#include <cstdint>

#define S_LEN 2304
#define C_DIM 1024
#define NH    16
#define HD    64
#define BATCH 2

// ---------------- scratch (all single fp16) -----------------------------------
__device__ __half g_Wq[(size_t)3 * C_DIM * C_DIM];
__device__ __half g_Wo[(size_t)C_DIM * C_DIM];
__device__ __half g_x[(size_t)BATCH * S_LEN * C_DIM];      // x^T tokens-major
__device__ __half g_z[(size_t)BATCH * S_LEN * C_DIM];
__device__ __half g_q[(size_t)BATCH * NH * S_LEN * HD];    // pre-scaled 1/8
__device__ __half g_k[(size_t)BATCH * NH * S_LEN * HD];
__device__ __half g_v[(size_t)BATCH * NH * S_LEN * HD];

// ---------------- helpers ----------------------------------------------------
__device__ __forceinline__ uint32_t smem_u32(const void* p) {
    uint32_t a;
    asm("{ .reg .u64 t; cvta.to.shared.u64 t, %1; cvt.u32.u64 %0, t; }" : "=r"(a) : "l"(p));
    return a;
}
__device__ __forceinline__ void ldsm4(uint32_t* r, uint32_t addr) {
    asm volatile("ldmatrix.sync.aligned.m8n8.x4.shared.b16 {%0,%1,%2,%3}, [%4];"
                 : "=r"(r[0]), "=r"(r[1]), "=r"(r[2]), "=r"(r[3]) : "r"(addr));
}
__device__ __forceinline__ void ldsm4t(uint32_t* r, uint32_t addr) {
    asm volatile("ldmatrix.sync.aligned.m8n8.x4.trans.shared.b16 {%0,%1,%2,%3}, [%4];"
                 : "=r"(r[0]), "=r"(r[1]), "=r"(r[2]), "=r"(r[3]) : "r"(addr));
}
__device__ __forceinline__ void mma_f16(float* c, const uint32_t* a,
                                        uint32_t b0, uint32_t b1) {
    asm volatile(
        "mma.sync.aligned.m16n8k16.row.col.f32.f16.f16.f32 "
        "{%0,%1,%2,%3}, {%4,%5,%6,%7}, {%8,%9}, {%0,%1,%2,%3};"
        : "+f"(c[0]), "+f"(c[1]), "+f"(c[2]), "+f"(c[3])
        : "r"(a[0]), "r"(a[1]), "r"(a[2]), "r"(a[3]), "r"(b0), "r"(b1));
}
#define CP16(dst, src) asm volatile("cp.async.cg.shared.global [%0], [%1], 16;" :: "r"(dst), "l"(src))
#define CP_COMMIT()    asm volatile("cp.async.commit_group;" ::: "memory")
#define CP_WAIT0()     asm volatile("cp.async.wait_group 0;" ::: "memory")
#define CP_WAIT1()     asm volatile("cp.async.wait_group 1;" ::: "memory")
#define CP_WAIT2()     asm volatile("cp.async.wait_group 2;" ::: "memory")

__device__ __forceinline__ uint32_t pack2h(float a, float b) {
    __half2 h = __floats2half2_rn(a, b);
    return *reinterpret_cast<uint32_t*>(&h);
}

// ---------------- prep kernels ----------------------------------------------
__global__ void tohalf_kernel(const float* __restrict__ src,
                              __half* __restrict__ dst, int n4) {
    int i = blockIdx.x * 256 + threadIdx.x;
    if (i >= n4) return;
    float4 v = reinterpret_cast<const float4*>(src)[i];
    uint32_t h0 = pack2h(v.x, v.y), h1 = pack2h(v.z, v.w);
    *reinterpret_cast<uint32_t*>(dst + i * 4)     = h0;
    *reinterpret_cast<uint32_t*>(dst + i * 4 + 2) = h1;
}

__global__ void xpose_half(const float* __restrict__ x) {
    __shared__ float tile[32][33];
    int b = blockIdx.z, t0 = blockIdx.x * 32, c0 = blockIdx.y * 32;
    int tx = threadIdx.x, ty = threadIdx.y;
    for (int i = ty; i < 32; i += 8)
        tile[i][tx] = x[((size_t)b * C_DIM + c0 + i) * S_LEN + t0 + tx];
    __syncthreads();
    for (int i = ty; i < 32; i += 8) {
        size_t oi = ((size_t)b * S_LEN + t0 + i) * C_DIM + c0 + tx;
        g_x[oi] = __float2half_rn(tile[tx][i]);
    }
}

// ---------------- mma.sync GEMM core: 256x128 tile, 512 thr, 4-stage ring ------
#define GP 72                          // pitch in halfs (144 B rows)
#define ABYTES (256 * 144)             // 36864
#define BBYTES (128 * 144)             // 18432
#define STBYTES (ABYTES + BBYTES)      // 55296

__device__ __forceinline__ void fill_async(
    uint32_t stage_s, int tid, int k0,
    const __half* A, const __half* B) {
#pragma unroll
    for (int i = tid; i < 2048; i += 512) {
        int r = i >> 3, c = (i & 7) * 16;
        CP16(stage_s + r * 144 + c, (const char*)(A + (size_t)r * C_DIM + k0) + c);
    }
#pragma unroll
    for (int i = tid; i < 1024; i += 512) {
        int r = i >> 3, c = (i & 7) * 16;
        CP16(stage_s + ABYTES + r * 144 + c, (const char*)(B + (size_t)r * C_DIM + k0) + c);
    }
    CP_COMMIT();
}

__device__ __forceinline__ void compute_stage(
    uint32_t st, int lane, int wm, int wn, float acc[4][4][4]) {
    uint32_t A_s = st, B_s = st + ABYTES;
    int ar = lane & 15, ach = (lane >> 4) * 8;
    int bg = lane >> 3, br = lane & 7;
    int brow = wn * 32 + (bg >> 1) * 8 + br;
    int bch = (bg & 1) * 8;
#pragma unroll
    for (int ks = 0; ks < 4; ks++) {
        uint32_t a[4][4], bb[2][4];
#pragma unroll
        for (int mi = 0; mi < 4; mi++)
            ldsm4(a[mi], A_s + ((wm * 64 + mi * 16 + ar) * GP + ks * 16 + ach) * 2);
#pragma unroll
        for (int nj = 0; nj < 2; nj++)
            ldsm4(bb[nj], B_s + ((brow + nj * 16) * GP + ks * 16 + bch) * 2);
#pragma unroll
        for (int mi = 0; mi < 4; mi++)
#pragma unroll
            for (int nj = 0; nj < 2; nj++) {
                mma_f16(acc[mi][nj * 2],     a[mi], bb[nj][0], bb[nj][1]);
                mma_f16(acc[mi][nj * 2 + 1], a[mi], bb[nj][2], bb[nj][3]);
            }
    }
}

// 4-stage ring, prefetch distance 2, one __syncthreads per stage.
__device__ __forceinline__ void gemm_body(
    uint32_t smb, int tid, float acc[4][4][4],
    const __half* A, const __half* B) {
    int lane = tid & 31, wid = tid >> 5;
    int wm = wid & 3, wn = wid >> 2;
    const int NC = C_DIM / 64;  // 16
    fill_async(smb, tid, 0, A, B);
    fill_async(smb + STBYTES, tid, 64, A, B);
    for (int ch = 0; ch < NC; ch++) {
        if (ch + 2 < NC) {
            fill_async(smb + ((ch + 2) & 3) * STBYTES, tid, (ch + 2) * 64, A, B);
            CP_WAIT2();
        } else if (ch + 2 == NC) {
            CP_WAIT1();
        } else {
            CP_WAIT0();
        }
        __syncthreads();
        compute_stage(smb + (ch & 3) * STBYTES, lane, wm, wn, acc);
    }
}

// ---------------- QKV projection (M = 256 tokens, N = 128 channels) ------------
__global__ __launch_bounds__(512, 1)
void qkv_tc(const float* __restrict__ bias) {
    extern __shared__ char sm[];
    uint32_t smb = smem_u32(sm);
    int tid = threadIdx.x;
    int b = blockIdx.z, n0 = blockIdx.x * 256, m0 = blockIdx.y * 128;

    float acc[4][4][4];
#pragma unroll
    for (int mi = 0; mi < 4; mi++)
#pragma unroll
        for (int ni = 0; ni < 4; ni++)
#pragma unroll
            for (int r = 0; r < 4; r++) acc[mi][ni][r] = 0.0f;

    gemm_body(smb, tid, acc,
              g_x + ((size_t)b * S_LEN + n0) * C_DIM,   // A rows = tokens
              g_Wq + (size_t)m0 * C_DIM);               // B rows = channels

    int lane = tid & 31, wid = tid >> 5;
    int wm = wid & 3, wn = wid >> 2;
    int tc = lane & 3;
    int which = m0 >> 10;
    __half* dstb = (which == 0) ? g_q : (which == 1) ? g_k : g_v;
    float scale = (which == 0) ? 0.125f : 1.0f;
    int mch0 = m0 + wn * 32;
    int head = (mch0 >> 6) & 15;
    int d0 = mch0 & 63;
    __half* base = dstb + ((size_t)(b * NH + head)) * S_LEN * HD;

    float bv0[4], bv1[4];
#pragma unroll
    for (int ni = 0; ni < 4; ni++) {
        bv0[ni] = bias[mch0 + ni * 8 + tc * 2];
        bv1[ni] = bias[mch0 + ni * 8 + tc * 2 + 1];
    }
#pragma unroll
    for (int mi = 0; mi < 4; mi++) {
#pragma unroll
        for (int rg = 0; rg < 2; rg++) {
            int t = n0 + wm * 64 + mi * 16 + (lane >> 2) + rg * 8;
            __half* rowp = base + (size_t)t * HD + d0 + tc * 2;
#pragma unroll
            for (int ni = 0; ni < 4; ni++) {
                uint32_t u = pack2h((acc[mi][ni][rg * 2 + 0] + bv0[ni]) * scale,
                                    (acc[mi][ni][rg * 2 + 1] + bv1[ni]) * scale);
                *reinterpret_cast<uint32_t*>(rowp + ni * 8) = u;
            }
        }
    }
}

// ---------------- Output projection (M = 256 co, N = 128 tokens) ---------------
__global__ __launch_bounds__(512, 1)
void out_tc(const float* __restrict__ bo, float* __restrict__ out) {
    extern __shared__ char sm[];
    uint32_t smb = smem_u32(sm);
    int tid = threadIdx.x;
    int b = blockIdx.z, m0 = blockIdx.y * 256, n0 = blockIdx.x * 128;

    float acc[4][4][4];
#pragma unroll
    for (int mi = 0; mi < 4; mi++)
#pragma unroll
        for (int ni = 0; ni < 4; ni++)
#pragma unroll
            for (int r = 0; r < 4; r++) acc[mi][ni][r] = 0.0f;

    gemm_body(smb, tid, acc,
              g_Wo + (size_t)m0 * C_DIM,
              g_z + ((size_t)b * S_LEN + n0) * C_DIM);

    int lane = tid & 31, wid = tid >> 5;
    int wm = wid & 3, wn = wid >> 2;
    int tc = lane & 3;
#pragma unroll
    for (int mi = 0; mi < 4; mi++) {
#pragma unroll
        for (int rg = 0; rg < 2; rg++) {
            int m = m0 + wm * 64 + mi * 16 + (lane >> 2) + rg * 8;
            float bv = bo[m];
            float* dst = out + ((size_t)b * C_DIM + m) * S_LEN;
#pragma unroll
            for (int ni = 0; ni < 4; ni++) {
                int t = n0 + wn * 32 + ni * 8 + tc * 2;
                float2 v = {acc[mi][ni][rg * 2 + 0] + bv,
                            acc[mi][ni][rg * 2 + 1] + bv};
                *reinterpret_cast<float2*>(dst + t) = v;
            }
        }
    }
}

// ---------------- Flash attention (single fp16, 4-stage ring, prefetch-2) ------
#define AP 72
#define QBYTES   18432              // Q, 128x144B
#define KVTILE   9216
#define KVBUF    18432              // K + V per stage

__device__ __forceinline__ void fill_kv(
    uint32_t dst, int tid, int s0, const __half* k, const __half* v) {
#pragma unroll
    for (int i = tid; i < 512; i += 256) {
        int r = i >> 3, c = (i & 7) * 16;
        uint32_t so = r * 144 + c;
        size_t go = (size_t)(s0 + r) * HD;
        CP16(dst + so,          (const char*)(k + go) + c);
        CP16(dst + KVTILE + so, (const char*)(v + go) + c);
    }
    CP_COMMIT();
}

__global__ __launch_bounds__(256, 2)
void attn_tc() {
    extern __shared__ char sm[];
    uint32_t smb = smem_u32(sm);
    uint32_t Q_s  = smb;
    uint32_t KV_s = smb + QBYTES;

    int head = blockIdx.y, b = blockIdx.z;
    int tid = threadIdx.x, lane = tid & 31, wid = tid >> 5;
    int r0w = wid * 16;
    int g = lane >> 2, tc = lane & 3;

    size_t base = ((size_t)(b * NH + head)) * S_LEN * HD;
    const __half* qp = g_q + base;
    const __half* kp = g_k + base;
    const __half* vp = g_v + base;

    int ar = lane & 15, ach = (lane >> 4) * 8;
    int bg = lane >> 3, br = lane & 7;
    int krow_off = ((bg >> 1) * 8 + br) * AP + (bg & 1) * 8;
    int vrow = ((lane >> 3) & 1) * 8 + (lane & 7);
    int vcol = (lane >> 4) * 8;

    for (int rep = 0; rep < 2; rep++) {
        int qt = rep == 0 ? (17 - (int)blockIdx.x) : (int)blockIdx.x;
        int q0 = qt * 128;

        // Q load (group retires before first compute via wait_group chain)
#pragma unroll
        for (int i = tid; i < 1024; i += 256) {
            int r = i >> 3, c = (i & 7) * 16;
            CP16(Q_s + r * 144 + c, (const char*)(qp + (size_t)(q0 + r) * HD) + c);
        }
        CP_COMMIT();

        float o[8][4] = {};
        float mA = -1e30f, mB = -1e30f, lA = 0.0f, lB = 0.0f;

        int nkt = 2 * qt + 2;
        fill_kv(KV_s, tid, 0, kp, vp);
        fill_kv(KV_s + KVBUF, tid, 64, kp, vp);
        for (int kt = 0; kt < nkt; kt++) {
            int c0 = kt * 64;
            if (kt + 2 < nkt) {
                fill_kv(KV_s + ((kt + 2) & 3) * KVBUF, tid, (kt + 2) * 64, kp, vp);
                CP_WAIT2();
            } else if (kt + 2 == nkt) {
                CP_WAIT1();
            } else {
                CP_WAIT0();
            }
            __syncthreads();
            uint32_t K_s = KV_s + (kt & 3) * KVBUF;
            uint32_t V_s = K_s + KVTILE;

            // ---- S = Q K^T ----
            float s[8][4] = {};
#pragma unroll
            for (int kc = 0; kc < 4; kc++) {
                uint32_t qh[4], kk[4][4];
                ldsm4(qh, Q_s + ((r0w + ar) * AP + kc * 16 + ach) * 2);
#pragma unroll
                for (int np = 0; np < 4; np++)
                    ldsm4(kk[np], K_s + (np * 16 * AP + kc * 16 + krow_off) * 2);
#pragma unroll
                for (int np = 0; np < 4; np++) {
                    mma_f16(s[np * 2],     qh, kk[np][0], kk[np][1]);
                    mma_f16(s[np * 2 + 1], qh, kk[np][2], kk[np][3]);
                }
            }

            // ---- mask (register domain) ----
            if (c0 + 63 > q0 + r0w) {
                int rowA = q0 + r0w + g, rowB = rowA + 8;
#pragma unroll
                for (int nf = 0; nf < 8; nf++) {
                    int col = c0 + nf * 8 + tc * 2;
                    if (col     > rowA) s[nf][0] -= 10000.0f;
                    if (col + 1 > rowA) s[nf][1] -= 10000.0f;
                    if (col     > rowB) s[nf][2] -= 10000.0f;
                    if (col + 1 > rowB) s[nf][3] -= 10000.0f;
                }
            }

            // ---- register softmax ----
            float pmA = -1e30f, pmB = -1e30f;
#pragma unroll
            for (int nf = 0; nf < 8; nf++) {
                pmA = fmaxf(pmA, fmaxf(s[nf][0], s[nf][1]));
                pmB = fmaxf(pmB, fmaxf(s[nf][2], s[nf][3]));
            }
            pmA = fmaxf(pmA, __shfl_xor_sync(0xffffffffu, pmA, 1));
            pmA = fmaxf(pmA, __shfl_xor_sync(0xffffffffu, pmA, 2));
            pmB = fmaxf(pmB, __shfl_xor_sync(0xffffffffu, pmB, 1));
            pmB = fmaxf(pmB, __shfl_xor_sync(0xffffffffu, pmB, 2));
            float mnA = fmaxf(mA, pmA), mnB = fmaxf(mB, pmB);
            float alA = __expf(mA - mnA), alB = __expf(mB - mnB);
            float lsA = 0.0f, lsB = 0.0f;
#pragma unroll
            for (int nf = 0; nf < 8; nf++) {
                s[nf][0] = __expf(s[nf][0] - mnA);
                s[nf][1] = __expf(s[nf][1] - mnA);
                s[nf][2] = __expf(s[nf][2] - mnB);
                s[nf][3] = __expf(s[nf][3] - mnB);
                lsA += s[nf][0] + s[nf][1];
                lsB += s[nf][2] + s[nf][3];
            }
            lsA += __shfl_xor_sync(0xffffffffu, lsA, 1);
            lsA += __shfl_xor_sync(0xffffffffu, lsA, 2);
            lsB += __shfl_xor_sync(0xffffffffu, lsB, 1);
            lsB += __shfl_xor_sync(0xffffffffu, lsB, 2);
            lA = lA * alA + lsA;
            lB = lB * alB + lsB;
            mA = mnA; mB = mnB;
#pragma unroll
            for (int nf = 0; nf < 8; nf++) {
                o[nf][0] *= alA; o[nf][1] *= alA;
                o[nf][2] *= alB; o[nf][3] *= alB;
            }

            // ---- O += P V ----
#pragma unroll
            for (int kc = 0; kc < 4; kc++) {
                uint32_t ph[4], vv[4][4];
                ph[0] = pack2h(s[2 * kc][0],     s[2 * kc][1]);
                ph[1] = pack2h(s[2 * kc][2],     s[2 * kc][3]);
                ph[2] = pack2h(s[2 * kc + 1][0], s[2 * kc + 1][1]);
                ph[3] = pack2h(s[2 * kc + 1][2], s[2 * kc + 1][3]);
#pragma unroll
                for (int np = 0; np < 4; np++)
                    ldsm4t(vv[np], V_s + ((kc * 16 + vrow) * AP + np * 16 + vcol) * 2);
#pragma unroll
                for (int np = 0; np < 4; np++) {
                    mma_f16(o[np * 2],     ph, vv[np][0], vv[np][1]);
                    mma_f16(o[np * 2 + 1], ph, vv[np][2], vv[np][3]);
                }
            }
            // no trailing sync — 4-stage ring + per-iter sync make refill safe
        }

        // ---- epilogue: z = O / l, fp16 ----
        float liA = 1.0f / lA, liB = 1.0f / lB;
        int tA = q0 + r0w + g, tB = tA + 8;
#pragma unroll
        for (int nf = 0; nf < 8; nf++) {
            int d = nf * 8 + tc * 2;
            size_t ziA = ((size_t)b * S_LEN + tA) * C_DIM + head * HD + d;
            size_t ziB = ((size_t)b * S_LEN + tB) * C_DIM + head * HD + d;
            *reinterpret_cast<uint32_t*>(g_z + ziA) = pack2h(o[nf][0] * liA, o[nf][1] * liA);
            *reinterpret_cast<uint32_t*>(g_z + ziB) = pack2h(o[nf][2] * liB, o[nf][3] * liB);
        }
        __syncthreads();   // protect Q/KV refill for rep 1
    }
}

// ---------------------------------------------------------------------------

extern "C" void kernel_launch(void* const* d_in, const int* in_sizes, int n_in,
                              void* d_out, int out_size) {
    const float* x    = (const float*)d_in[0];
    const float* Wqkv = (const float*)d_in[1];
    const float* bqkv = (const float*)d_in[2];
    const float* Wo   = (const float*)d_in[3];
    const float* bo   = (const float*)d_in[4];
    float* out = (float*)d_out;

    __half *wq, *wo;
    cudaGetSymbolAddress((void**)&wq, g_Wq);
    cudaGetSymbolAddress((void**)&wo, g_Wo);

    int nq4 = 3 * C_DIM * C_DIM / 4;
    tohalf_kernel<<<(nq4 + 255) / 256, 256>>>(Wqkv, wq, nq4);
    int no4 = C_DIM * C_DIM / 4;
    tohalf_kernel<<<(no4 + 255) / 256, 256>>>(Wo, wo, no4);

    dim3 gT(S_LEN / 32, C_DIM / 32, BATCH);
    xpose_half<<<gT, dim3(32, 8)>>>(x);

    size_t gsmem = 4 * STBYTES;   // 221184
    cudaFuncSetAttribute(qkv_tc, cudaFuncAttributeMaxDynamicSharedMemorySize, (int)gsmem);
    cudaFuncSetAttribute(out_tc, cudaFuncAttributeMaxDynamicSharedMemorySize, (int)gsmem);

    dim3 gA(S_LEN / 256, 3 * C_DIM / 128, BATCH);   // (9, 24, 2)
    qkv_tc<<<gA, 512, gsmem>>>(bqkv);

    size_t asmem = QBYTES + 4 * KVBUF;   // 92160
    cudaFuncSetAttribute(attn_tc, cudaFuncAttributeMaxDynamicSharedMemorySize, (int)asmem);
    dim3 gB(9, NH, BATCH);
    attn_tc<<<gB, 256, asmem>>>();

    dim3 gC(S_LEN / 128, C_DIM / 256, BATCH);       // (18, 4, 2)
    out_tc<<<gC, 512, gsmem>>>(bo, out);
}

// round 12
// speedup vs baseline: 9.7107x; 1.0274x over previous
#include <cuda_runtime.h>
#include <cuda_fp16.h>
#include <cstdint>

#define S_LEN 2304
#define C_DIM 1024
#define NH    16
#define HD    64
#define BATCH 2

// ---------------- scratch (all single fp16) -----------------------------------
__device__ __half g_Wq[(size_t)3 * C_DIM * C_DIM];
__device__ __half g_Wo[(size_t)C_DIM * C_DIM];
__device__ __half g_x[(size_t)BATCH * S_LEN * C_DIM];      // x^T tokens-major
__device__ __half g_z[(size_t)BATCH * S_LEN * C_DIM];
__device__ __half g_q[(size_t)BATCH * NH * S_LEN * HD];    // pre-scaled 1/8*log2e
__device__ __half g_k[(size_t)BATCH * NH * S_LEN * HD];
__device__ __half g_v[(size_t)BATCH * NH * S_LEN * HD];

// ---------------- helpers ----------------------------------------------------
__device__ __forceinline__ uint32_t smem_u32(const void* p) {
    uint32_t a;
    asm("{ .reg .u64 t; cvta.to.shared.u64 t, %1; cvt.u32.u64 %0, t; }" : "=r"(a) : "l"(p));
    return a;
}
__device__ __forceinline__ void ldsm4(uint32_t* r, uint32_t addr) {
    asm volatile("ldmatrix.sync.aligned.m8n8.x4.shared.b16 {%0,%1,%2,%3}, [%4];"
                 : "=r"(r[0]), "=r"(r[1]), "=r"(r[2]), "=r"(r[3]) : "r"(addr));
}
__device__ __forceinline__ void ldsm4t(uint32_t* r, uint32_t addr) {
    asm volatile("ldmatrix.sync.aligned.m8n8.x4.trans.shared.b16 {%0,%1,%2,%3}, [%4];"
                 : "=r"(r[0]), "=r"(r[1]), "=r"(r[2]), "=r"(r[3]) : "r"(addr));
}
__device__ __forceinline__ void mma_f16(float* c, const uint32_t* a,
                                        uint32_t b0, uint32_t b1) {
    asm volatile(
        "mma.sync.aligned.m16n8k16.row.col.f32.f16.f16.f32 "
        "{%0,%1,%2,%3}, {%4,%5,%6,%7}, {%8,%9}, {%0,%1,%2,%3};"
        : "+f"(c[0]), "+f"(c[1]), "+f"(c[2]), "+f"(c[3])
        : "r"(a[0]), "r"(a[1]), "r"(a[2]), "r"(a[3]), "r"(b0), "r"(b1));
}
#define CP16(dst, src) asm volatile("cp.async.cg.shared.global [%0], [%1], 16;" :: "r"(dst), "l"(src))
#define CP_COMMIT()    asm volatile("cp.async.commit_group;" ::: "memory")
#define CP_WAIT0()     asm volatile("cp.async.wait_group 0;" ::: "memory")
#define CP_WAIT1()     asm volatile("cp.async.wait_group 1;" ::: "memory")
#define CP_WAIT2()     asm volatile("cp.async.wait_group 2;" ::: "memory")

__device__ __forceinline__ uint32_t pack2h(float a, float b) {
    __half2 h = __floats2half2_rn(a, b);
    return *reinterpret_cast<uint32_t*>(&h);
}
__device__ __forceinline__ uint32_t h2ex2(uint32_t x) {
    uint32_t d;
    asm("ex2.approx.f16x2 %0, %1;" : "=r"(d) : "r"(x));
    return d;
}
__device__ __forceinline__ float2 h2f2(uint32_t x) {
    __half2 h = *reinterpret_cast<__half2*>(&x);
    return __half22float2(h);
}

#define LOG2E 1.4426950408889634f
#define MASK2 14426.950408889634f   // 10000 * log2(e)

// ---------------- prep kernels ----------------------------------------------
__global__ void tohalf_kernel(const float* __restrict__ src,
                              __half* __restrict__ dst, int n4) {
    int i = blockIdx.x * 256 + threadIdx.x;
    if (i >= n4) return;
    float4 v = reinterpret_cast<const float4*>(src)[i];
    uint32_t h0 = pack2h(v.x, v.y), h1 = pack2h(v.z, v.w);
    *reinterpret_cast<uint32_t*>(dst + i * 4)     = h0;
    *reinterpret_cast<uint32_t*>(dst + i * 4 + 2) = h1;
}

__global__ void xpose_half(const float* __restrict__ x) {
    __shared__ float tile[32][33];
    int b = blockIdx.z, t0 = blockIdx.x * 32, c0 = blockIdx.y * 32;
    int tx = threadIdx.x, ty = threadIdx.y;
    for (int i = ty; i < 32; i += 8)
        tile[i][tx] = x[((size_t)b * C_DIM + c0 + i) * S_LEN + t0 + tx];
    __syncthreads();
    for (int i = ty; i < 32; i += 8) {
        size_t oi = ((size_t)b * S_LEN + t0 + i) * C_DIM + c0 + tx;
        g_x[oi] = __float2half_rn(tile[tx][i]);
    }
}

// ---------------- mma.sync GEMM core: 256x128 tile, 512 thr, 4-stage ring ------
#define GP 72                          // pitch in halfs (144 B rows)
#define ABYTES (256 * 144)             // 36864
#define BBYTES (128 * 144)             // 18432
#define STBYTES (ABYTES + BBYTES)      // 55296

__device__ __forceinline__ void fill_async(
    uint32_t stage_s, int tid, int k0,
    const __half* A, const __half* B) {
#pragma unroll
    for (int i = tid; i < 2048; i += 512) {
        int r = i >> 3, c = (i & 7) * 16;
        CP16(stage_s + r * 144 + c, (const char*)(A + (size_t)r * C_DIM + k0) + c);
    }
#pragma unroll
    for (int i = tid; i < 1024; i += 512) {
        int r = i >> 3, c = (i & 7) * 16;
        CP16(stage_s + ABYTES + r * 144 + c, (const char*)(B + (size_t)r * C_DIM + k0) + c);
    }
    CP_COMMIT();
}

__device__ __forceinline__ void compute_stage(
    uint32_t st, int lane, int wm, int wn, float acc[4][4][4]) {
    uint32_t A_s = st, B_s = st + ABYTES;
    int ar = lane & 15, ach = (lane >> 4) * 8;
    int bg = lane >> 3, br = lane & 7;
    int brow = wn * 32 + (bg >> 1) * 8 + br;
    int bch = (bg & 1) * 8;
#pragma unroll
    for (int ks = 0; ks < 4; ks++) {
        uint32_t a[4][4], bb[2][4];
#pragma unroll
        for (int mi = 0; mi < 4; mi++)
            ldsm4(a[mi], A_s + ((wm * 64 + mi * 16 + ar) * GP + ks * 16 + ach) * 2);
#pragma unroll
        for (int nj = 0; nj < 2; nj++)
            ldsm4(bb[nj], B_s + ((brow + nj * 16) * GP + ks * 16 + bch) * 2);
#pragma unroll
        for (int mi = 0; mi < 4; mi++)
#pragma unroll
            for (int nj = 0; nj < 2; nj++) {
                mma_f16(acc[mi][nj * 2],     a[mi], bb[nj][0], bb[nj][1]);
                mma_f16(acc[mi][nj * 2 + 1], a[mi], bb[nj][2], bb[nj][3]);
            }
    }
}

__device__ __forceinline__ void gemm_body(
    uint32_t smb, int tid, float acc[4][4][4],
    const __half* A, const __half* B) {
    int lane = tid & 31, wid = tid >> 5;
    int wm = wid & 3, wn = wid >> 2;
    const int NC = C_DIM / 64;  // 16
    fill_async(smb, tid, 0, A, B);
    fill_async(smb + STBYTES, tid, 64, A, B);
    for (int ch = 0; ch < NC; ch++) {
        if (ch + 2 < NC) {
            fill_async(smb + ((ch + 2) & 3) * STBYTES, tid, (ch + 2) * 64, A, B);
            CP_WAIT2();
        } else if (ch + 2 == NC) {
            CP_WAIT1();
        } else {
            CP_WAIT0();
        }
        __syncthreads();
        compute_stage(smb + (ch & 3) * STBYTES, lane, wm, wn, acc);
    }
}

// ---------------- QKV projection (M = 256 tokens, N = 128 channels) ------------
__global__ __launch_bounds__(512, 1)
void qkv_tc(const float* __restrict__ bias) {
    extern __shared__ char sm[];
    uint32_t smb = smem_u32(sm);
    int tid = threadIdx.x;
    int b = blockIdx.z, n0 = blockIdx.x * 256, m0 = blockIdx.y * 128;

    float acc[4][4][4];
#pragma unroll
    for (int mi = 0; mi < 4; mi++)
#pragma unroll
        for (int ni = 0; ni < 4; ni++)
#pragma unroll
            for (int r = 0; r < 4; r++) acc[mi][ni][r] = 0.0f;

    gemm_body(smb, tid, acc,
              g_x + ((size_t)b * S_LEN + n0) * C_DIM,
              g_Wq + (size_t)m0 * C_DIM);

    int lane = tid & 31, wid = tid >> 5;
    int wm = wid & 3, wn = wid >> 2;
    int tc = lane & 3;
    int which = m0 >> 10;
    __half* dstb = (which == 0) ? g_q : (which == 1) ? g_k : g_v;
    float scale = (which == 0) ? (0.125f * LOG2E) : 1.0f;   // q in base-2 domain
    int mch0 = m0 + wn * 32;
    int head = (mch0 >> 6) & 15;
    int d0 = mch0 & 63;
    __half* base = dstb + ((size_t)(b * NH + head)) * S_LEN * HD;

    float bv0[4], bv1[4];
#pragma unroll
    for (int ni = 0; ni < 4; ni++) {
        bv0[ni] = bias[mch0 + ni * 8 + tc * 2];
        bv1[ni] = bias[mch0 + ni * 8 + tc * 2 + 1];
    }
#pragma unroll
    for (int mi = 0; mi < 4; mi++) {
#pragma unroll
        for (int rg = 0; rg < 2; rg++) {
            int t = n0 + wm * 64 + mi * 16 + (lane >> 2) + rg * 8;
            __half* rowp = base + (size_t)t * HD + d0 + tc * 2;
#pragma unroll
            for (int ni = 0; ni < 4; ni++) {
                uint32_t u = pack2h((acc[mi][ni][rg * 2 + 0] + bv0[ni]) * scale,
                                    (acc[mi][ni][rg * 2 + 1] + bv1[ni]) * scale);
                *reinterpret_cast<uint32_t*>(rowp + ni * 8) = u;
            }
        }
    }
}

// ---------------- Output projection (M = 256 co, N = 128 tokens) ---------------
__global__ __launch_bounds__(512, 1)
void out_tc(const float* __restrict__ bo, float* __restrict__ out) {
    extern __shared__ char sm[];
    uint32_t smb = smem_u32(sm);
    int tid = threadIdx.x;
    int b = blockIdx.z, m0 = blockIdx.y * 256, n0 = blockIdx.x * 128;

    float acc[4][4][4];
#pragma unroll
    for (int mi = 0; mi < 4; mi++)
#pragma unroll
        for (int ni = 0; ni < 4; ni++)
#pragma unroll
            for (int r = 0; r < 4; r++) acc[mi][ni][r] = 0.0f;

    gemm_body(smb, tid, acc,
              g_Wo + (size_t)m0 * C_DIM,
              g_z + ((size_t)b * S_LEN + n0) * C_DIM);

    int lane = tid & 31, wid = tid >> 5;
    int wm = wid & 3, wn = wid >> 2;
    int tc = lane & 3;
#pragma unroll
    for (int mi = 0; mi < 4; mi++) {
#pragma unroll
        for (int rg = 0; rg < 2; rg++) {
            int m = m0 + wm * 64 + mi * 16 + (lane >> 2) + rg * 8;
            float bv = bo[m];
            float* dst = out + ((size_t)b * C_DIM + m) * S_LEN;
#pragma unroll
            for (int ni = 0; ni < 4; ni++) {
                int t = n0 + wn * 32 + ni * 8 + tc * 2;
                float2 v = {acc[mi][ni][rg * 2 + 0] + bv,
                            acc[mi][ni][rg * 2 + 1] + bv};
                *reinterpret_cast<float2*>(dst + t) = v;
            }
        }
    }
}

// ---------------- Flash attention (base-2 softmax, ex2.f16x2) -------------------
#define AP 72
#define QBYTES   18432
#define KVTILE   9216
#define KVBUF    18432

__device__ __forceinline__ void fill_kv(
    uint32_t dst, int tid, int s0, const __half* k, const __half* v) {
#pragma unroll
    for (int i = tid; i < 512; i += 256) {
        int r = i >> 3, c = (i & 7) * 16;
        uint32_t so = r * 144 + c;
        size_t go = (size_t)(s0 + r) * HD;
        CP16(dst + so,          (const char*)(k + go) + c);
        CP16(dst + KVTILE + so, (const char*)(v + go) + c);
    }
    CP_COMMIT();
}

__global__ __launch_bounds__(256, 2)
void attn_tc() {
    extern __shared__ char sm[];
    uint32_t smb = smem_u32(sm);
    uint32_t Q_s  = smb;
    uint32_t KV_s = smb + QBYTES;

    int head = blockIdx.y, b = blockIdx.z;
    int tid = threadIdx.x, lane = tid & 31, wid = tid >> 5;
    int r0w = wid * 16;
    int g = lane >> 2, tc = lane & 3;

    size_t base = ((size_t)(b * NH + head)) * S_LEN * HD;
    const __half* qp = g_q + base;
    const __half* kp = g_k + base;
    const __half* vp = g_v + base;

    int ar = lane & 15, ach = (lane >> 4) * 8;
    int bg = lane >> 3, br = lane & 7;
    int krow_off = ((bg >> 1) * 8 + br) * AP + (bg & 1) * 8;
    int vrow = ((lane >> 3) & 1) * 8 + (lane & 7);
    int vcol = (lane >> 4) * 8;

    for (int rep = 0; rep < 2; rep++) {
        int qt = rep == 0 ? (17 - (int)blockIdx.x) : (int)blockIdx.x;
        int q0 = qt * 128;

#pragma unroll
        for (int i = tid; i < 1024; i += 256) {
            int r = i >> 3, c = (i & 7) * 16;
            CP16(Q_s + r * 144 + c, (const char*)(qp + (size_t)(q0 + r) * HD) + c);
        }
        CP_COMMIT();

        float o[8][4] = {};
        float mA = -1e30f, mB = -1e30f, lA = 0.0f, lB = 0.0f;

        int nkt = 2 * qt + 2;
        fill_kv(KV_s, tid, 0, kp, vp);
        fill_kv(KV_s + KVBUF, tid, 64, kp, vp);
        for (int kt = 0; kt < nkt; kt++) {
            int c0 = kt * 64;
            if (kt + 2 < nkt) {
                fill_kv(KV_s + ((kt + 2) & 3) * KVBUF, tid, (kt + 2) * 64, kp, vp);
                CP_WAIT2();
            } else if (kt + 2 == nkt) {
                CP_WAIT1();
            } else {
                CP_WAIT0();
            }
            __syncthreads();
            uint32_t K_s = KV_s + (kt & 3) * KVBUF;
            uint32_t V_s = K_s + KVTILE;

            // ---- S = Q K^T (S already in log2 units) ----
            float s[8][4] = {};
#pragma unroll
            for (int kc = 0; kc < 4; kc++) {
                uint32_t qh[4], kk[4][4];
                ldsm4(qh, Q_s + ((r0w + ar) * AP + kc * 16 + ach) * 2);
#pragma unroll
                for (int np = 0; np < 4; np++)
                    ldsm4(kk[np], K_s + (np * 16 * AP + kc * 16 + krow_off) * 2);
#pragma unroll
                for (int np = 0; np < 4; np++) {
                    mma_f16(s[np * 2],     qh, kk[np][0], kk[np][1]);
                    mma_f16(s[np * 2 + 1], qh, kk[np][2], kk[np][3]);
                }
            }

            // ---- mask (register domain, base-2) ----
            if (c0 + 63 > q0 + r0w) {
                int rowA = q0 + r0w + g, rowB = rowA + 8;
#pragma unroll
                for (int nf = 0; nf < 8; nf++) {
                    int col = c0 + nf * 8 + tc * 2;
                    if (col     > rowA) s[nf][0] -= MASK2;
                    if (col + 1 > rowA) s[nf][1] -= MASK2;
                    if (col     > rowB) s[nf][2] -= MASK2;
                    if (col + 1 > rowB) s[nf][3] -= MASK2;
                }
            }

            // ---- register softmax (base-2, fp16x2 ex2) ----
            float pmA = -1e30f, pmB = -1e30f;
#pragma unroll
            for (int nf = 0; nf < 8; nf++) {
                pmA = fmaxf(pmA, fmaxf(s[nf][0], s[nf][1]));
                pmB = fmaxf(pmB, fmaxf(s[nf][2], s[nf][3]));
            }
            pmA = fmaxf(pmA, __shfl_xor_sync(0xffffffffu, pmA, 1));
            pmA = fmaxf(pmA, __shfl_xor_sync(0xffffffffu, pmA, 2));
            pmB = fmaxf(pmB, __shfl_xor_sync(0xffffffffu, pmB, 1));
            pmB = fmaxf(pmB, __shfl_xor_sync(0xffffffffu, pmB, 2));
            float mnA = fmaxf(mA, pmA), mnB = fmaxf(mB, pmB);
            float alA = exp2f(mA - mnA), alB = exp2f(mB - mnB);

            uint32_t pu[8][2];
            float lsA = 0.0f, lsB = 0.0f;
#pragma unroll
            for (int nf = 0; nf < 8; nf++) {
                pu[nf][0] = h2ex2(pack2h(s[nf][0] - mnA, s[nf][1] - mnA));
                pu[nf][1] = h2ex2(pack2h(s[nf][2] - mnB, s[nf][3] - mnB));
                float2 fA = h2f2(pu[nf][0]);
                float2 fB = h2f2(pu[nf][1]);
                lsA += fA.x + fA.y;
                lsB += fB.x + fB.y;
            }
            lsA += __shfl_xor_sync(0xffffffffu, lsA, 1);
            lsA += __shfl_xor_sync(0xffffffffu, lsA, 2);
            lsB += __shfl_xor_sync(0xffffffffu, lsB, 1);
            lsB += __shfl_xor_sync(0xffffffffu, lsB, 2);
            lA = lA * alA + lsA;
            lB = lB * alB + lsB;
            mA = mnA; mB = mnB;
#pragma unroll
            for (int nf = 0; nf < 8; nf++) {
                o[nf][0] *= alA; o[nf][1] *= alA;
                o[nf][2] *= alB; o[nf][3] *= alB;
            }

            // ---- O += P V (P already in fp16 regs) ----
#pragma unroll
            for (int kc = 0; kc < 4; kc++) {
                uint32_t ph[4], vv[4][4];
                ph[0] = pu[2 * kc][0];
                ph[1] = pu[2 * kc][1];
                ph[2] = pu[2 * kc + 1][0];
                ph[3] = pu[2 * kc + 1][1];
#pragma unroll
                for (int np = 0; np < 4; np++)
                    ldsm4t(vv[np], V_s + ((kc * 16 + vrow) * AP + np * 16 + vcol) * 2);
#pragma unroll
                for (int np = 0; np < 4; np++) {
                    mma_f16(o[np * 2],     ph, vv[np][0], vv[np][1]);
                    mma_f16(o[np * 2 + 1], ph, vv[np][2], vv[np][3]);
                }
            }
        }

        // ---- epilogue: z = O / l, fp16 ----
        float liA = 1.0f / lA, liB = 1.0f / lB;
        int tA = q0 + r0w + g, tB = tA + 8;
#pragma unroll
        for (int nf = 0; nf < 8; nf++) {
            int d = nf * 8 + tc * 2;
            size_t ziA = ((size_t)b * S_LEN + tA) * C_DIM + head * HD + d;
            size_t ziB = ((size_t)b * S_LEN + tB) * C_DIM + head * HD + d;
            *reinterpret_cast<uint32_t*>(g_z + ziA) = pack2h(o[nf][0] * liA, o[nf][1] * liA);
            *reinterpret_cast<uint32_t*>(g_z + ziB) = pack2h(o[nf][2] * liB, o[nf][3] * liB);
        }
        __syncthreads();
    }
}

// ---------------------------------------------------------------------------

extern "C" void kernel_launch(void* const* d_in, const int* in_sizes, int n_in,
                              void* d_out, int out_size) {
    const float* x    = (const float*)d_in[0];
    const float* Wqkv = (const float*)d_in[1];
    const float* bqkv = (const float*)d_in[2];
    const float* Wo   = (const float*)d_in[3];
    const float* bo   = (const float*)d_in[4];
    float* out = (float*)d_out;

    __half *wq, *wo;
    cudaGetSymbolAddress((void**)&wq, g_Wq);
    cudaGetSymbolAddress((void**)&wo, g_Wo);

    int nq4 = 3 * C_DIM * C_DIM / 4;
    tohalf_kernel<<<(nq4 + 255) / 256, 256>>>(Wqkv, wq, nq4);
    int no4 = C_DIM * C_DIM / 4;
    tohalf_kernel<<<(no4 + 255) / 256, 256>>>(Wo, wo, no4);

    dim3 gT(S_LEN / 32, C_DIM / 32, BATCH);
    xpose_half<<<gT, dim3(32, 8)>>>(x);

    size_t gsmem = 4 * STBYTES;   // 221184
    cudaFuncSetAttribute(qkv_tc, cudaFuncAttributeMaxDynamicSharedMemorySize, (int)gsmem);
    cudaFuncSetAttribute(out_tc, cudaFuncAttributeMaxDynamicSharedMemorySize, (int)gsmem);

    dim3 gA(S_LEN / 256, 3 * C_DIM / 128, BATCH);   // (9, 24, 2)
    qkv_tc<<<gA, 512, gsmem>>>(bqkv);

    size_t asmem = QBYTES + 4 * KVBUF;   // 92160
    cudaFuncSetAttribute(attn_tc, cudaFuncAttributeMaxDynamicSharedMemorySize, (int)asmem);
    dim3 gB(9, NH, BATCH);
    attn_tc<<<gB, 256, asmem>>>();

    dim3 gC(S_LEN / 128, C_DIM / 256, BATCH);       // (18, 4, 2)
    out_tc<<<gC, 512, gsmem>>>(bo, out);
}